// round 8
// baseline (speedup 1.0000x reference)
#include <cuda_runtime.h>
#include <cuda_bf16.h>
#include <math.h>
#include <stdint.h>

// Problem constants
#define BATCH 4
#define SEQ   2048
#define EMBED 1024
#define HSZ   1024
#define QKV3  3072
#define BS    (BATCH*SEQ)

typedef __nv_bfloat16 bf16;

// Scratch (device globals -- no allocation allowed)
__device__ bf16  g_xh[(size_t)BS * EMBED];
__device__ bf16  g_xl[(size_t)BS * EMBED];
__device__ bf16  g_wqh[(size_t)QKV3 * EMBED];
__device__ bf16  g_wql[(size_t)QKV3 * EMBED];
__device__ bf16  g_wph[(size_t)EMBED * HSZ];
__device__ bf16  g_wpl[(size_t)EMBED * HSZ];
__device__ bf16  g_qkvh[(size_t)BS * QKV3];
__device__ bf16  g_qkvl[(size_t)BS * QKV3];
__device__ float g_scores[(size_t)BATCH * SEQ * SEQ];
__device__ bf16  g_ph[(size_t)BATCH * SEQ * SEQ];
__device__ bf16  g_pl[(size_t)BATCH * SEQ * SEQ];
__device__ bf16  g_vTh[(size_t)BATCH * HSZ * SEQ];
__device__ bf16  g_vTl[(size_t)BATCH * HSZ * SEQ];
__device__ bf16  g_oh[(size_t)BATCH * SEQ * HSZ];
__device__ bf16  g_ol[(size_t)BATCH * SEQ * HSZ];
__device__ bf16  g_oTh[(size_t)BATCH * HSZ * SEQ];
__device__ bf16  g_oTl[(size_t)BATCH * HSZ * SEQ];

// ---------------------------------------------------------------------------
__device__ __forceinline__ uint32_t smem_u32(const void* p) {
    uint32_t a;
    asm("{ .reg .u64 t; cvta.to.shared.u64 t, %1; cvt.u32.u64 %0, t; }"
        : "=r"(a) : "l"(p));
    return a;
}
__device__ __forceinline__ void cp16(uint32_t dst, const void* src) {
    asm volatile("cp.async.cg.shared.global [%0], [%1], 16;"
                 :: "r"(dst), "l"(src));
}
__device__ __forceinline__ void ldsm4(uint32_t* r, uint32_t addr) {
    asm volatile("ldmatrix.sync.aligned.m8n8.x4.shared.b16 {%0,%1,%2,%3}, [%4];"
                 : "=r"(r[0]), "=r"(r[1]), "=r"(r[2]), "=r"(r[3]) : "r"(addr));
}
__device__ __forceinline__ void mma16816(float* c, const uint32_t* a,
                                         const uint32_t* b) {
    asm volatile(
        "mma.sync.aligned.m16n8k16.row.col.f32.bf16.bf16.f32 "
        "{%0,%1,%2,%3}, {%4,%5,%6,%7}, {%8,%9}, {%0,%1,%2,%3};"
        : "+f"(c[0]), "+f"(c[1]), "+f"(c[2]), "+f"(c[3])
        : "r"(a[0]), "r"(a[1]), "r"(a[2]), "r"(a[3]), "r"(b[0]), "r"(b[1]));
}

// ---------------------------------------------------------------------------
// bf16x3 NT GEMM: C[m,n] = alpha * sum_k (Ah+Al)[m,k]*(Bh+Bl)[n,k]  (3 MMAs)
// BM=64, BN=128, BK=32. 256 threads = 8 warps (2m x 4n); warp tile 32x32.
// SMEM rows interleave limbs: [hi 64B | lo 64B] = 128B, SW128 XOR swizzle.
// Stage = A 8KB + B 16KB = 24KB; 4 stages = 96KB -> 2 CTAs/SM (16 warps).
// Single __syncthreads per K-iter; global prefetch distance 3.
// MODE 0: fp32 out; 1: fp32+bias; 2: split bf16 out (Ch,Cl)
// ---------------------------------------------------------------------------
template <int MODE>
__global__ __launch_bounds__(256, 2) void tc_gemm(
    const bf16* __restrict__ Ah, const bf16* __restrict__ Al,
    const bf16* __restrict__ Bh, const bf16* __restrict__ Bl,
    float* __restrict__ C, bf16* __restrict__ Ch, bf16* __restrict__ Cl,
    const float* __restrict__ bias,
    int K, int lda, int ldb, int ldc,
    long long sA, long long sB, long long sC, float alpha)
{
    constexpr uint32_t B_OFF = 8192u;          // A: 64x128B
    constexpr uint32_t STAGE = 24576u;         // + B: 128x128B

    extern __shared__ char dsm[];
    const uint32_t base = smem_u32(dsm);

    const int tid = threadIdx.x;
    const int wid = tid >> 5, lane = tid & 31;
    const int wm = wid >> 2, wn = wid & 3;     // 2 x 4 warps
    const int gid = lane >> 2, tig = lane & 3;

    Ah += (long long)blockIdx.z * sA;  Al += (long long)blockIdx.z * sA;
    Bh += (long long)blockIdx.z * sB;  Bl += (long long)blockIdx.z * sB;
    const long long co = (long long)blockIdx.z * sC;
    const int m0 = blockIdx.y * 64;
    const int n0 = blockIdx.x * 128;

    // ldmatrix per-lane row/chunk decode
    const int rAl = lane & 15,                       cA16 = (lane >> 4) << 4;
    const int rBl = (lane & 7) | ((lane >> 4) << 3), cB16 = ((lane >> 3) & 1) << 4;

    uint32_t rbA[2], swA[2], rbB[2], swB[2];
#pragma unroll
    for (int mt = 0; mt < 2; mt++) {
        int row = wm * 32 + mt * 16 + rAl;
        rbA[mt] = (uint32_t)row << 7;
        swA[mt] = (uint32_t)(row & 7) << 4;
    }
#pragma unroll
    for (int np = 0; np < 2; np++) {
        int row = wn * 32 + np * 16 + rBl;
        rbB[np] = (uint32_t)row << 7;
        swB[np] = (uint32_t)(row & 7) << 4;
    }

    float c[2][4][4];
#pragma unroll
    for (int mt = 0; mt < 2; mt++)
#pragma unroll
        for (int nt = 0; nt < 4; nt++)
#pragma unroll
            for (int i = 0; i < 4; i++) c[mt][nt][i] = 0.f;

    const int NIT = K >> 5;   // BK = 32

    // Per-thread fixed load assignment (limb from chunk index)
    auto load_stage = [&](int it, int s) {
        const uint32_t st = base + (uint32_t)s * STAGE;
        const int c0 = it << 5;
#pragma unroll
        for (int i = 0; i < 2; i++) {              // A: 64 rows x 8 chunks
            int idx = tid + i * 256;
            int r = idx >> 3, ch = idx & 7;
            uint32_t off = ((uint32_t)r << 7) + (((uint32_t)ch << 4) ^ ((uint32_t)(r & 7) << 4));
            const bf16* src = (ch < 4 ? Ah : Al) + (size_t)(m0 + r) * lda + c0 + (ch & 3) * 8;
            cp16(st + off, src);
        }
#pragma unroll
        for (int i = 0; i < 4; i++) {              // B: 128 rows x 8 chunks
            int idx = tid + i * 256;
            int r = idx >> 3, ch = idx & 7;
            uint32_t off = ((uint32_t)r << 7) + (((uint32_t)ch << 4) ^ ((uint32_t)(r & 7) << 4));
            const bf16* src = (ch < 4 ? Bh : Bl) + (size_t)(n0 + r) * ldb + c0 + (ch & 3) * 8;
            cp16(st + B_OFF + off, src);
        }
        asm volatile("cp.async.commit_group;" ::: "memory");
    };

    load_stage(0, 0);
    load_stage(1, 1);
    load_stage(2, 2);

    uint32_t ah[2][4], al[2][4], bh[2][4], bl[2][4];

    auto ld_frags = [&](uint32_t st, int ks) {
        const uint32_t kh = (uint32_t)(ks << 5);        // hi chunk base
        const uint32_t kl = kh + 64u;                   // lo chunk base
#pragma unroll
        for (int mt = 0; mt < 2; mt++) {
            ldsm4(ah[mt], st + rbA[mt] + ((kh + cA16) ^ swA[mt]));
            ldsm4(al[mt], st + rbA[mt] + ((kl + cA16) ^ swA[mt]));
        }
#pragma unroll
        for (int np = 0; np < 2; np++) {
            ldsm4(bh[np], st + B_OFF + rbB[np] + ((kh + cB16) ^ swB[np]));
            ldsm4(bl[np], st + B_OFF + rbB[np] + ((kl + cB16) ^ swB[np]));
        }
    };

    auto do_mmas = [&]() {
#pragma unroll
        for (int np = 0; np < 2; np++)
#pragma unroll
            for (int mt = 0; mt < 2; mt++)
#pragma unroll
                for (int h = 0; h < 2; h++) {
                    float* cc = c[mt][np * 2 + h];
                    mma16816(cc, ah[mt], bh[np] + 2 * h);
                    mma16816(cc, ah[mt], bl[np] + 2 * h);
                    mma16816(cc, al[mt], bh[np] + 2 * h);
                }
    };

#pragma unroll 1
    for (int it = 0; it < NIT; it++) {
        asm volatile("cp.async.wait_group 2;" ::: "memory");
        __syncthreads();

        const uint32_t st = base + (uint32_t)(it & 3) * STAGE;
        ld_frags(st, 0);
        // overlap next-stage global loads (slot (it+3)&3 == (it-1)&3, safe:
        // all warps finished reading it-1 before this iter's sync)
        if (it + 3 < NIT) load_stage(it + 3, (it + 3) & 3);
        else asm volatile("cp.async.commit_group;" ::: "memory");
        do_mmas();
        ld_frags(st, 1);
        do_mmas();
    }

    // Epilogue
#pragma unroll
    for (int mt = 0; mt < 2; mt++) {
#pragma unroll
        for (int nt = 0; nt < 4; nt++) {
            int m = m0 + wm * 32 + mt * 16 + gid;
            int n = n0 + wn * 32 + nt * 8 + tig * 2;
            float v0 = alpha * c[mt][nt][0];
            float v1 = alpha * c[mt][nt][1];
            float v2 = alpha * c[mt][nt][2];
            float v3 = alpha * c[mt][nt][3];
            if (MODE == 1) {
                float b0 = bias[n], b1 = bias[n + 1];
                v0 += b0; v1 += b1; v2 += b0; v3 += b1;
            }
            if (MODE == 2) {
                bf16 h0 = __float2bfloat16(v0);
                bf16 h1 = __float2bfloat16(v1);
                bf16 h2 = __float2bfloat16(v2);
                bf16 h3 = __float2bfloat16(v3);
                bf16 l0 = __float2bfloat16(v0 - __bfloat162float(h0));
                bf16 l1 = __float2bfloat16(v1 - __bfloat162float(h1));
                bf16 l2 = __float2bfloat16(v2 - __bfloat162float(h2));
                bf16 l3 = __float2bfloat16(v3 - __bfloat162float(h3));
                __nv_bfloat162 hh0{h0, h1}, hh1{h2, h3};
                __nv_bfloat162 ll0{l0, l1}, ll1{l2, l3};
                *(__nv_bfloat162*)&Ch[co + (size_t)m * ldc + n]       = hh0;
                *(__nv_bfloat162*)&Ch[co + (size_t)(m + 8) * ldc + n] = hh1;
                *(__nv_bfloat162*)&Cl[co + (size_t)m * ldc + n]       = ll0;
                *(__nv_bfloat162*)&Cl[co + (size_t)(m + 8) * ldc + n] = ll1;
            } else {
                *(float2*)&C[co + (size_t)m * ldc + n]       = make_float2(v0, v1);
                *(float2*)&C[co + (size_t)(m + 8) * ldc + n] = make_float2(v2, v3);
            }
        }
    }
}

// ---------------------------------------------------------------------------
// Elementwise fp32 -> (hi, lo) bf16 split
// ---------------------------------------------------------------------------
__global__ __launch_bounds__(256) void split_kernel(
    const float* __restrict__ in, bf16* __restrict__ oh, bf16* __restrict__ ol,
    long long n)
{
    long long i = (long long)blockIdx.x * 256 + threadIdx.x;
    long long stride = (long long)gridDim.x * 256;
    for (; i < n; i += stride) {
        float v = in[i];
        bf16 h = __float2bfloat16(v);
        oh[i] = h;
        ol[i] = __float2bfloat16(v - __bfloat162float(h));
    }
}

// ---------------------------------------------------------------------------
// Row softmax: read fp32 scores, write split bf16 probs.
// ---------------------------------------------------------------------------
__global__ __launch_bounds__(256) void softmax_kernel(
    const float* __restrict__ scores, bf16* __restrict__ ph, bf16* __restrict__ pl)
{
    const float* row = scores + (size_t)blockIdx.x * SEQ;
    bf16* rh = ph + (size_t)blockIdx.x * SEQ;
    bf16* rl = pl + (size_t)blockIdx.x * SEQ;
    const int t = threadIdx.x;

    float v[8];
    float m = -INFINITY;
#pragma unroll
    for (int i = 0; i < 8; i++) {
        v[i] = row[t + i * 256];
        m = fmaxf(m, v[i]);
    }
#pragma unroll
    for (int o = 16; o > 0; o >>= 1)
        m = fmaxf(m, __shfl_xor_sync(0xffffffffu, m, o));

    __shared__ float redmax[8], redsum[8];
    if ((t & 31) == 0) redmax[t >> 5] = m;
    __syncthreads();
    float mm = redmax[0];
#pragma unroll
    for (int i = 1; i < 8; i++) mm = fmaxf(mm, redmax[i]);

    float s = 0.f;
#pragma unroll
    for (int i = 0; i < 8; i++) { v[i] = __expf(v[i] - mm); s += v[i]; }
#pragma unroll
    for (int o = 16; o > 0; o >>= 1)
        s += __shfl_xor_sync(0xffffffffu, s, o);
    if ((t & 31) == 0) redsum[t >> 5] = s;
    __syncthreads();
    float ss = 0.f;
#pragma unroll
    for (int i = 0; i < 8; i++) ss += redsum[i];
    float inv = 1.0f / ss;

#pragma unroll
    for (int i = 0; i < 8; i++) {
        float p = v[i] * inv;
        bf16 h = __float2bfloat16(p);
        rh[t + i * 256] = h;
        rl[t + i * 256] = __float2bfloat16(p - __bfloat162float(h));
    }
}

// ---------------------------------------------------------------------------
// Per-batch transpose of a bf16 (hi, lo) pair: out[c][r] = in[r][c]
// ---------------------------------------------------------------------------
__global__ __launch_bounds__(256) void transpose_pair(
    const bf16* __restrict__ inh, const bf16* __restrict__ inl,
    bf16* __restrict__ outh, bf16* __restrict__ outl,
    int ld_in, int ld_out, long long sIn, long long sOut)
{
    __shared__ bf16 th[32][33];
    __shared__ bf16 tl[32][33];
    inh += (long long)blockIdx.z * sIn;   inl += (long long)blockIdx.z * sIn;
    outh += (long long)blockIdx.z * sOut; outl += (long long)blockIdx.z * sOut;
    const int x0 = blockIdx.x * 32;
    const int y0 = blockIdx.y * 32;

#pragma unroll
    for (int i = threadIdx.y; i < 32; i += 8) {
        th[i][threadIdx.x] = inh[(size_t)(y0 + i) * ld_in + x0 + threadIdx.x];
        tl[i][threadIdx.x] = inl[(size_t)(y0 + i) * ld_in + x0 + threadIdx.x];
    }
    __syncthreads();
#pragma unroll
    for (int i = threadIdx.y; i < 32; i += 8) {
        outh[(size_t)(x0 + i) * ld_out + y0 + threadIdx.x] = th[threadIdx.x][i];
        outl[(size_t)(x0 + i) * ld_out + y0 + threadIdx.x] = tl[threadIdx.x][i];
    }
}

// ---------------------------------------------------------------------------
extern "C" void kernel_launch(void* const* d_in, const int* in_sizes, int n_in,
                              void* d_out, int out_size)
{
    const float* x      = (const float*)d_in[0];   // [B,S,E]
    const float* w_qkv  = (const float*)d_in[1];   // [3H,E]
    const float* w_proj = (const float*)d_in[2];   // [E,H]
    const float* b_proj = (const float*)d_in[3];   // [E]
    float* y = (float*)d_out;                      // [B,S,E]

    bf16 *xh, *xl, *wqh, *wql, *wph, *wpl, *qkvh, *qkvl;
    bf16 *ph, *pl, *vTh, *vTl, *oh, *ol, *oTh, *oTl;
    float* scores;
    cudaGetSymbolAddress((void**)&xh, g_xh);     cudaGetSymbolAddress((void**)&xl, g_xl);
    cudaGetSymbolAddress((void**)&wqh, g_wqh);   cudaGetSymbolAddress((void**)&wql, g_wql);
    cudaGetSymbolAddress((void**)&wph, g_wph);   cudaGetSymbolAddress((void**)&wpl, g_wpl);
    cudaGetSymbolAddress((void**)&qkvh, g_qkvh); cudaGetSymbolAddress((void**)&qkvl, g_qkvl);
    cudaGetSymbolAddress((void**)&scores, g_scores);
    cudaGetSymbolAddress((void**)&ph, g_ph);     cudaGetSymbolAddress((void**)&pl, g_pl);
    cudaGetSymbolAddress((void**)&vTh, g_vTh);   cudaGetSymbolAddress((void**)&vTl, g_vTl);
    cudaGetSymbolAddress((void**)&oh, g_oh);     cudaGetSymbolAddress((void**)&ol, g_ol);
    cudaGetSymbolAddress((void**)&oTh, g_oTh);   cudaGetSymbolAddress((void**)&oTl, g_oTl);

    const int shm = 4 * 24576;   // 96KB -> 2 CTAs/SM
    cudaFuncSetAttribute(tc_gemm<0>, cudaFuncAttributeMaxDynamicSharedMemorySize, shm);
    cudaFuncSetAttribute(tc_gemm<1>, cudaFuncAttributeMaxDynamicSharedMemorySize, shm);
    cudaFuncSetAttribute(tc_gemm<2>, cudaFuncAttributeMaxDynamicSharedMemorySize, shm);

    const long long sQKV = (long long)SEQ * QKV3;
    const long long sSS  = (long long)SEQ * SEQ;
    const long long sSH  = (long long)SEQ * HSZ;
    const long long sHS  = (long long)HSZ * SEQ;

    // 0. split inputs into bf16 (hi, lo)
    split_kernel<<<1024, 256>>>(x,      xh,  xl,  (long long)BS * EMBED);
    split_kernel<<<512,  256>>>(w_qkv,  wqh, wql, (long long)QKV3 * EMBED);
    split_kernel<<<256,  256>>>(w_proj, wph, wpl, (long long)EMBED * HSZ);

    // 1. qkv = x @ w_qkv^T   [8192 x 3072 x 1024], split output. 3072 CTAs.
    tc_gemm<2><<<dim3(QKV3 / 128, BS / 64, 1), 256, shm>>>(
        xh, xl, wqh, wql, nullptr, qkvh, qkvl, nullptr,
        EMBED, EMBED, EMBED, QKV3, 0, 0, 0, 1.0f);

    // 2. scores = 0.125 * q @ k^T   4x [2048 x 2048 x 1024]. 2048 CTAs.
    tc_gemm<0><<<dim3(SEQ / 128, SEQ / 64, BATCH), 256, shm>>>(
        qkvh, qkvl, qkvh + HSZ, qkvl + HSZ, scores, nullptr, nullptr, nullptr,
        HSZ, QKV3, QKV3, SEQ, sQKV, sQKV, sSS, 0.125f);

    // 3. softmax -> split probs
    softmax_kernel<<<BATCH * SEQ, 256>>>(scores, ph, pl);

    // 4. vT = v^T per batch (v strided inside qkv split arrays)
    transpose_pair<<<dim3(HSZ / 32, SEQ / 32, BATCH), dim3(32, 8)>>>(
        qkvh + 2 * HSZ, qkvl + 2 * HSZ, vTh, vTl, QKV3, SEQ, sQKV, sHS);

    // 5. out = probs @ vT^T   4x [2048 x 1024 x 2048], split output. 1024 CTAs.
    tc_gemm<2><<<dim3(HSZ / 128, SEQ / 64, BATCH), 256, shm>>>(
        ph, pl, vTh, vTl, nullptr, oh, ol, nullptr,
        SEQ, SEQ, SEQ, HSZ, sSS, sHS, sSH, 1.0f);

    // 6. scrambling reshape == per-batch transpose (flat re-view)
    transpose_pair<<<dim3(HSZ / 32, SEQ / 32, BATCH), dim3(32, 8)>>>(
        oh, ol, oTh, oTl, HSZ, SEQ, sSH, sHS);

    // 7. y = out2 @ w_proj^T + b   [8192 x 1024 x 1024], fp32 + bias. 1024 CTAs.
    tc_gemm<1><<<dim3(EMBED / 128, BS / 64, 1), 256, shm>>>(
        oTh, oTl, wph, wpl, y, nullptr, nullptr, b_proj,
        HSZ, HSZ, HSZ, EMBED, 0, 0, 0, 1.0f);
}

// round 9
// speedup vs baseline: 1.0802x; 1.0802x over previous
#include <cuda_runtime.h>
#include <cuda_bf16.h>
#include <math.h>
#include <stdint.h>

// Problem constants
#define BATCH 4
#define SEQ   2048
#define EMBED 1024
#define HSZ   1024
#define QKV3  3072
#define BS    (BATCH*SEQ)

typedef __nv_bfloat16 bf16;

// Scratch (device globals -- no allocation allowed)
__device__ bf16  g_xh[(size_t)BS * EMBED];
__device__ bf16  g_xl[(size_t)BS * EMBED];
__device__ bf16  g_wqh[(size_t)QKV3 * EMBED];
__device__ bf16  g_wql[(size_t)QKV3 * EMBED];
__device__ bf16  g_wph[(size_t)EMBED * HSZ];
__device__ bf16  g_wpl[(size_t)EMBED * HSZ];
__device__ bf16  g_qkvh[(size_t)BS * QKV3];
__device__ bf16  g_qkvl[(size_t)BS * QKV3];
__device__ float g_scores[(size_t)BATCH * SEQ * SEQ];
__device__ bf16  g_ph[(size_t)BATCH * SEQ * SEQ];
__device__ bf16  g_pl[(size_t)BATCH * SEQ * SEQ];
__device__ bf16  g_vTh[(size_t)BATCH * HSZ * SEQ];
__device__ bf16  g_vTl[(size_t)BATCH * HSZ * SEQ];
__device__ bf16  g_oh[(size_t)BATCH * SEQ * HSZ];
__device__ bf16  g_ol[(size_t)BATCH * SEQ * HSZ];
__device__ bf16  g_oTh[(size_t)BATCH * HSZ * SEQ];
__device__ bf16  g_oTl[(size_t)BATCH * HSZ * SEQ];

// ---------------------------------------------------------------------------
__device__ __forceinline__ uint32_t smem_u32(const void* p) {
    uint32_t a;
    asm("{ .reg .u64 t; cvta.to.shared.u64 t, %1; cvt.u32.u64 %0, t; }"
        : "=r"(a) : "l"(p));
    return a;
}
__device__ __forceinline__ void cp16(uint32_t dst, const void* src) {
    asm volatile("cp.async.cg.shared.global [%0], [%1], 16;"
                 :: "r"(dst), "l"(src));
}
__device__ __forceinline__ void ldsm4(uint32_t* r, uint32_t addr) {
    asm volatile("ldmatrix.sync.aligned.m8n8.x4.shared.b16 {%0,%1,%2,%3}, [%4];"
                 : "=r"(r[0]), "=r"(r[1]), "=r"(r[2]), "=r"(r[3]) : "r"(addr));
}
__device__ __forceinline__ void mma16816(float* c, const uint32_t* a,
                                         const uint32_t* b) {
    asm volatile(
        "mma.sync.aligned.m16n8k16.row.col.f32.bf16.bf16.f32 "
        "{%0,%1,%2,%3}, {%4,%5,%6,%7}, {%8,%9}, {%0,%1,%2,%3};"
        : "+f"(c[0]), "+f"(c[1]), "+f"(c[2]), "+f"(c[3])
        : "r"(a[0]), "r"(a[1]), "r"(a[2]), "r"(a[3]), "r"(b[0]), "r"(b[1]));
}

// ---------------------------------------------------------------------------
// bf16x3 NT GEMM: C[m,n] = alpha * sum_k (Ah+Al)[m,k]*(Bh+Bl)[n,k]  (3 MMAs)
// BM=128, BN=128, BK=64. 256 threads = 8 warps (4m x 2n); warp tile 32x64
// (mt=2, np=4) -> 48 MMAs : 12 ldsm4 per k-step (4:1).
// 3-stage cp.async pipeline (64KB/stage, 192KB), ONE __syncthreads per K-iter,
// fragment double-buffering across k-steps (R7-proven ordering).
// MODE 0: fp32 out; 1: fp32+bias; 2: split bf16 out (Ch,Cl)
// ---------------------------------------------------------------------------
template <int MODE>
__global__ __launch_bounds__(256, 1) void tc_gemm(
    const bf16* __restrict__ Ah, const bf16* __restrict__ Al,
    const bf16* __restrict__ Bh, const bf16* __restrict__ Bl,
    float* __restrict__ C, bf16* __restrict__ Ch, bf16* __restrict__ Cl,
    const float* __restrict__ bias,
    int K, int lda, int ldb, int ldc,
    long long sA, long long sB, long long sC, float alpha)
{
    constexpr uint32_t A_LIMB = 16384u;       // 128 rows x 128B
    constexpr uint32_t B_OFF  = 32768u;
    constexpr uint32_t B_LIMB = 16384u;       // 128 rows x 128B
    constexpr uint32_t STAGE  = 65536u;       // 64KB

    extern __shared__ char dsm[];
    const uint32_t base = smem_u32(dsm);

    const int tid = threadIdx.x;
    const int wid = tid >> 5, lane = tid & 31;
    const int wm = wid >> 1, wn = wid & 1;     // 4 x 2 warps
    const int gid = lane >> 2, tig = lane & 3;

    Ah += (long long)blockIdx.z * sA;  Al += (long long)blockIdx.z * sA;
    Bh += (long long)blockIdx.z * sB;  Bl += (long long)blockIdx.z * sB;
    const long long co = (long long)blockIdx.z * sC;
    const int m0 = blockIdx.y * 128;
    const int n0 = blockIdx.x * 128;

    // ldmatrix per-lane row/chunk decode
    const int rAl = lane & 15,                       cA16 = (lane >> 4) << 4;
    const int rBl = (lane & 7) | ((lane >> 4) << 3), cB16 = ((lane >> 3) & 1) << 4;

    uint32_t rbA[2], swA[2], rbB[4], swB[4];
#pragma unroll
    for (int mt = 0; mt < 2; mt++) {
        int row = wm * 32 + mt * 16 + rAl;
        rbA[mt] = (uint32_t)row << 7;
        swA[mt] = (uint32_t)(row & 7) << 4;
    }
#pragma unroll
    for (int np = 0; np < 4; np++) {
        int row = wn * 64 + np * 16 + rBl;
        rbB[np] = (uint32_t)row << 7;
        swB[np] = (uint32_t)(row & 7) << 4;
    }

    float c[2][8][4];
#pragma unroll
    for (int mt = 0; mt < 2; mt++)
#pragma unroll
        for (int nt = 0; nt < 8; nt++)
#pragma unroll
            for (int i = 0; i < 4; i++) c[mt][nt][i] = 0.f;

    const int NIT = K >> 6;   // BK = 64

    auto load_stage = [&](int it, int s) {
        const uint32_t st = base + (uint32_t)s * STAGE;
        const int c0 = it << 6;
#pragma unroll
        for (int i = 0; i < 4; i++) {              // A: 128 rows x 8 cp16
            int idx = tid + i * 256;
            int r = idx >> 3, ch = idx & 7;
            uint32_t off = ((uint32_t)r << 7) + (((uint32_t)ch << 4) ^ ((uint32_t)(r & 7) << 4));
            cp16(st + off,          Ah + (size_t)(m0 + r) * lda + c0 + ch * 8);
            cp16(st + A_LIMB + off, Al + (size_t)(m0 + r) * lda + c0 + ch * 8);
        }
#pragma unroll
        for (int i = 0; i < 4; i++) {              // B: 128 rows x 8 cp16
            int idx = tid + i * 256;
            int r = idx >> 3, ch = idx & 7;
            uint32_t off = ((uint32_t)r << 7) + (((uint32_t)ch << 4) ^ ((uint32_t)(r & 7) << 4));
            cp16(st + B_OFF + off,          Bh + (size_t)(n0 + r) * ldb + c0 + ch * 8);
            cp16(st + B_OFF + B_LIMB + off, Bl + (size_t)(n0 + r) * ldb + c0 + ch * 8);
        }
        asm volatile("cp.async.commit_group;" ::: "memory");
    };

    load_stage(0, 0);
    load_stage(1, 1);

    // Fragment double buffers
    uint32_t ah[2][2][4], al[2][2][4];   // [buf][mt][reg]
    uint32_t bh[2][4][4], bl[2][4][4];   // [buf][np][reg]

    auto ld_frags = [&](uint32_t st, int ks, int buf) {
        const uint32_t kb = (uint32_t)ks << 5;
#pragma unroll
        for (int mt = 0; mt < 2; mt++) {
            uint32_t a = st + rbA[mt] + ((kb + cA16) ^ swA[mt]);
            ldsm4(ah[buf][mt], a);
            ldsm4(al[buf][mt], a + A_LIMB);
        }
#pragma unroll
        for (int np = 0; np < 4; np++) {
            uint32_t b = st + B_OFF + rbB[np] + ((kb + cB16) ^ swB[np]);
            ldsm4(bh[buf][np], b);
            ldsm4(bl[buf][np], b + B_LIMB);
        }
    };

    auto do_mmas = [&](int buf) {
#pragma unroll
        for (int np = 0; np < 4; np++)
#pragma unroll
            for (int mt = 0; mt < 2; mt++)
#pragma unroll
                for (int h = 0; h < 2; h++) {
                    float* cc = c[mt][np * 2 + h];
                    mma16816(cc, ah[buf][mt], bh[buf][np] + 2 * h);
                    mma16816(cc, ah[buf][mt], bl[buf][np] + 2 * h);
                    mma16816(cc, al[buf][mt], bh[buf][np] + 2 * h);
                }
    };

#pragma unroll 1
    for (int it = 0; it < NIT; it++) {
        asm volatile("cp.async.wait_group 1;" ::: "memory");
        __syncthreads();

        const uint32_t st = base + (uint32_t)(it % 3) * STAGE;
        ld_frags(st, 0, 0);
#pragma unroll
        for (int ks = 0; ks < 4; ks++) {
            if (ks < 3) {
                ld_frags(st, ks + 1, (ks + 1) & 1);   // prefetch next k-step
            } else {
                // overlap next-stage global loads with last k-step's MMAs;
                // slot (it+2)%3 == (it-1)%3 was fully consumed before this
                // iteration's __syncthreads -> safe to overwrite.
                if (it + 2 < NIT) load_stage(it + 2, (it + 2) % 3);
                else asm volatile("cp.async.commit_group;" ::: "memory");
            }
            do_mmas(ks & 1);
        }
    }

    // Epilogue
#pragma unroll
    for (int mt = 0; mt < 2; mt++) {
#pragma unroll
        for (int nt = 0; nt < 8; nt++) {
            int m = m0 + wm * 32 + mt * 16 + gid;
            int n = n0 + wn * 64 + nt * 8 + tig * 2;
            float v0 = alpha * c[mt][nt][0];
            float v1 = alpha * c[mt][nt][1];
            float v2 = alpha * c[mt][nt][2];
            float v3 = alpha * c[mt][nt][3];
            if (MODE == 1) {
                float b0 = bias[n], b1 = bias[n + 1];
                v0 += b0; v1 += b1; v2 += b0; v3 += b1;
            }
            if (MODE == 2) {
                bf16 h0 = __float2bfloat16(v0);
                bf16 h1 = __float2bfloat16(v1);
                bf16 h2 = __float2bfloat16(v2);
                bf16 h3 = __float2bfloat16(v3);
                bf16 l0 = __float2bfloat16(v0 - __bfloat162float(h0));
                bf16 l1 = __float2bfloat16(v1 - __bfloat162float(h1));
                bf16 l2 = __float2bfloat16(v2 - __bfloat162float(h2));
                bf16 l3 = __float2bfloat16(v3 - __bfloat162float(h3));
                __nv_bfloat162 hh0{h0, h1}, hh1{h2, h3};
                __nv_bfloat162 ll0{l0, l1}, ll1{l2, l3};
                *(__nv_bfloat162*)&Ch[co + (size_t)m * ldc + n]       = hh0;
                *(__nv_bfloat162*)&Ch[co + (size_t)(m + 8) * ldc + n] = hh1;
                *(__nv_bfloat162*)&Cl[co + (size_t)m * ldc + n]       = ll0;
                *(__nv_bfloat162*)&Cl[co + (size_t)(m + 8) * ldc + n] = ll1;
            } else {
                *(float2*)&C[co + (size_t)m * ldc + n]       = make_float2(v0, v1);
                *(float2*)&C[co + (size_t)(m + 8) * ldc + n] = make_float2(v2, v3);
            }
        }
    }
}

// ---------------------------------------------------------------------------
// Elementwise fp32 -> (hi, lo) bf16 split
// ---------------------------------------------------------------------------
__global__ __launch_bounds__(256) void split_kernel(
    const float* __restrict__ in, bf16* __restrict__ oh, bf16* __restrict__ ol,
    long long n)
{
    long long i = (long long)blockIdx.x * 256 + threadIdx.x;
    long long stride = (long long)gridDim.x * 256;
    for (; i < n; i += stride) {
        float v = in[i];
        bf16 h = __float2bfloat16(v);
        oh[i] = h;
        ol[i] = __float2bfloat16(v - __bfloat162float(h));
    }
}

// ---------------------------------------------------------------------------
// Row softmax: read fp32 scores, write split bf16 probs.
// ---------------------------------------------------------------------------
__global__ __launch_bounds__(256) void softmax_kernel(
    const float* __restrict__ scores, bf16* __restrict__ ph, bf16* __restrict__ pl)
{
    const float* row = scores + (size_t)blockIdx.x * SEQ;
    bf16* rh = ph + (size_t)blockIdx.x * SEQ;
    bf16* rl = pl + (size_t)blockIdx.x * SEQ;
    const int t = threadIdx.x;

    float v[8];
    float m = -INFINITY;
#pragma unroll
    for (int i = 0; i < 8; i++) {
        v[i] = row[t + i * 256];
        m = fmaxf(m, v[i]);
    }
#pragma unroll
    for (int o = 16; o > 0; o >>= 1)
        m = fmaxf(m, __shfl_xor_sync(0xffffffffu, m, o));

    __shared__ float redmax[8], redsum[8];
    if ((t & 31) == 0) redmax[t >> 5] = m;
    __syncthreads();
    float mm = redmax[0];
#pragma unroll
    for (int i = 1; i < 8; i++) mm = fmaxf(mm, redmax[i]);

    float s = 0.f;
#pragma unroll
    for (int i = 0; i < 8; i++) { v[i] = __expf(v[i] - mm); s += v[i]; }
#pragma unroll
    for (int o = 16; o > 0; o >>= 1)
        s += __shfl_xor_sync(0xffffffffu, s, o);
    if ((t & 31) == 0) redsum[t >> 5] = s;
    __syncthreads();
    float ss = 0.f;
#pragma unroll
    for (int i = 0; i < 8; i++) ss += redsum[i];
    float inv = 1.0f / ss;

#pragma unroll
    for (int i = 0; i < 8; i++) {
        float p = v[i] * inv;
        bf16 h = __float2bfloat16(p);
        rh[t + i * 256] = h;
        rl[t + i * 256] = __float2bfloat16(p - __bfloat162float(h));
    }
}

// ---------------------------------------------------------------------------
// Per-batch transpose of a bf16 (hi, lo) pair: out[c][r] = in[r][c]
// ---------------------------------------------------------------------------
__global__ __launch_bounds__(256) void transpose_pair(
    const bf16* __restrict__ inh, const bf16* __restrict__ inl,
    bf16* __restrict__ outh, bf16* __restrict__ outl,
    int ld_in, int ld_out, long long sIn, long long sOut)
{
    __shared__ bf16 th[32][33];
    __shared__ bf16 tl[32][33];
    inh += (long long)blockIdx.z * sIn;   inl += (long long)blockIdx.z * sIn;
    outh += (long long)blockIdx.z * sOut; outl += (long long)blockIdx.z * sOut;
    const int x0 = blockIdx.x * 32;
    const int y0 = blockIdx.y * 32;

#pragma unroll
    for (int i = threadIdx.y; i < 32; i += 8) {
        th[i][threadIdx.x] = inh[(size_t)(y0 + i) * ld_in + x0 + threadIdx.x];
        tl[i][threadIdx.x] = inl[(size_t)(y0 + i) * ld_in + x0 + threadIdx.x];
    }
    __syncthreads();
#pragma unroll
    for (int i = threadIdx.y; i < 32; i += 8) {
        outh[(size_t)(x0 + i) * ld_out + y0 + threadIdx.x] = th[threadIdx.x][i];
        outl[(size_t)(x0 + i) * ld_out + y0 + threadIdx.x] = tl[threadIdx.x][i];
    }
}

// ---------------------------------------------------------------------------
extern "C" void kernel_launch(void* const* d_in, const int* in_sizes, int n_in,
                              void* d_out, int out_size)
{
    const float* x      = (const float*)d_in[0];   // [B,S,E]
    const float* w_qkv  = (const float*)d_in[1];   // [3H,E]
    const float* w_proj = (const float*)d_in[2];   // [E,H]
    const float* b_proj = (const float*)d_in[3];   // [E]
    float* y = (float*)d_out;                      // [B,S,E]

    bf16 *xh, *xl, *wqh, *wql, *wph, *wpl, *qkvh, *qkvl;
    bf16 *ph, *pl, *vTh, *vTl, *oh, *ol, *oTh, *oTl;
    float* scores;
    cudaGetSymbolAddress((void**)&xh, g_xh);     cudaGetSymbolAddress((void**)&xl, g_xl);
    cudaGetSymbolAddress((void**)&wqh, g_wqh);   cudaGetSymbolAddress((void**)&wql, g_wql);
    cudaGetSymbolAddress((void**)&wph, g_wph);   cudaGetSymbolAddress((void**)&wpl, g_wpl);
    cudaGetSymbolAddress((void**)&qkvh, g_qkvh); cudaGetSymbolAddress((void**)&qkvl, g_qkvl);
    cudaGetSymbolAddress((void**)&scores, g_scores);
    cudaGetSymbolAddress((void**)&ph, g_ph);     cudaGetSymbolAddress((void**)&pl, g_pl);
    cudaGetSymbolAddress((void**)&vTh, g_vTh);   cudaGetSymbolAddress((void**)&vTl, g_vTl);
    cudaGetSymbolAddress((void**)&oh, g_oh);     cudaGetSymbolAddress((void**)&ol, g_ol);
    cudaGetSymbolAddress((void**)&oTh, g_oTh);   cudaGetSymbolAddress((void**)&oTl, g_oTl);

    const int shm = 3 * 65536;   // 192KB
    cudaFuncSetAttribute(tc_gemm<0>, cudaFuncAttributeMaxDynamicSharedMemorySize, shm);
    cudaFuncSetAttribute(tc_gemm<1>, cudaFuncAttributeMaxDynamicSharedMemorySize, shm);
    cudaFuncSetAttribute(tc_gemm<2>, cudaFuncAttributeMaxDynamicSharedMemorySize, shm);

    const long long sQKV = (long long)SEQ * QKV3;
    const long long sSS  = (long long)SEQ * SEQ;
    const long long sSH  = (long long)SEQ * HSZ;
    const long long sHS  = (long long)HSZ * SEQ;

    // 0. split inputs into bf16 (hi, lo)
    split_kernel<<<1024, 256>>>(x,      xh,  xl,  (long long)BS * EMBED);
    split_kernel<<<512,  256>>>(w_qkv,  wqh, wql, (long long)QKV3 * EMBED);
    split_kernel<<<256,  256>>>(w_proj, wph, wpl, (long long)EMBED * HSZ);

    // 1. qkv = x @ w_qkv^T   [8192 x 3072 x 1024], split output. 1536 CTAs.
    tc_gemm<2><<<dim3(QKV3 / 128, BS / 128, 1), 256, shm>>>(
        xh, xl, wqh, wql, nullptr, qkvh, qkvl, nullptr,
        EMBED, EMBED, EMBED, QKV3, 0, 0, 0, 1.0f);

    // 2. scores = 0.125 * q @ k^T   4x [2048 x 2048 x 1024]. 1024 CTAs.
    tc_gemm<0><<<dim3(SEQ / 128, SEQ / 128, BATCH), 256, shm>>>(
        qkvh, qkvl, qkvh + HSZ, qkvl + HSZ, scores, nullptr, nullptr, nullptr,
        HSZ, QKV3, QKV3, SEQ, sQKV, sQKV, sSS, 0.125f);

    // 3. softmax -> split probs
    softmax_kernel<<<BATCH * SEQ, 256>>>(scores, ph, pl);

    // 4. vT = v^T per batch (v strided inside qkv split arrays)
    transpose_pair<<<dim3(HSZ / 32, SEQ / 32, BATCH), dim3(32, 8)>>>(
        qkvh + 2 * HSZ, qkvl + 2 * HSZ, vTh, vTl, QKV3, SEQ, sQKV, sHS);

    // 5. out = probs @ vT^T   4x [2048 x 1024 x 2048], split output. 512 CTAs.
    tc_gemm<2><<<dim3(HSZ / 128, SEQ / 128, BATCH), 256, shm>>>(
        ph, pl, vTh, vTl, nullptr, oh, ol, nullptr,
        SEQ, SEQ, SEQ, HSZ, sSS, sHS, sSH, 1.0f);

    // 6. scrambling reshape == per-batch transpose (flat re-view)
    transpose_pair<<<dim3(HSZ / 32, SEQ / 32, BATCH), dim3(32, 8)>>>(
        oh, ol, oTh, oTl, HSZ, SEQ, sSH, sHS);

    // 7. y = out2 @ w_proj^T + b   [8192 x 1024 x 1024], fp32 + bias. 512 CTAs.
    tc_gemm<1><<<dim3(EMBED / 128, BS / 128, 1), 256, shm>>>(
        oTh, oTl, wph, wpl, y, nullptr, nullptr, b_proj,
        HSZ, HSZ, HSZ, EMBED, 0, 0, 0, 1.0f);
}

// round 10
// speedup vs baseline: 1.1067x; 1.0245x over previous
#include <cuda_runtime.h>
#include <cuda_fp16.h>
#include <math.h>
#include <stdint.h>

// Problem constants
#define BATCH 4
#define SEQ   2048
#define EMBED 1024
#define HSZ   1024
#define QKV3  3072
#define BS    (BATCH*SEQ)

typedef __half h16;

// Scratch (device globals -- no allocation allowed)
__device__ h16   g_xh[(size_t)BS * EMBED];
__device__ h16   g_xl[(size_t)BS * EMBED];
__device__ h16   g_wqh[(size_t)QKV3 * EMBED];
__device__ h16   g_wql[(size_t)QKV3 * EMBED];
__device__ h16   g_wph[(size_t)EMBED * HSZ];
__device__ h16   g_wpl[(size_t)EMBED * HSZ];
__device__ h16   g_qkvh[(size_t)BS * QKV3];
__device__ h16   g_qkvl[(size_t)BS * QKV3];
__device__ float g_scores[(size_t)BATCH * SEQ * SEQ];
__device__ h16   g_ph[(size_t)BATCH * SEQ * SEQ];
__device__ h16   g_pl[(size_t)BATCH * SEQ * SEQ];
__device__ h16   g_vTh[(size_t)BATCH * HSZ * SEQ];
__device__ h16   g_vTl[(size_t)BATCH * HSZ * SEQ];
__device__ h16   g_oh[(size_t)BATCH * SEQ * HSZ];
__device__ h16   g_ol[(size_t)BATCH * SEQ * HSZ];
__device__ h16   g_oTh[(size_t)BATCH * HSZ * SEQ];
__device__ h16   g_oTl[(size_t)BATCH * HSZ * SEQ];

// ---------------------------------------------------------------------------
__device__ __forceinline__ uint32_t smem_u32(const void* p) {
    uint32_t a;
    asm("{ .reg .u64 t; cvta.to.shared.u64 t, %1; cvt.u32.u64 %0, t; }"
        : "=r"(a) : "l"(p));
    return a;
}
__device__ __forceinline__ void cp16(uint32_t dst, const void* src) {
    asm volatile("cp.async.cg.shared.global [%0], [%1], 16;"
                 :: "r"(dst), "l"(src));
}
__device__ __forceinline__ void ldsm4(uint32_t* r, uint32_t addr) {
    asm volatile("ldmatrix.sync.aligned.m8n8.x4.shared.b16 {%0,%1,%2,%3}, [%4];"
                 : "=r"(r[0]), "=r"(r[1]), "=r"(r[2]), "=r"(r[3]) : "r"(addr));
}
// fp16 inputs, fp32 accumulators (main term)
__device__ __forceinline__ void mma_f32(float* c, const uint32_t* a,
                                        const uint32_t* b) {
    asm volatile(
        "mma.sync.aligned.m16n8k16.row.col.f32.f16.f16.f32 "
        "{%0,%1,%2,%3}, {%4,%5,%6,%7}, {%8,%9}, {%0,%1,%2,%3};"
        : "+f"(c[0]), "+f"(c[1]), "+f"(c[2]), "+f"(c[3])
        : "r"(a[0]), "r"(a[1]), "r"(a[2]), "r"(a[3]), "r"(b[0]), "r"(b[1]));
}
// fp16 inputs, fp16 accumulators (cross terms, ~2^-11 of result magnitude)
__device__ __forceinline__ void mma_f16(uint32_t* d, const uint32_t* a,
                                        const uint32_t* b) {
    asm volatile(
        "mma.sync.aligned.m16n8k16.row.col.f16.f16.f16.f16 "
        "{%0,%1}, {%2,%3,%4,%5}, {%6,%7}, {%0,%1};"
        : "+r"(d[0]), "+r"(d[1])
        : "r"(a[0]), "r"(a[1]), "r"(a[2]), "r"(a[3]), "r"(b[0]), "r"(b[1]));
}

// ---------------------------------------------------------------------------
// fp16x3 NT GEMM: C[m,n] = alpha * sum_k (Ah+Al)[m,k]*(Bh+Bl)[n,k]
// main term ah*bh in fp32 accum; cross terms ah*bl + al*bh in fp16 accum
// (cross terms are ~2^-11 of result -> f16 accumulation error ~2e-6 relative).
// BM=64, BN=128, BK=64. 256 threads = 8 warps (2m x 4n); warp tile 32x32.
// 4-stage cp.async pipeline (48KB/stage, 192KB), ONE __syncthreads per K-iter,
// fragment double-buffering across k-steps (R7-proven ordering).
// MODE 0: fp32 out; 1: fp32+bias; 2: split fp16 out (Ch,Cl)
// ---------------------------------------------------------------------------
template <int MODE>
__global__ __launch_bounds__(256, 1) void tc_gemm(
    const h16* __restrict__ Ah, const h16* __restrict__ Al,
    const h16* __restrict__ Bh, const h16* __restrict__ Bl,
    float* __restrict__ C, h16* __restrict__ Ch, h16* __restrict__ Cl,
    const float* __restrict__ bias,
    int K, int lda, int ldb, int ldc,
    long long sA, long long sB, long long sC, float alpha)
{
    constexpr uint32_t A_LIMB = 8192u;        // 64 rows x 128B
    constexpr uint32_t B_OFF  = 16384u;
    constexpr uint32_t B_LIMB = 16384u;       // 128 rows x 128B
    constexpr uint32_t STAGE  = 49152u;       // 48KB

    extern __shared__ char dsm[];
    const uint32_t base = smem_u32(dsm);

    const int tid = threadIdx.x;
    const int wid = tid >> 5, lane = tid & 31;
    const int wm = wid >> 2, wn = wid & 3;     // 2 x 4 warps
    const int gid = lane >> 2, tig = lane & 3;

    Ah += (long long)blockIdx.z * sA;  Al += (long long)blockIdx.z * sA;
    Bh += (long long)blockIdx.z * sB;  Bl += (long long)blockIdx.z * sB;
    const long long co = (long long)blockIdx.z * sC;
    const int m0 = blockIdx.y * 64;
    const int n0 = blockIdx.x * 128;

    // ldmatrix per-lane row/chunk decode
    const int rAl = lane & 15,                       cA16 = (lane >> 4) << 4;
    const int rBl = (lane & 7) | ((lane >> 4) << 3), cB16 = ((lane >> 3) & 1) << 4;

    uint32_t rbA[2], swA[2], rbB[2], swB[2];
#pragma unroll
    for (int mt = 0; mt < 2; mt++) {
        int row = wm * 32 + mt * 16 + rAl;
        rbA[mt] = (uint32_t)row << 7;
        swA[mt] = (uint32_t)(row & 7) << 4;
    }
#pragma unroll
    for (int np = 0; np < 2; np++) {
        int row = wn * 32 + np * 16 + rBl;
        rbB[np] = (uint32_t)row << 7;
        swB[np] = (uint32_t)(row & 7) << 4;
    }

    float c[2][4][4];
    uint32_t cf[2][4][2];                      // f16x2 cross accumulators
#pragma unroll
    for (int mt = 0; mt < 2; mt++)
#pragma unroll
        for (int nt = 0; nt < 4; nt++) {
#pragma unroll
            for (int i = 0; i < 4; i++) c[mt][nt][i] = 0.f;
            cf[mt][nt][0] = 0u; cf[mt][nt][1] = 0u;
        }

    const int NIT = K >> 6;   // BK = 64

    auto load_stage = [&](int it, int s) {
        const uint32_t st = base + (uint32_t)s * STAGE;
        const int c0 = it << 6;
#pragma unroll
        for (int i = 0; i < 2; i++) {              // A: 64 rows x 8 cp16
            int idx = tid + i * 256;
            int r = idx >> 3, ch = idx & 7;
            uint32_t off = ((uint32_t)r << 7) + (((uint32_t)ch << 4) ^ ((uint32_t)(r & 7) << 4));
            cp16(st + off,          Ah + (size_t)(m0 + r) * lda + c0 + ch * 8);
            cp16(st + A_LIMB + off, Al + (size_t)(m0 + r) * lda + c0 + ch * 8);
        }
#pragma unroll
        for (int i = 0; i < 4; i++) {              // B: 128 rows x 8 cp16
            int idx = tid + i * 256;
            int r = idx >> 3, ch = idx & 7;
            uint32_t off = ((uint32_t)r << 7) + (((uint32_t)ch << 4) ^ ((uint32_t)(r & 7) << 4));
            cp16(st + B_OFF + off,          Bh + (size_t)(n0 + r) * ldb + c0 + ch * 8);
            cp16(st + B_OFF + B_LIMB + off, Bl + (size_t)(n0 + r) * ldb + c0 + ch * 8);
        }
        asm volatile("cp.async.commit_group;" ::: "memory");
    };

    load_stage(0, 0);
    load_stage(1, 1);
    load_stage(2, 2);

    // Fragment double buffers
    uint32_t ah[2][2][4], al[2][2][4];   // [buf][mt][reg]
    uint32_t bh[2][2][4], bl[2][2][4];   // [buf][np][reg]

    auto ld_frags = [&](uint32_t st, int ks, int buf) {
        const uint32_t kb = (uint32_t)ks << 5;
#pragma unroll
        for (int mt = 0; mt < 2; mt++) {
            uint32_t a = st + rbA[mt] + ((kb + cA16) ^ swA[mt]);
            ldsm4(ah[buf][mt], a);
            ldsm4(al[buf][mt], a + A_LIMB);
        }
#pragma unroll
        for (int np = 0; np < 2; np++) {
            uint32_t b = st + B_OFF + rbB[np] + ((kb + cB16) ^ swB[np]);
            ldsm4(bh[buf][np], b);
            ldsm4(bl[buf][np], b + B_LIMB);
        }
    };

    auto do_mmas = [&](int buf) {
#pragma unroll
        for (int np = 0; np < 2; np++)
#pragma unroll
            for (int mt = 0; mt < 2; mt++)
#pragma unroll
                for (int h = 0; h < 2; h++) {
                    float*    cc = c[mt][np * 2 + h];
                    uint32_t* xf = cf[mt][np * 2 + h];
                    mma_f32(cc, ah[buf][mt], bh[buf][np] + 2 * h);
                    mma_f16(xf, ah[buf][mt], bl[buf][np] + 2 * h);
                    mma_f16(xf, al[buf][mt], bh[buf][np] + 2 * h);
                }
    };

#pragma unroll 1
    for (int it = 0; it < NIT; it++) {
        asm volatile("cp.async.wait_group 2;" ::: "memory");
        __syncthreads();

        const uint32_t st = base + (uint32_t)(it & 3) * STAGE;
        ld_frags(st, 0, 0);
#pragma unroll
        for (int ks = 0; ks < 4; ks++) {
            if (ks < 3) {
                ld_frags(st, ks + 1, (ks + 1) & 1);   // prefetch next k-step
            } else {
                // overlap next-stage global loads with last k-step's MMAs;
                // slot (it+3)&3 == (it-1)&3 was fully consumed before this
                // iteration's __syncthreads -> safe to overwrite.
                if (it + 3 < NIT) load_stage(it + 3, (it + 3) & 3);
                else asm volatile("cp.async.commit_group;" ::: "memory");
            }
            do_mmas(ks & 1);
        }
    }

    // Epilogue: result = main(f32) + cross(f16x2 unpacked)
#pragma unroll
    for (int mt = 0; mt < 2; mt++) {
#pragma unroll
        for (int nt = 0; nt < 4; nt++) {
            int m = m0 + wm * 32 + mt * 16 + gid;
            int n = n0 + wn * 32 + nt * 8 + tig * 2;
            __half2 u0 = *reinterpret_cast<__half2*>(&cf[mt][nt][0]);
            __half2 u1 = *reinterpret_cast<__half2*>(&cf[mt][nt][1]);
            float v0 = alpha * (c[mt][nt][0] + __low2float(u0));
            float v1 = alpha * (c[mt][nt][1] + __high2float(u0));
            float v2 = alpha * (c[mt][nt][2] + __low2float(u1));
            float v3 = alpha * (c[mt][nt][3] + __high2float(u1));
            if (MODE == 1) {
                float b0 = bias[n], b1 = bias[n + 1];
                v0 += b0; v1 += b1; v2 += b0; v3 += b1;
            }
            if (MODE == 2) {
                h16 h0 = __float2half(v0);
                h16 h1 = __float2half(v1);
                h16 h2 = __float2half(v2);
                h16 h3 = __float2half(v3);
                h16 l0 = __float2half(v0 - __half2float(h0));
                h16 l1 = __float2half(v1 - __half2float(h1));
                h16 l2 = __float2half(v2 - __half2float(h2));
                h16 l3 = __float2half(v3 - __half2float(h3));
                __half2 hh0{h0, h1}, hh1{h2, h3};
                __half2 ll0{l0, l1}, ll1{l2, l3};
                *(__half2*)&Ch[co + (size_t)m * ldc + n]       = hh0;
                *(__half2*)&Ch[co + (size_t)(m + 8) * ldc + n] = hh1;
                *(__half2*)&Cl[co + (size_t)m * ldc + n]       = ll0;
                *(__half2*)&Cl[co + (size_t)(m + 8) * ldc + n] = ll1;
            } else {
                *(float2*)&C[co + (size_t)m * ldc + n]       = make_float2(v0, v1);
                *(float2*)&C[co + (size_t)(m + 8) * ldc + n] = make_float2(v2, v3);
            }
        }
    }
}

// ---------------------------------------------------------------------------
// Elementwise fp32 -> (hi, lo) fp16 split
// ---------------------------------------------------------------------------
__global__ __launch_bounds__(256) void split_kernel(
    const float* __restrict__ in, h16* __restrict__ oh, h16* __restrict__ ol,
    long long n)
{
    long long i = (long long)blockIdx.x * 256 + threadIdx.x;
    long long stride = (long long)gridDim.x * 256;
    for (; i < n; i += stride) {
        float v = in[i];
        h16 h = __float2half(v);
        oh[i] = h;
        ol[i] = __float2half(v - __half2float(h));
    }
}

// ---------------------------------------------------------------------------
// Row softmax: read fp32 scores, write split fp16 probs.
// ---------------------------------------------------------------------------
__global__ __launch_bounds__(256) void softmax_kernel(
    const float* __restrict__ scores, h16* __restrict__ ph, h16* __restrict__ pl)
{
    const float* row = scores + (size_t)blockIdx.x * SEQ;
    h16* rh = ph + (size_t)blockIdx.x * SEQ;
    h16* rl = pl + (size_t)blockIdx.x * SEQ;
    const int t = threadIdx.x;

    float v[8];
    float m = -INFINITY;
#pragma unroll
    for (int i = 0; i < 8; i++) {
        v[i] = row[t + i * 256];
        m = fmaxf(m, v[i]);
    }
#pragma unroll
    for (int o = 16; o > 0; o >>= 1)
        m = fmaxf(m, __shfl_xor_sync(0xffffffffu, m, o));

    __shared__ float redmax[8], redsum[8];
    if ((t & 31) == 0) redmax[t >> 5] = m;
    __syncthreads();
    float mm = redmax[0];
#pragma unroll
    for (int i = 1; i < 8; i++) mm = fmaxf(mm, redmax[i]);

    float s = 0.f;
#pragma unroll
    for (int i = 0; i < 8; i++) { v[i] = __expf(v[i] - mm); s += v[i]; }
#pragma unroll
    for (int o = 16; o > 0; o >>= 1)
        s += __shfl_xor_sync(0xffffffffu, s, o);
    if ((t & 31) == 0) redsum[t >> 5] = s;
    __syncthreads();
    float ss = 0.f;
#pragma unroll
    for (int i = 0; i < 8; i++) ss += redsum[i];
    float inv = 1.0f / ss;

#pragma unroll
    for (int i = 0; i < 8; i++) {
        float p = v[i] * inv;
        h16 h = __float2half(p);
        rh[t + i * 256] = h;
        rl[t + i * 256] = __float2half(p - __half2float(h));
    }
}

// ---------------------------------------------------------------------------
// Per-batch transpose of an fp16 (hi, lo) pair: out[c][r] = in[r][c]
// ---------------------------------------------------------------------------
__global__ __launch_bounds__(256) void transpose_pair(
    const h16* __restrict__ inh, const h16* __restrict__ inl,
    h16* __restrict__ outh, h16* __restrict__ outl,
    int ld_in, int ld_out, long long sIn, long long sOut)
{
    __shared__ h16 th[32][33];
    __shared__ h16 tl[32][33];
    inh += (long long)blockIdx.z * sIn;   inl += (long long)blockIdx.z * sIn;
    outh += (long long)blockIdx.z * sOut; outl += (long long)blockIdx.z * sOut;
    const int x0 = blockIdx.x * 32;
    const int y0 = blockIdx.y * 32;

#pragma unroll
    for (int i = threadIdx.y; i < 32; i += 8) {
        th[i][threadIdx.x] = inh[(size_t)(y0 + i) * ld_in + x0 + threadIdx.x];
        tl[i][threadIdx.x] = inl[(size_t)(y0 + i) * ld_in + x0 + threadIdx.x];
    }
    __syncthreads();
#pragma unroll
    for (int i = threadIdx.y; i < 32; i += 8) {
        outh[(size_t)(x0 + i) * ld_out + y0 + threadIdx.x] = th[threadIdx.x][i];
        outl[(size_t)(x0 + i) * ld_out + y0 + threadIdx.x] = tl[threadIdx.x][i];
    }
}

// ---------------------------------------------------------------------------
extern "C" void kernel_launch(void* const* d_in, const int* in_sizes, int n_in,
                              void* d_out, int out_size)
{
    const float* x      = (const float*)d_in[0];   // [B,S,E]
    const float* w_qkv  = (const float*)d_in[1];   // [3H,E]
    const float* w_proj = (const float*)d_in[2];   // [E,H]
    const float* b_proj = (const float*)d_in[3];   // [E]
    float* y = (float*)d_out;                      // [B,S,E]

    h16 *xh, *xl, *wqh, *wql, *wph, *wpl, *qkvh, *qkvl;
    h16 *ph, *pl, *vTh, *vTl, *oh, *ol, *oTh, *oTl;
    float* scores;
    cudaGetSymbolAddress((void**)&xh, g_xh);     cudaGetSymbolAddress((void**)&xl, g_xl);
    cudaGetSymbolAddress((void**)&wqh, g_wqh);   cudaGetSymbolAddress((void**)&wql, g_wql);
    cudaGetSymbolAddress((void**)&wph, g_wph);   cudaGetSymbolAddress((void**)&wpl, g_wpl);
    cudaGetSymbolAddress((void**)&qkvh, g_qkvh); cudaGetSymbolAddress((void**)&qkvl, g_qkvl);
    cudaGetSymbolAddress((void**)&scores, g_scores);
    cudaGetSymbolAddress((void**)&ph, g_ph);     cudaGetSymbolAddress((void**)&pl, g_pl);
    cudaGetSymbolAddress((void**)&vTh, g_vTh);   cudaGetSymbolAddress((void**)&vTl, g_vTl);
    cudaGetSymbolAddress((void**)&oh, g_oh);     cudaGetSymbolAddress((void**)&ol, g_ol);
    cudaGetSymbolAddress((void**)&oTh, g_oTh);   cudaGetSymbolAddress((void**)&oTl, g_oTl);

    const int shm = 4 * 49152;   // 192KB
    cudaFuncSetAttribute(tc_gemm<0>, cudaFuncAttributeMaxDynamicSharedMemorySize, shm);
    cudaFuncSetAttribute(tc_gemm<1>, cudaFuncAttributeMaxDynamicSharedMemorySize, shm);
    cudaFuncSetAttribute(tc_gemm<2>, cudaFuncAttributeMaxDynamicSharedMemorySize, shm);

    const long long sQKV = (long long)SEQ * QKV3;
    const long long sSS  = (long long)SEQ * SEQ;
    const long long sSH  = (long long)SEQ * HSZ;
    const long long sHS  = (long long)HSZ * SEQ;

    // 0. split inputs into fp16 (hi, lo)
    split_kernel<<<1024, 256>>>(x,      xh,  xl,  (long long)BS * EMBED);
    split_kernel<<<512,  256>>>(w_qkv,  wqh, wql, (long long)QKV3 * EMBED);
    split_kernel<<<256,  256>>>(w_proj, wph, wpl, (long long)EMBED * HSZ);

    // 1. qkv = x @ w_qkv^T   [8192 x 3072 x 1024], split output. 3072 CTAs.
    tc_gemm<2><<<dim3(QKV3 / 128, BS / 64, 1), 256, shm>>>(
        xh, xl, wqh, wql, nullptr, qkvh, qkvl, nullptr,
        EMBED, EMBED, EMBED, QKV3, 0, 0, 0, 1.0f);

    // 2. scores = 0.125 * q @ k^T   4x [2048 x 2048 x 1024]. 2048 CTAs.
    tc_gemm<0><<<dim3(SEQ / 128, SEQ / 64, BATCH), 256, shm>>>(
        qkvh, qkvl, qkvh + HSZ, qkvl + HSZ, scores, nullptr, nullptr, nullptr,
        HSZ, QKV3, QKV3, SEQ, sQKV, sQKV, sSS, 0.125f);

    // 3. softmax -> split probs
    softmax_kernel<<<BATCH * SEQ, 256>>>(scores, ph, pl);

    // 4. vT = v^T per batch (v strided inside qkv split arrays)
    transpose_pair<<<dim3(HSZ / 32, SEQ / 32, BATCH), dim3(32, 8)>>>(
        qkvh + 2 * HSZ, qkvl + 2 * HSZ, vTh, vTl, QKV3, SEQ, sQKV, sHS);

    // 5. out = probs @ vT^T   4x [2048 x 1024 x 2048], split output. 1024 CTAs.
    tc_gemm<2><<<dim3(HSZ / 128, SEQ / 64, BATCH), 256, shm>>>(
        ph, pl, vTh, vTl, nullptr, oh, ol, nullptr,
        SEQ, SEQ, SEQ, HSZ, sSS, sHS, sSH, 1.0f);

    // 6. scrambling reshape == per-batch transpose (flat re-view)
    transpose_pair<<<dim3(HSZ / 32, SEQ / 32, BATCH), dim3(32, 8)>>>(
        oh, ol, oTh, oTl, HSZ, SEQ, sSH, sHS);

    // 7. y = out2 @ w_proj^T + b   [8192 x 1024 x 1024], fp32 + bias. 1024 CTAs.
    tc_gemm<1><<<dim3(EMBED / 128, BS / 64, 1), 256, shm>>>(
        oTh, oTl, wph, wpl, y, nullptr, nullptr, b_proj,
        HSZ, HSZ, HSZ, EMBED, 0, 0, 0, 1.0f);
}

// round 11
// speedup vs baseline: 1.2212x; 1.1035x over previous
#include <cuda_runtime.h>
#include <cuda_fp16.h>
#include <math.h>
#include <stdint.h>

// Problem constants
#define BATCH 4
#define SEQ   2048
#define EMBED 1024
#define HSZ   1024
#define QKV3  3072
#define BS    (BATCH*SEQ)

typedef __half h16;

// Scratch (device globals -- no allocation allowed)
__device__ h16   g_xh[(size_t)BS * EMBED];
__device__ h16   g_xl[(size_t)BS * EMBED];
__device__ h16   g_wqh[(size_t)QKV3 * EMBED];
__device__ h16   g_wql[(size_t)QKV3 * EMBED];
__device__ h16   g_wph[(size_t)EMBED * HSZ];
__device__ h16   g_wpl[(size_t)EMBED * HSZ];
__device__ h16   g_qkvh[(size_t)BS * QKV3];
__device__ h16   g_qkvl[(size_t)BS * QKV3];
__device__ float g_scores[(size_t)BATCH * SEQ * SEQ];
__device__ h16   g_ph[(size_t)BATCH * SEQ * SEQ];
__device__ h16   g_pl[(size_t)BATCH * SEQ * SEQ];
__device__ h16   g_vTh[(size_t)BATCH * HSZ * SEQ];
__device__ h16   g_oh[(size_t)BATCH * SEQ * HSZ];
__device__ h16   g_ol[(size_t)BATCH * SEQ * HSZ];
__device__ h16   g_oTh[(size_t)BATCH * HSZ * SEQ];
__device__ h16   g_oTl[(size_t)BATCH * HSZ * SEQ];

// ---------------------------------------------------------------------------
__device__ __forceinline__ uint32_t smem_u32(const void* p) {
    uint32_t a;
    asm("{ .reg .u64 t; cvta.to.shared.u64 t, %1; cvt.u32.u64 %0, t; }"
        : "=r"(a) : "l"(p));
    return a;
}
__device__ __forceinline__ void cp16(uint32_t dst, const void* src) {
    asm volatile("cp.async.cg.shared.global [%0], [%1], 16;"
                 :: "r"(dst), "l"(src));
}
__device__ __forceinline__ void ldsm4(uint32_t* r, uint32_t addr) {
    asm volatile("ldmatrix.sync.aligned.m8n8.x4.shared.b16 {%0,%1,%2,%3}, [%4];"
                 : "=r"(r[0]), "=r"(r[1]), "=r"(r[2]), "=r"(r[3]) : "r"(addr));
}
// fp16 inputs, fp32 accumulators (main term)
__device__ __forceinline__ void mma_f32(float* c, const uint32_t* a,
                                        const uint32_t* b) {
    asm volatile(
        "mma.sync.aligned.m16n8k16.row.col.f32.f16.f16.f32 "
        "{%0,%1,%2,%3}, {%4,%5,%6,%7}, {%8,%9}, {%0,%1,%2,%3};"
        : "+f"(c[0]), "+f"(c[1]), "+f"(c[2]), "+f"(c[3])
        : "r"(a[0]), "r"(a[1]), "r"(a[2]), "r"(a[3]), "r"(b[0]), "r"(b[1]));
}
// fp16 inputs, fp16 accumulators (cross terms, ~2^-11 of result magnitude)
__device__ __forceinline__ void mma_f16(uint32_t* d, const uint32_t* a,
                                        const uint32_t* b) {
    asm volatile(
        "mma.sync.aligned.m16n8k16.row.col.f16.f16.f16.f16 "
        "{%0,%1}, {%2,%3,%4,%5}, {%6,%7}, {%0,%1};"
        : "+r"(d[0]), "+r"(d[1])
        : "r"(a[0]), "r"(a[1]), "r"(a[2]), "r"(a[3]), "r"(b[0]), "r"(b[1]));
}

// ---------------------------------------------------------------------------
// fp16 multi-limb NT GEMM.
// NL=2: C = alpha*(Ah+Al)*(Bh+Bl)^T, 3 MMAs/product (ah*bh f32; crosses f16).
// NL=1: C = alpha*(Ah+Al)*Bh^T, 2 MMAs/product (ah*bh f32; al*bh f16).
//       B single-rounded fp16 -> adds ~2.8e-4 RMS relative error.
// BM=64, BN=128, BK=64. 256 threads = 8 warps (2m x 4n); warp tile 32x32.
// 4-stage cp.async pipeline, ONE __syncthreads per K-iter, frag double-buffer.
// MODE 0: fp32 out; 1: fp32+bias; 2: split fp16 out (Ch,Cl)
// ---------------------------------------------------------------------------
template <int MODE, int NL>
__global__ __launch_bounds__(256, 1) void tc_gemm(
    const h16* __restrict__ Ah, const h16* __restrict__ Al,
    const h16* __restrict__ Bh, const h16* __restrict__ Bl,
    float* __restrict__ C, h16* __restrict__ Ch, h16* __restrict__ Cl,
    const float* __restrict__ bias,
    int K, int lda, int ldb, int ldc,
    long long sA, long long sB, long long sC, float alpha)
{
    constexpr uint32_t A_LIMB = 8192u;        // 64 rows x 128B
    constexpr uint32_t B_OFF  = 16384u;
    constexpr uint32_t B_LIMB = 16384u;       // 128 rows x 128B
    constexpr uint32_t STAGE  = B_OFF + (uint32_t)NL * B_LIMB;  // 32KB or 48KB

    extern __shared__ char dsm[];
    const uint32_t base = smem_u32(dsm);

    const int tid = threadIdx.x;
    const int wid = tid >> 5, lane = tid & 31;
    const int wm = wid >> 2, wn = wid & 3;     // 2 x 4 warps
    const int gid = lane >> 2, tig = lane & 3;

    Ah += (long long)blockIdx.z * sA;  Al += (long long)blockIdx.z * sA;
    Bh += (long long)blockIdx.z * sB;
    if (NL == 2) Bl += (long long)blockIdx.z * sB;
    const long long co = (long long)blockIdx.z * sC;
    const int m0 = blockIdx.y * 64;
    const int n0 = blockIdx.x * 128;

    // ldmatrix per-lane row/chunk decode
    const int rAl = lane & 15,                       cA16 = (lane >> 4) << 4;
    const int rBl = (lane & 7) | ((lane >> 4) << 3), cB16 = ((lane >> 3) & 1) << 4;

    uint32_t rbA[2], swA[2], rbB[2], swB[2];
#pragma unroll
    for (int mt = 0; mt < 2; mt++) {
        int row = wm * 32 + mt * 16 + rAl;
        rbA[mt] = (uint32_t)row << 7;
        swA[mt] = (uint32_t)(row & 7) << 4;
    }
#pragma unroll
    for (int np = 0; np < 2; np++) {
        int row = wn * 32 + np * 16 + rBl;
        rbB[np] = (uint32_t)row << 7;
        swB[np] = (uint32_t)(row & 7) << 4;
    }

    float c[2][4][4];
    uint32_t cf[2][4][2];                      // f16x2 cross accumulators
#pragma unroll
    for (int mt = 0; mt < 2; mt++)
#pragma unroll
        for (int nt = 0; nt < 4; nt++) {
#pragma unroll
            for (int i = 0; i < 4; i++) c[mt][nt][i] = 0.f;
            cf[mt][nt][0] = 0u; cf[mt][nt][1] = 0u;
        }

    const int NIT = K >> 6;   // BK = 64

    auto load_stage = [&](int it, int s) {
        const uint32_t st = base + (uint32_t)s * STAGE;
        const int c0 = it << 6;
#pragma unroll
        for (int i = 0; i < 2; i++) {              // A: 64 rows x 8 cp16
            int idx = tid + i * 256;
            int r = idx >> 3, ch = idx & 7;
            uint32_t off = ((uint32_t)r << 7) + (((uint32_t)ch << 4) ^ ((uint32_t)(r & 7) << 4));
            cp16(st + off,          Ah + (size_t)(m0 + r) * lda + c0 + ch * 8);
            cp16(st + A_LIMB + off, Al + (size_t)(m0 + r) * lda + c0 + ch * 8);
        }
#pragma unroll
        for (int i = 0; i < 4; i++) {              // B: 128 rows x 8 cp16
            int idx = tid + i * 256;
            int r = idx >> 3, ch = idx & 7;
            uint32_t off = ((uint32_t)r << 7) + (((uint32_t)ch << 4) ^ ((uint32_t)(r & 7) << 4));
            cp16(st + B_OFF + off, Bh + (size_t)(n0 + r) * ldb + c0 + ch * 8);
            if (NL == 2)
                cp16(st + B_OFF + B_LIMB + off, Bl + (size_t)(n0 + r) * ldb + c0 + ch * 8);
        }
        asm volatile("cp.async.commit_group;" ::: "memory");
    };

    load_stage(0, 0);
    load_stage(1, 1);
    load_stage(2, 2);

    // Fragment double buffers
    uint32_t ah[2][2][4], al[2][2][4];   // [buf][mt][reg]
    uint32_t bh[2][2][4], bl[2][2][4];   // [buf][np][reg]

    auto ld_frags = [&](uint32_t st, int ks, int buf) {
        const uint32_t kb = (uint32_t)ks << 5;
#pragma unroll
        for (int mt = 0; mt < 2; mt++) {
            uint32_t a = st + rbA[mt] + ((kb + cA16) ^ swA[mt]);
            ldsm4(ah[buf][mt], a);
            ldsm4(al[buf][mt], a + A_LIMB);
        }
#pragma unroll
        for (int np = 0; np < 2; np++) {
            uint32_t b = st + B_OFF + rbB[np] + ((kb + cB16) ^ swB[np]);
            ldsm4(bh[buf][np], b);
            if (NL == 2) ldsm4(bl[buf][np], b + B_LIMB);
        }
    };

    auto do_mmas = [&](int buf) {
#pragma unroll
        for (int np = 0; np < 2; np++)
#pragma unroll
            for (int mt = 0; mt < 2; mt++)
#pragma unroll
                for (int h = 0; h < 2; h++) {
                    float*    cc = c[mt][np * 2 + h];
                    uint32_t* xf = cf[mt][np * 2 + h];
                    mma_f32(cc, ah[buf][mt], bh[buf][np] + 2 * h);
                    if (NL == 2) mma_f16(xf, ah[buf][mt], bl[buf][np] + 2 * h);
                    mma_f16(xf, al[buf][mt], bh[buf][np] + 2 * h);
                }
    };

#pragma unroll 1
    for (int it = 0; it < NIT; it++) {
        asm volatile("cp.async.wait_group 2;" ::: "memory");
        __syncthreads();

        const uint32_t st = base + (uint32_t)(it & 3) * STAGE;
        ld_frags(st, 0, 0);
#pragma unroll
        for (int ks = 0; ks < 4; ks++) {
            if (ks < 3) {
                ld_frags(st, ks + 1, (ks + 1) & 1);   // prefetch next k-step
            } else {
                // overlap next-stage global loads with last k-step's MMAs;
                // slot (it+3)&3 == (it-1)&3 was fully consumed before this
                // iteration's __syncthreads -> safe to overwrite.
                if (it + 3 < NIT) load_stage(it + 3, (it + 3) & 3);
                else asm volatile("cp.async.commit_group;" ::: "memory");
            }
            do_mmas(ks & 1);
        }
    }

    // Epilogue: result = main(f32) + cross(f16x2 unpacked)
#pragma unroll
    for (int mt = 0; mt < 2; mt++) {
#pragma unroll
        for (int nt = 0; nt < 4; nt++) {
            int m = m0 + wm * 32 + mt * 16 + gid;
            int n = n0 + wn * 32 + nt * 8 + tig * 2;
            __half2 u0 = *reinterpret_cast<__half2*>(&cf[mt][nt][0]);
            __half2 u1 = *reinterpret_cast<__half2*>(&cf[mt][nt][1]);
            float v0 = alpha * (c[mt][nt][0] + __low2float(u0));
            float v1 = alpha * (c[mt][nt][1] + __high2float(u0));
            float v2 = alpha * (c[mt][nt][2] + __low2float(u1));
            float v3 = alpha * (c[mt][nt][3] + __high2float(u1));
            if (MODE == 1) {
                float b0 = bias[n], b1 = bias[n + 1];
                v0 += b0; v1 += b1; v2 += b0; v3 += b1;
            }
            if (MODE == 2) {
                h16 h0 = __float2half(v0);
                h16 h1 = __float2half(v1);
                h16 h2 = __float2half(v2);
                h16 h3 = __float2half(v3);
                h16 l0 = __float2half(v0 - __half2float(h0));
                h16 l1 = __float2half(v1 - __half2float(h1));
                h16 l2 = __float2half(v2 - __half2float(h2));
                h16 l3 = __float2half(v3 - __half2float(h3));
                __half2 hh0{h0, h1}, hh1{h2, h3};
                __half2 ll0{l0, l1}, ll1{l2, l3};
                *(__half2*)&Ch[co + (size_t)m * ldc + n]       = hh0;
                *(__half2*)&Ch[co + (size_t)(m + 8) * ldc + n] = hh1;
                *(__half2*)&Cl[co + (size_t)m * ldc + n]       = ll0;
                *(__half2*)&Cl[co + (size_t)(m + 8) * ldc + n] = ll1;
            } else {
                *(float2*)&C[co + (size_t)m * ldc + n]       = make_float2(v0, v1);
                *(float2*)&C[co + (size_t)(m + 8) * ldc + n] = make_float2(v2, v3);
            }
        }
    }
}

// ---------------------------------------------------------------------------
// Elementwise fp32 -> (hi, lo) fp16 split
// ---------------------------------------------------------------------------
__global__ __launch_bounds__(256) void split_kernel(
    const float* __restrict__ in, h16* __restrict__ oh, h16* __restrict__ ol,
    long long n)
{
    long long i = (long long)blockIdx.x * 256 + threadIdx.x;
    long long stride = (long long)gridDim.x * 256;
    for (; i < n; i += stride) {
        float v = in[i];
        h16 h = __float2half(v);
        oh[i] = h;
        ol[i] = __float2half(v - __half2float(h));
    }
}

// ---------------------------------------------------------------------------
// Row softmax: read fp32 scores, write split fp16 probs.
// ---------------------------------------------------------------------------
__global__ __launch_bounds__(256) void softmax_kernel(
    const float* __restrict__ scores, h16* __restrict__ ph, h16* __restrict__ pl)
{
    const float* row = scores + (size_t)blockIdx.x * SEQ;
    h16* rh = ph + (size_t)blockIdx.x * SEQ;
    h16* rl = pl + (size_t)blockIdx.x * SEQ;
    const int t = threadIdx.x;

    float v[8];
    float m = -INFINITY;
#pragma unroll
    for (int i = 0; i < 8; i++) {
        v[i] = row[t + i * 256];
        m = fmaxf(m, v[i]);
    }
#pragma unroll
    for (int o = 16; o > 0; o >>= 1)
        m = fmaxf(m, __shfl_xor_sync(0xffffffffu, m, o));

    __shared__ float redmax[8], redsum[8];
    if ((t & 31) == 0) redmax[t >> 5] = m;
    __syncthreads();
    float mm = redmax[0];
#pragma unroll
    for (int i = 1; i < 8; i++) mm = fmaxf(mm, redmax[i]);

    float s = 0.f;
#pragma unroll
    for (int i = 0; i < 8; i++) { v[i] = __expf(v[i] - mm); s += v[i]; }
#pragma unroll
    for (int o = 16; o > 0; o >>= 1)
        s += __shfl_xor_sync(0xffffffffu, s, o);
    if ((t & 31) == 0) redsum[t >> 5] = s;
    __syncthreads();
    float ss = 0.f;
#pragma unroll
    for (int i = 0; i < 8; i++) ss += redsum[i];
    float inv = 1.0f / ss;

#pragma unroll
    for (int i = 0; i < 8; i++) {
        float p = v[i] * inv;
        h16 h = __float2half(p);
        rh[t + i * 256] = h;
        rl[t + i * 256] = __float2half(p - __half2float(h));
    }
}

// ---------------------------------------------------------------------------
// Per-batch transpose of an fp16 (hi, lo) pair: out[c][r] = in[r][c]
// ---------------------------------------------------------------------------
__global__ __launch_bounds__(256) void transpose_pair(
    const h16* __restrict__ inh, const h16* __restrict__ inl,
    h16* __restrict__ outh, h16* __restrict__ outl,
    int ld_in, int ld_out, long long sIn, long long sOut)
{
    __shared__ h16 th[32][33];
    __shared__ h16 tl[32][33];
    inh += (long long)blockIdx.z * sIn;   inl += (long long)blockIdx.z * sIn;
    outh += (long long)blockIdx.z * sOut; outl += (long long)blockIdx.z * sOut;
    const int x0 = blockIdx.x * 32;
    const int y0 = blockIdx.y * 32;

#pragma unroll
    for (int i = threadIdx.y; i < 32; i += 8) {
        th[i][threadIdx.x] = inh[(size_t)(y0 + i) * ld_in + x0 + threadIdx.x];
        tl[i][threadIdx.x] = inl[(size_t)(y0 + i) * ld_in + x0 + threadIdx.x];
    }
    __syncthreads();
#pragma unroll
    for (int i = threadIdx.y; i < 32; i += 8) {
        outh[(size_t)(x0 + i) * ld_out + y0 + threadIdx.x] = th[threadIdx.x][i];
        outl[(size_t)(x0 + i) * ld_out + y0 + threadIdx.x] = tl[threadIdx.x][i];
    }
}

// ---------------------------------------------------------------------------
// Per-batch transpose of a single fp16 array: out[c][r] = in[r][c]
// ---------------------------------------------------------------------------
__global__ __launch_bounds__(256) void transpose_one(
    const h16* __restrict__ in, h16* __restrict__ out,
    int ld_in, int ld_out, long long sIn, long long sOut)
{
    __shared__ h16 t[32][33];
    in  += (long long)blockIdx.z * sIn;
    out += (long long)blockIdx.z * sOut;
    const int x0 = blockIdx.x * 32;
    const int y0 = blockIdx.y * 32;

#pragma unroll
    for (int i = threadIdx.y; i < 32; i += 8)
        t[i][threadIdx.x] = in[(size_t)(y0 + i) * ld_in + x0 + threadIdx.x];
    __syncthreads();
#pragma unroll
    for (int i = threadIdx.y; i < 32; i += 8)
        out[(size_t)(x0 + i) * ld_out + y0 + threadIdx.x] = t[threadIdx.x][i];
}

// ---------------------------------------------------------------------------
extern "C" void kernel_launch(void* const* d_in, const int* in_sizes, int n_in,
                              void* d_out, int out_size)
{
    const float* x      = (const float*)d_in[0];   // [B,S,E]
    const float* w_qkv  = (const float*)d_in[1];   // [3H,E]
    const float* w_proj = (const float*)d_in[2];   // [E,H]
    const float* b_proj = (const float*)d_in[3];   // [E]
    float* y = (float*)d_out;                      // [B,S,E]

    h16 *xh, *xl, *wqh, *wql, *wph, *wpl, *qkvh, *qkvl;
    h16 *ph, *pl, *vTh, *oh, *ol, *oTh, *oTl;
    float* scores;
    cudaGetSymbolAddress((void**)&xh, g_xh);     cudaGetSymbolAddress((void**)&xl, g_xl);
    cudaGetSymbolAddress((void**)&wqh, g_wqh);   cudaGetSymbolAddress((void**)&wql, g_wql);
    cudaGetSymbolAddress((void**)&wph, g_wph);   cudaGetSymbolAddress((void**)&wpl, g_wpl);
    cudaGetSymbolAddress((void**)&qkvh, g_qkvh); cudaGetSymbolAddress((void**)&qkvl, g_qkvl);
    cudaGetSymbolAddress((void**)&scores, g_scores);
    cudaGetSymbolAddress((void**)&ph, g_ph);     cudaGetSymbolAddress((void**)&pl, g_pl);
    cudaGetSymbolAddress((void**)&vTh, g_vTh);
    cudaGetSymbolAddress((void**)&oh, g_oh);     cudaGetSymbolAddress((void**)&ol, g_ol);
    cudaGetSymbolAddress((void**)&oTh, g_oTh);   cudaGetSymbolAddress((void**)&oTl, g_oTl);

    const int shm2 = 4 * 49152;   // NL=2: 192KB
    const int shm1 = 4 * 32768;   // NL=1: 128KB
    cudaFuncSetAttribute(tc_gemm<2,2>, cudaFuncAttributeMaxDynamicSharedMemorySize, shm2);
    cudaFuncSetAttribute(tc_gemm<0,2>, cudaFuncAttributeMaxDynamicSharedMemorySize, shm2);
    cudaFuncSetAttribute(tc_gemm<2,1>, cudaFuncAttributeMaxDynamicSharedMemorySize, shm1);
    cudaFuncSetAttribute(tc_gemm<1,1>, cudaFuncAttributeMaxDynamicSharedMemorySize, shm1);

    const long long sQKV = (long long)SEQ * QKV3;
    const long long sSS  = (long long)SEQ * SEQ;
    const long long sSH  = (long long)SEQ * HSZ;
    const long long sHS  = (long long)HSZ * SEQ;

    // 0. split inputs into fp16 (hi, lo)
    split_kernel<<<1024, 256>>>(x,      xh,  xl,  (long long)BS * EMBED);
    split_kernel<<<512,  256>>>(w_qkv,  wqh, wql, (long long)QKV3 * EMBED);
    split_kernel<<<256,  256>>>(w_proj, wph, wpl, (long long)EMBED * HSZ);

    // 1. qkv = x @ w_qkv^T   [8192 x 3072 x 1024], 3-MMA, split out. 3072 CTAs.
    tc_gemm<2,2><<<dim3(QKV3 / 128, BS / 64, 1), 256, shm2>>>(
        xh, xl, wqh, wql, nullptr, qkvh, qkvl, nullptr,
        EMBED, EMBED, EMBED, QKV3, 0, 0, 0, 1.0f);

    // 2. scores = 0.125 * q @ k^T   4x [2048 x 2048 x 1024], 3-MMA. 2048 CTAs.
    tc_gemm<0,2><<<dim3(SEQ / 128, SEQ / 64, BATCH), 256, shm2>>>(
        qkvh, qkvl, qkvh + HSZ, qkvl + HSZ, scores, nullptr, nullptr, nullptr,
        HSZ, QKV3, QKV3, SEQ, sQKV, sQKV, sSS, 0.125f);

    // 3. softmax -> split probs
    softmax_kernel<<<BATCH * SEQ, 256>>>(scores, ph, pl);

    // 4. vT = v^T per batch (hi limb only; B operand of PV is single-rounded)
    transpose_one<<<dim3(HSZ / 32, SEQ / 32, BATCH), dim3(32, 8)>>>(
        qkvh + 2 * HSZ, vTh, QKV3, SEQ, sQKV, sHS);

    // 5. out = probs @ vT^T   4x [2048 x 1024 x 2048], 2-MMA, split out. 1024 CTAs.
    tc_gemm<2,1><<<dim3(HSZ / 128, SEQ / 64, BATCH), 256, shm1>>>(
        ph, pl, vTh, nullptr, nullptr, oh, ol, nullptr,
        SEQ, SEQ, SEQ, HSZ, sSS, sHS, sSH, 1.0f);

    // 6. scrambling reshape == per-batch transpose (flat re-view)
    transpose_pair<<<dim3(HSZ / 32, SEQ / 32, BATCH), dim3(32, 8)>>>(
        oh, ol, oTh, oTl, HSZ, SEQ, sSH, sHS);

    // 7. y = out2 @ w_proj^T + b   [8192 x 1024 x 1024], 2-MMA, fp32+bias. 1024 CTAs.
    tc_gemm<1,1><<<dim3(EMBED / 128, BS / 64, 1), 256, shm1>>>(
        oTh, oTl, wph, nullptr, y, nullptr, nullptr, b_proj,
        HSZ, HSZ, HSZ, EMBED, 0, 0, 0, 1.0f);
}

// round 12
// speedup vs baseline: 1.4081x; 1.1530x over previous
#include <cuda_runtime.h>
#include <cuda_fp16.h>
#include <math.h>
#include <stdint.h>

// Problem constants
#define BATCH 4
#define SEQ   2048
#define EMBED 1024
#define HSZ   1024
#define QKV3  3072
#define BS    (BATCH*SEQ)

typedef __half h16;

// Scratch (device globals -- no allocation allowed)
__device__ h16   g_xh[(size_t)BS * EMBED];
__device__ h16   g_xl[(size_t)BS * EMBED];
__device__ h16   g_wqh[(size_t)QKV3 * EMBED];
__device__ h16   g_wql[(size_t)QKV3 * EMBED];
__device__ h16   g_wph[(size_t)EMBED * HSZ];
__device__ h16   g_qkvh[(size_t)BS * QKV3];
__device__ h16   g_qkvl[(size_t)BS * QKV3];
__device__ float g_scores[(size_t)BATCH * SEQ * SEQ];
__device__ h16   g_ph[(size_t)BATCH * SEQ * SEQ];
__device__ h16   g_vTh[(size_t)BATCH * HSZ * SEQ];
__device__ h16   g_oh[(size_t)BATCH * SEQ * HSZ];
__device__ h16   g_oTh[(size_t)BATCH * HSZ * SEQ];

// ---------------------------------------------------------------------------
__device__ __forceinline__ uint32_t smem_u32(const void* p) {
    uint32_t a;
    asm("{ .reg .u64 t; cvta.to.shared.u64 t, %1; cvt.u32.u64 %0, t; }"
        : "=r"(a) : "l"(p));
    return a;
}
__device__ __forceinline__ void cp16(uint32_t dst, const void* src) {
    asm volatile("cp.async.cg.shared.global [%0], [%1], 16;"
                 :: "r"(dst), "l"(src));
}
__device__ __forceinline__ void ldsm4(uint32_t* r, uint32_t addr) {
    asm volatile("ldmatrix.sync.aligned.m8n8.x4.shared.b16 {%0,%1,%2,%3}, [%4];"
                 : "=r"(r[0]), "=r"(r[1]), "=r"(r[2]), "=r"(r[3]) : "r"(addr));
}
// fp16 inputs, fp32 accumulators (main term)
__device__ __forceinline__ void mma_f32(float* c, const uint32_t* a,
                                        const uint32_t* b) {
    asm volatile(
        "mma.sync.aligned.m16n8k16.row.col.f32.f16.f16.f32 "
        "{%0,%1,%2,%3}, {%4,%5,%6,%7}, {%8,%9}, {%0,%1,%2,%3};"
        : "+f"(c[0]), "+f"(c[1]), "+f"(c[2]), "+f"(c[3])
        : "r"(a[0]), "r"(a[1]), "r"(a[2]), "r"(a[3]), "r"(b[0]), "r"(b[1]));
}
// fp16 inputs, fp16 accumulators (cross terms, ~2^-11 of result magnitude)
__device__ __forceinline__ void mma_f16(uint32_t* d, const uint32_t* a,
                                        const uint32_t* b) {
    asm volatile(
        "mma.sync.aligned.m16n8k16.row.col.f16.f16.f16.f16 "
        "{%0,%1}, {%2,%3,%4,%5}, {%6,%7}, {%0,%1};"
        : "+r"(d[0]), "+r"(d[1])
        : "r"(a[0]), "r"(a[1]), "r"(a[2]), "r"(a[3]), "r"(b[0]), "r"(b[1]));
}

// ---------------------------------------------------------------------------
// fp16 multi-limb NT GEMM.
// NL=2: C = alpha*(Ah+Al)*(Bh+Bl)^T, 3 MMAs (ah*bh f32; crosses f16-acc).
// NL=1: C = alpha*(Ah+Al)*Bh^T,      2 MMAs (ah*bh f32; al*bh f16-acc).
// NL=0: C = alpha*Ah*Bh^T,           1 MMA  (pure fp16 in, f32 acc).
// BM=64, BN=128, BK=64. 256 threads = 8 warps (2m x 4n); warp tile 32x32.
// 4-stage cp.async pipeline, ONE __syncthreads per K-iter, frag double-buffer.
// MODE 0: fp32 out; 1: fp32+bias; 2: split fp16 out (Ch,Cl); 3: fp16 out (Ch)
// ---------------------------------------------------------------------------
template <int MODE, int NL>
__global__ __launch_bounds__(256, 1) void tc_gemm(
    const h16* __restrict__ Ah, const h16* __restrict__ Al,
    const h16* __restrict__ Bh, const h16* __restrict__ Bl,
    float* __restrict__ C, h16* __restrict__ Ch, h16* __restrict__ Cl,
    const float* __restrict__ bias,
    int K, int lda, int ldb, int ldc,
    long long sA, long long sB, long long sC, float alpha)
{
    constexpr int ALN = (NL >= 1) ? 2 : 1;            // A limbs
    constexpr int BLN = (NL == 2) ? 2 : 1;            // B limbs
    constexpr uint32_t A_LIMB = 8192u;                // 64 rows x 128B
    constexpr uint32_t B_OFF  = (uint32_t)ALN * A_LIMB;
    constexpr uint32_t B_LIMB = 16384u;               // 128 rows x 128B
    constexpr uint32_t STAGE  = B_OFF + (uint32_t)BLN * B_LIMB;

    extern __shared__ char dsm[];
    const uint32_t base = smem_u32(dsm);

    const int tid = threadIdx.x;
    const int wid = tid >> 5, lane = tid & 31;
    const int wm = wid >> 2, wn = wid & 3;     // 2 x 4 warps
    const int gid = lane >> 2, tig = lane & 3;

    Ah += (long long)blockIdx.z * sA;
    if (ALN == 2) Al += (long long)blockIdx.z * sA;
    Bh += (long long)blockIdx.z * sB;
    if (BLN == 2) Bl += (long long)blockIdx.z * sB;
    const long long co = (long long)blockIdx.z * sC;
    const int m0 = blockIdx.y * 64;
    const int n0 = blockIdx.x * 128;

    // ldmatrix per-lane row/chunk decode
    const int rAl = lane & 15,                       cA16 = (lane >> 4) << 4;
    const int rBl = (lane & 7) | ((lane >> 4) << 3), cB16 = ((lane >> 3) & 1) << 4;

    uint32_t rbA[2], swA[2], rbB[2], swB[2];
#pragma unroll
    for (int mt = 0; mt < 2; mt++) {
        int row = wm * 32 + mt * 16 + rAl;
        rbA[mt] = (uint32_t)row << 7;
        swA[mt] = (uint32_t)(row & 7) << 4;
    }
#pragma unroll
    for (int np = 0; np < 2; np++) {
        int row = wn * 32 + np * 16 + rBl;
        rbB[np] = (uint32_t)row << 7;
        swB[np] = (uint32_t)(row & 7) << 4;
    }

    float c[2][4][4];
    uint32_t cf[2][4][2];                      // f16x2 cross accumulators
#pragma unroll
    for (int mt = 0; mt < 2; mt++)
#pragma unroll
        for (int nt = 0; nt < 4; nt++) {
#pragma unroll
            for (int i = 0; i < 4; i++) c[mt][nt][i] = 0.f;
            cf[mt][nt][0] = 0u; cf[mt][nt][1] = 0u;
        }

    const int NIT = K >> 6;   // BK = 64

    auto load_stage = [&](int it, int s) {
        const uint32_t st = base + (uint32_t)s * STAGE;
        const int c0 = it << 6;
#pragma unroll
        for (int i = 0; i < 2; i++) {              // A: 64 rows x 8 cp16
            int idx = tid + i * 256;
            int r = idx >> 3, ch = idx & 7;
            uint32_t off = ((uint32_t)r << 7) + (((uint32_t)ch << 4) ^ ((uint32_t)(r & 7) << 4));
            cp16(st + off, Ah + (size_t)(m0 + r) * lda + c0 + ch * 8);
            if (ALN == 2)
                cp16(st + A_LIMB + off, Al + (size_t)(m0 + r) * lda + c0 + ch * 8);
        }
#pragma unroll
        for (int i = 0; i < 4; i++) {              // B: 128 rows x 8 cp16
            int idx = tid + i * 256;
            int r = idx >> 3, ch = idx & 7;
            uint32_t off = ((uint32_t)r << 7) + (((uint32_t)ch << 4) ^ ((uint32_t)(r & 7) << 4));
            cp16(st + B_OFF + off, Bh + (size_t)(n0 + r) * ldb + c0 + ch * 8);
            if (BLN == 2)
                cp16(st + B_OFF + B_LIMB + off, Bl + (size_t)(n0 + r) * ldb + c0 + ch * 8);
        }
        asm volatile("cp.async.commit_group;" ::: "memory");
    };

    load_stage(0, 0);
    load_stage(1, 1);
    load_stage(2, 2);

    // Fragment double buffers
    uint32_t ah[2][2][4], al[2][2][4];   // [buf][mt][reg]
    uint32_t bh[2][2][4], bl[2][2][4];   // [buf][np][reg]

    auto ld_frags = [&](uint32_t st, int ks, int buf) {
        const uint32_t kb = (uint32_t)ks << 5;
#pragma unroll
        for (int mt = 0; mt < 2; mt++) {
            uint32_t a = st + rbA[mt] + ((kb + cA16) ^ swA[mt]);
            ldsm4(ah[buf][mt], a);
            if (ALN == 2) ldsm4(al[buf][mt], a + A_LIMB);
        }
#pragma unroll
        for (int np = 0; np < 2; np++) {
            uint32_t b = st + B_OFF + rbB[np] + ((kb + cB16) ^ swB[np]);
            ldsm4(bh[buf][np], b);
            if (BLN == 2) ldsm4(bl[buf][np], b + B_LIMB);
        }
    };

    auto do_mmas = [&](int buf) {
#pragma unroll
        for (int np = 0; np < 2; np++)
#pragma unroll
            for (int mt = 0; mt < 2; mt++)
#pragma unroll
                for (int h = 0; h < 2; h++) {
                    float*    cc = c[mt][np * 2 + h];
                    uint32_t* xf = cf[mt][np * 2 + h];
                    mma_f32(cc, ah[buf][mt], bh[buf][np] + 2 * h);
                    if (NL == 2) mma_f16(xf, ah[buf][mt], bl[buf][np] + 2 * h);
                    if (NL >= 1) mma_f16(xf, al[buf][mt], bh[buf][np] + 2 * h);
                }
    };

#pragma unroll 1
    for (int it = 0; it < NIT; it++) {
        asm volatile("cp.async.wait_group 2;" ::: "memory");
        __syncthreads();

        const uint32_t st = base + (uint32_t)(it & 3) * STAGE;
        ld_frags(st, 0, 0);
#pragma unroll
        for (int ks = 0; ks < 4; ks++) {
            if (ks < 3) {
                ld_frags(st, ks + 1, (ks + 1) & 1);   // prefetch next k-step
            } else {
                // overlap next-stage global loads with last k-step's MMAs;
                // slot (it+3)&3 == (it-1)&3 was fully consumed before this
                // iteration's __syncthreads -> safe to overwrite.
                if (it + 3 < NIT) load_stage(it + 3, (it + 3) & 3);
                else asm volatile("cp.async.commit_group;" ::: "memory");
            }
            do_mmas(ks & 1);
        }
    }

    // Epilogue: result = main(f32) + cross(f16x2 unpacked, if any)
#pragma unroll
    for (int mt = 0; mt < 2; mt++) {
#pragma unroll
        for (int nt = 0; nt < 4; nt++) {
            int m = m0 + wm * 32 + mt * 16 + gid;
            int n = n0 + wn * 32 + nt * 8 + tig * 2;
            float v0, v1, v2, v3;
            if (NL >= 1) {
                __half2 u0 = *reinterpret_cast<__half2*>(&cf[mt][nt][0]);
                __half2 u1 = *reinterpret_cast<__half2*>(&cf[mt][nt][1]);
                v0 = alpha * (c[mt][nt][0] + __low2float(u0));
                v1 = alpha * (c[mt][nt][1] + __high2float(u0));
                v2 = alpha * (c[mt][nt][2] + __low2float(u1));
                v3 = alpha * (c[mt][nt][3] + __high2float(u1));
            } else {
                v0 = alpha * c[mt][nt][0];
                v1 = alpha * c[mt][nt][1];
                v2 = alpha * c[mt][nt][2];
                v3 = alpha * c[mt][nt][3];
            }
            if (MODE == 1) {
                float b0 = bias[n], b1 = bias[n + 1];
                v0 += b0; v1 += b1; v2 += b0; v3 += b1;
            }
            if (MODE == 2 || MODE == 3) {
                h16 h0 = __float2half(v0);
                h16 h1 = __float2half(v1);
                h16 h2 = __float2half(v2);
                h16 h3 = __float2half(v3);
                __half2 hh0{h0, h1}, hh1{h2, h3};
                *(__half2*)&Ch[co + (size_t)m * ldc + n]       = hh0;
                *(__half2*)&Ch[co + (size_t)(m + 8) * ldc + n] = hh1;
                if (MODE == 2) {
                    h16 l0 = __float2half(v0 - __half2float(h0));
                    h16 l1 = __float2half(v1 - __half2float(h1));
                    h16 l2 = __float2half(v2 - __half2float(h2));
                    h16 l3 = __float2half(v3 - __half2float(h3));
                    __half2 ll0{l0, l1}, ll1{l2, l3};
                    *(__half2*)&Cl[co + (size_t)m * ldc + n]       = ll0;
                    *(__half2*)&Cl[co + (size_t)(m + 8) * ldc + n] = ll1;
                }
            } else {
                *(float2*)&C[co + (size_t)m * ldc + n]       = make_float2(v0, v1);
                *(float2*)&C[co + (size_t)(m + 8) * ldc + n] = make_float2(v2, v3);
            }
        }
    }
}

// ---------------------------------------------------------------------------
// Elementwise fp32 -> (hi, lo) fp16 split
// ---------------------------------------------------------------------------
__global__ __launch_bounds__(256) void split_kernel(
    const float* __restrict__ in, h16* __restrict__ oh, h16* __restrict__ ol,
    long long n)
{
    long long i = (long long)blockIdx.x * 256 + threadIdx.x;
    long long stride = (long long)gridDim.x * 256;
    for (; i < n; i += stride) {
        float v = in[i];
        h16 h = __float2half(v);
        oh[i] = h;
        ol[i] = __float2half(v - __half2float(h));
    }
}

// ---------------------------------------------------------------------------
// Elementwise fp32 -> fp16 round (hi only)
// ---------------------------------------------------------------------------
__global__ __launch_bounds__(256) void round_kernel(
    const float* __restrict__ in, h16* __restrict__ oh, long long n)
{
    long long i = (long long)blockIdx.x * 256 + threadIdx.x;
    long long stride = (long long)gridDim.x * 256;
    for (; i < n; i += stride)
        oh[i] = __float2half(in[i]);
}

// ---------------------------------------------------------------------------
// Row softmax: read fp32 scores, write fp16 probs (single-rounded).
// ---------------------------------------------------------------------------
__global__ __launch_bounds__(256) void softmax_kernel(
    const float* __restrict__ scores, h16* __restrict__ ph)
{
    const float* row = scores + (size_t)blockIdx.x * SEQ;
    h16* rh = ph + (size_t)blockIdx.x * SEQ;
    const int t = threadIdx.x;

    float v[8];
    float m = -INFINITY;
#pragma unroll
    for (int i = 0; i < 8; i++) {
        v[i] = row[t + i * 256];
        m = fmaxf(m, v[i]);
    }
#pragma unroll
    for (int o = 16; o > 0; o >>= 1)
        m = fmaxf(m, __shfl_xor_sync(0xffffffffu, m, o));

    __shared__ float redmax[8], redsum[8];
    if ((t & 31) == 0) redmax[t >> 5] = m;
    __syncthreads();
    float mm = redmax[0];
#pragma unroll
    for (int i = 1; i < 8; i++) mm = fmaxf(mm, redmax[i]);

    float s = 0.f;
#pragma unroll
    for (int i = 0; i < 8; i++) { v[i] = __expf(v[i] - mm); s += v[i]; }
#pragma unroll
    for (int o = 16; o > 0; o >>= 1)
        s += __shfl_xor_sync(0xffffffffu, s, o);
    if ((t & 31) == 0) redsum[t >> 5] = s;
    __syncthreads();
    float ss = 0.f;
#pragma unroll
    for (int i = 0; i < 8; i++) ss += redsum[i];
    float inv = 1.0f / ss;

#pragma unroll
    for (int i = 0; i < 8; i++)
        rh[t + i * 256] = __float2half(v[i] * inv);
}

// ---------------------------------------------------------------------------
// Per-batch transpose of a single fp16 array: out[c][r] = in[r][c]
// ---------------------------------------------------------------------------
__global__ __launch_bounds__(256) void transpose_one(
    const h16* __restrict__ in, h16* __restrict__ out,
    int ld_in, int ld_out, long long sIn, long long sOut)
{
    __shared__ h16 t[32][33];
    in  += (long long)blockIdx.z * sIn;
    out += (long long)blockIdx.z * sOut;
    const int x0 = blockIdx.x * 32;
    const int y0 = blockIdx.y * 32;

#pragma unroll
    for (int i = threadIdx.y; i < 32; i += 8)
        t[i][threadIdx.x] = in[(size_t)(y0 + i) * ld_in + x0 + threadIdx.x];
    __syncthreads();
#pragma unroll
    for (int i = threadIdx.y; i < 32; i += 8)
        out[(size_t)(x0 + i) * ld_out + y0 + threadIdx.x] = t[threadIdx.x][i];
}

// ---------------------------------------------------------------------------
extern "C" void kernel_launch(void* const* d_in, const int* in_sizes, int n_in,
                              void* d_out, int out_size)
{
    const float* x      = (const float*)d_in[0];   // [B,S,E]
    const float* w_qkv  = (const float*)d_in[1];   // [3H,E]
    const float* w_proj = (const float*)d_in[2];   // [E,H]
    const float* b_proj = (const float*)d_in[3];   // [E]
    float* y = (float*)d_out;                      // [B,S,E]

    h16 *xh, *xl, *wqh, *wql, *wph, *qkvh, *qkvl;
    h16 *ph, *vTh, *oh, *oTh;
    float* scores;
    cudaGetSymbolAddress((void**)&xh, g_xh);     cudaGetSymbolAddress((void**)&xl, g_xl);
    cudaGetSymbolAddress((void**)&wqh, g_wqh);   cudaGetSymbolAddress((void**)&wql, g_wql);
    cudaGetSymbolAddress((void**)&wph, g_wph);
    cudaGetSymbolAddress((void**)&qkvh, g_qkvh); cudaGetSymbolAddress((void**)&qkvl, g_qkvl);
    cudaGetSymbolAddress((void**)&scores, g_scores);
    cudaGetSymbolAddress((void**)&ph, g_ph);
    cudaGetSymbolAddress((void**)&vTh, g_vTh);
    cudaGetSymbolAddress((void**)&oh, g_oh);
    cudaGetSymbolAddress((void**)&oTh, g_oTh);

    const int shm2 = 4 * 49152;   // NL=2: 192KB
    const int shm0 = 4 * 24576;   // NL=0: 96KB
    cudaFuncSetAttribute(tc_gemm<2,2>, cudaFuncAttributeMaxDynamicSharedMemorySize, shm2);
    cudaFuncSetAttribute(tc_gemm<0,2>, cudaFuncAttributeMaxDynamicSharedMemorySize, shm2);
    cudaFuncSetAttribute(tc_gemm<3,0>, cudaFuncAttributeMaxDynamicSharedMemorySize, shm0);
    cudaFuncSetAttribute(tc_gemm<1,0>, cudaFuncAttributeMaxDynamicSharedMemorySize, shm0);

    const long long sQKV = (long long)SEQ * QKV3;
    const long long sSS  = (long long)SEQ * SEQ;
    const long long sSH  = (long long)SEQ * HSZ;
    const long long sHS  = (long long)HSZ * SEQ;

    // 0. split / round inputs to fp16
    split_kernel<<<1024, 256>>>(x,      xh,  xl,  (long long)BS * EMBED);
    split_kernel<<<512,  256>>>(w_qkv,  wqh, wql, (long long)QKV3 * EMBED);
    round_kernel<<<256,  256>>>(w_proj, wph,      (long long)EMBED * HSZ);

    // 1. qkv = x @ w_qkv^T   [8192 x 3072 x 1024], 3-MMA, split out. 3072 CTAs.
    tc_gemm<2,2><<<dim3(QKV3 / 128, BS / 64, 1), 256, shm2>>>(
        xh, xl, wqh, wql, nullptr, qkvh, qkvl, nullptr,
        EMBED, EMBED, EMBED, QKV3, 0, 0, 0, 1.0f);

    // 2. scores = 0.125 * q @ k^T   4x [2048 x 2048 x 1024], 3-MMA. 2048 CTAs.
    tc_gemm<0,2><<<dim3(SEQ / 128, SEQ / 64, BATCH), 256, shm2>>>(
        qkvh, qkvl, qkvh + HSZ, qkvl + HSZ, scores, nullptr, nullptr, nullptr,
        HSZ, QKV3, QKV3, SEQ, sQKV, sQKV, sSS, 0.125f);

    // 3. softmax -> fp16 probs (single-rounded)
    softmax_kernel<<<BATCH * SEQ, 256>>>(scores, ph);

    // 4. vT = v^T per batch (hi limb only)
    transpose_one<<<dim3(HSZ / 32, SEQ / 32, BATCH), dim3(32, 8)>>>(
        qkvh + 2 * HSZ, vTh, QKV3, SEQ, sQKV, sHS);

    // 5. out = probs @ vT^T   4x [2048 x 1024 x 2048], 1-MMA pure fp16. 1024 CTAs.
    tc_gemm<3,0><<<dim3(HSZ / 128, SEQ / 64, BATCH), 256, shm0>>>(
        ph, nullptr, vTh, nullptr, nullptr, oh, nullptr, nullptr,
        SEQ, SEQ, SEQ, HSZ, sSS, sHS, sSH, 1.0f);

    // 6. scrambling reshape == per-batch transpose (flat re-view)
    transpose_one<<<dim3(HSZ / 32, SEQ / 32, BATCH), dim3(32, 8)>>>(
        oh, oTh, HSZ, SEQ, sSH, sHS);

    // 7. y = out2 @ w_proj^T + b   [8192 x 1024 x 1024], 1-MMA, fp32+bias. 1024 CTAs.
    tc_gemm<1,0><<<dim3(EMBED / 128, BS / 64, 1), 256, shm0>>>(
        oTh, nullptr, wph, nullptr, y, nullptr, nullptr, b_proj,
        HSZ, HSZ, HSZ, EMBED, 0, 0, 0, 1.0f);
}

// round 13
// speedup vs baseline: 1.5180x; 1.0781x over previous
#include <cuda_runtime.h>
#include <cuda_fp16.h>
#include <math.h>
#include <stdint.h>

// Problem constants
#define BATCH 4
#define SEQ   2048
#define EMBED 1024
#define HSZ   1024
#define QKV3  3072
#define BS    (BATCH*SEQ)

typedef __half h16;

// Scratch (device globals -- no allocation allowed)
__device__ h16   g_xh[(size_t)BS * EMBED];
__device__ h16   g_xl[(size_t)BS * EMBED];
__device__ h16   g_wqh[(size_t)QKV3 * EMBED];
__device__ h16   g_wql[(size_t)QKV3 * EMBED];
__device__ h16   g_wph[(size_t)EMBED * HSZ];
__device__ h16   g_qkvh[(size_t)BS * QKV3];
__device__ h16   g_qkvl[(size_t)BS * QKV3];
__device__ float g_scores[(size_t)BATCH * SEQ * SEQ];
__device__ h16   g_ph[(size_t)BATCH * SEQ * SEQ];
__device__ h16   g_vTh[(size_t)BATCH * HSZ * SEQ];
__device__ h16   g_oh[(size_t)BATCH * SEQ * HSZ];
__device__ h16   g_oTh[(size_t)BATCH * HSZ * SEQ];

// ---------------------------------------------------------------------------
__device__ __forceinline__ uint32_t smem_u32(const void* p) {
    uint32_t a;
    asm("{ .reg .u64 t; cvta.to.shared.u64 t, %1; cvt.u32.u64 %0, t; }"
        : "=r"(a) : "l"(p));
    return a;
}
__device__ __forceinline__ void cp16(uint32_t dst, const void* src) {
    asm volatile("cp.async.cg.shared.global [%0], [%1], 16;"
                 :: "r"(dst), "l"(src));
}
__device__ __forceinline__ void ldsm4(uint32_t* r, uint32_t addr) {
    asm volatile("ldmatrix.sync.aligned.m8n8.x4.shared.b16 {%0,%1,%2,%3}, [%4];"
                 : "=r"(r[0]), "=r"(r[1]), "=r"(r[2]), "=r"(r[3]) : "r"(addr));
}
// fp16 inputs, fp32 accumulators (main term)
__device__ __forceinline__ void mma_f32(float* c, const uint32_t* a,
                                        const uint32_t* b) {
    asm volatile(
        "mma.sync.aligned.m16n8k16.row.col.f32.f16.f16.f32 "
        "{%0,%1,%2,%3}, {%4,%5,%6,%7}, {%8,%9}, {%0,%1,%2,%3};"
        : "+f"(c[0]), "+f"(c[1]), "+f"(c[2]), "+f"(c[3])
        : "r"(a[0]), "r"(a[1]), "r"(a[2]), "r"(a[3]), "r"(b[0]), "r"(b[1]));
}
// fp16 inputs, fp16 accumulators (cross terms, ~2^-11 of result magnitude)
__device__ __forceinline__ void mma_f16(uint32_t* d, const uint32_t* a,
                                        const uint32_t* b) {
    asm volatile(
        "mma.sync.aligned.m16n8k16.row.col.f16.f16.f16.f16 "
        "{%0,%1}, {%2,%3,%4,%5}, {%6,%7}, {%0,%1};"
        : "+r"(d[0]), "+r"(d[1])
        : "r"(a[0]), "r"(a[1]), "r"(a[2]), "r"(a[3]), "r"(b[0]), "r"(b[1]));
}

// ---------------------------------------------------------------------------
// fp16 multi-limb NT GEMM.
// NL=2: C = alpha*(Ah+Al)*(Bh+Bl)^T, 3 MMAs (ah*bh f32; crosses f16-acc).
// NL=1: C = alpha*(Ah+Al)*Bh^T,      2 MMAs (ah*bh f32; al*bh f16-acc).
// NL=0: C = alpha*Ah*Bh^T,           1 MMA  (pure fp16 in, f32 acc).
// BM=64, BN=128, BK=64. 256 threads = 8 warps (2m x 4n); warp tile 32x32.
// 4-stage cp.async pipeline, ONE __syncthreads per K-iter, frag double-buffer.
// MODE 0: fp32 out; 1: fp32+bias; 2: split fp16 out (Ch,Cl); 3: fp16 out (Ch)
// ---------------------------------------------------------------------------
template <int MODE, int NL>
__global__ __launch_bounds__(256, 1) void tc_gemm(
    const h16* __restrict__ Ah, const h16* __restrict__ Al,
    const h16* __restrict__ Bh, const h16* __restrict__ Bl,
    float* __restrict__ C, h16* __restrict__ Ch, h16* __restrict__ Cl,
    const float* __restrict__ bias,
    int K, int lda, int ldb, int ldc,
    long long sA, long long sB, long long sC, float alpha)
{
    constexpr int ALN = (NL >= 1) ? 2 : 1;            // A limbs
    constexpr int BLN = (NL == 2) ? 2 : 1;            // B limbs
    constexpr uint32_t A_LIMB = 8192u;                // 64 rows x 128B
    constexpr uint32_t B_OFF  = (uint32_t)ALN * A_LIMB;
    constexpr uint32_t B_LIMB = 16384u;               // 128 rows x 128B
    constexpr uint32_t STAGE  = B_OFF + (uint32_t)BLN * B_LIMB;

    extern __shared__ char dsm[];
    const uint32_t base = smem_u32(dsm);

    const int tid = threadIdx.x;
    const int wid = tid >> 5, lane = tid & 31;
    const int wm = wid >> 2, wn = wid & 3;     // 2 x 4 warps
    const int gid = lane >> 2, tig = lane & 3;

    Ah += (long long)blockIdx.z * sA;
    if (ALN == 2) Al += (long long)blockIdx.z * sA;
    Bh += (long long)blockIdx.z * sB;
    if (BLN == 2) Bl += (long long)blockIdx.z * sB;
    const long long co = (long long)blockIdx.z * sC;
    const int m0 = blockIdx.y * 64;
    const int n0 = blockIdx.x * 128;

    // ldmatrix per-lane row/chunk decode
    const int rAl = lane & 15,                       cA16 = (lane >> 4) << 4;
    const int rBl = (lane & 7) | ((lane >> 4) << 3), cB16 = ((lane >> 3) & 1) << 4;

    uint32_t rbA[2], swA[2], rbB[2], swB[2];
#pragma unroll
    for (int mt = 0; mt < 2; mt++) {
        int row = wm * 32 + mt * 16 + rAl;
        rbA[mt] = (uint32_t)row << 7;
        swA[mt] = (uint32_t)(row & 7) << 4;
    }
#pragma unroll
    for (int np = 0; np < 2; np++) {
        int row = wn * 32 + np * 16 + rBl;
        rbB[np] = (uint32_t)row << 7;
        swB[np] = (uint32_t)(row & 7) << 4;
    }

    float c[2][4][4];
    uint32_t cf[2][4][2];                      // f16x2 cross accumulators
#pragma unroll
    for (int mt = 0; mt < 2; mt++)
#pragma unroll
        for (int nt = 0; nt < 4; nt++) {
#pragma unroll
            for (int i = 0; i < 4; i++) c[mt][nt][i] = 0.f;
            cf[mt][nt][0] = 0u; cf[mt][nt][1] = 0u;
        }

    const int NIT = K >> 6;   // BK = 64

    auto load_stage = [&](int it, int s) {
        const uint32_t st = base + (uint32_t)s * STAGE;
        const int c0 = it << 6;
#pragma unroll
        for (int i = 0; i < 2; i++) {              // A: 64 rows x 8 cp16
            int idx = tid + i * 256;
            int r = idx >> 3, ch = idx & 7;
            uint32_t off = ((uint32_t)r << 7) + (((uint32_t)ch << 4) ^ ((uint32_t)(r & 7) << 4));
            cp16(st + off, Ah + (size_t)(m0 + r) * lda + c0 + ch * 8);
            if (ALN == 2)
                cp16(st + A_LIMB + off, Al + (size_t)(m0 + r) * lda + c0 + ch * 8);
        }
#pragma unroll
        for (int i = 0; i < 4; i++) {              // B: 128 rows x 8 cp16
            int idx = tid + i * 256;
            int r = idx >> 3, ch = idx & 7;
            uint32_t off = ((uint32_t)r << 7) + (((uint32_t)ch << 4) ^ ((uint32_t)(r & 7) << 4));
            cp16(st + B_OFF + off, Bh + (size_t)(n0 + r) * ldb + c0 + ch * 8);
            if (BLN == 2)
                cp16(st + B_OFF + B_LIMB + off, Bl + (size_t)(n0 + r) * ldb + c0 + ch * 8);
        }
        asm volatile("cp.async.commit_group;" ::: "memory");
    };

    load_stage(0, 0);
    load_stage(1, 1);
    load_stage(2, 2);

    // Fragment double buffers
    uint32_t ah[2][2][4], al[2][2][4];   // [buf][mt][reg]
    uint32_t bh[2][2][4], bl[2][2][4];   // [buf][np][reg]

    auto ld_frags = [&](uint32_t st, int ks, int buf) {
        const uint32_t kb = (uint32_t)ks << 5;
#pragma unroll
        for (int mt = 0; mt < 2; mt++) {
            uint32_t a = st + rbA[mt] + ((kb + cA16) ^ swA[mt]);
            ldsm4(ah[buf][mt], a);
            if (ALN == 2) ldsm4(al[buf][mt], a + A_LIMB);
        }
#pragma unroll
        for (int np = 0; np < 2; np++) {
            uint32_t b = st + B_OFF + rbB[np] + ((kb + cB16) ^ swB[np]);
            ldsm4(bh[buf][np], b);
            if (BLN == 2) ldsm4(bl[buf][np], b + B_LIMB);
        }
    };

    auto do_mmas = [&](int buf) {
#pragma unroll
        for (int np = 0; np < 2; np++)
#pragma unroll
            for (int mt = 0; mt < 2; mt++)
#pragma unroll
                for (int h = 0; h < 2; h++) {
                    float*    cc = c[mt][np * 2 + h];
                    uint32_t* xf = cf[mt][np * 2 + h];
                    mma_f32(cc, ah[buf][mt], bh[buf][np] + 2 * h);
                    if (NL == 2) mma_f16(xf, ah[buf][mt], bl[buf][np] + 2 * h);
                    if (NL >= 1) mma_f16(xf, al[buf][mt], bh[buf][np] + 2 * h);
                }
    };

#pragma unroll 1
    for (int it = 0; it < NIT; it++) {
        asm volatile("cp.async.wait_group 2;" ::: "memory");
        __syncthreads();

        const uint32_t st = base + (uint32_t)(it & 3) * STAGE;
        ld_frags(st, 0, 0);
#pragma unroll
        for (int ks = 0; ks < 4; ks++) {
            if (ks < 3) {
                ld_frags(st, ks + 1, (ks + 1) & 1);   // prefetch next k-step
            } else {
                // overlap next-stage global loads with last k-step's MMAs;
                // slot (it+3)&3 == (it-1)&3 was fully consumed before this
                // iteration's __syncthreads -> safe to overwrite.
                if (it + 3 < NIT) load_stage(it + 3, (it + 3) & 3);
                else asm volatile("cp.async.commit_group;" ::: "memory");
            }
            do_mmas(ks & 1);
        }
    }

    // Epilogue: result = main(f32) + cross(f16x2 unpacked, if any)
#pragma unroll
    for (int mt = 0; mt < 2; mt++) {
#pragma unroll
        for (int nt = 0; nt < 4; nt++) {
            int m = m0 + wm * 32 + mt * 16 + gid;
            int n = n0 + wn * 32 + nt * 8 + tig * 2;
            float v0, v1, v2, v3;
            if (NL >= 1) {
                __half2 u0 = *reinterpret_cast<__half2*>(&cf[mt][nt][0]);
                __half2 u1 = *reinterpret_cast<__half2*>(&cf[mt][nt][1]);
                v0 = alpha * (c[mt][nt][0] + __low2float(u0));
                v1 = alpha * (c[mt][nt][1] + __high2float(u0));
                v2 = alpha * (c[mt][nt][2] + __low2float(u1));
                v3 = alpha * (c[mt][nt][3] + __high2float(u1));
            } else {
                v0 = alpha * c[mt][nt][0];
                v1 = alpha * c[mt][nt][1];
                v2 = alpha * c[mt][nt][2];
                v3 = alpha * c[mt][nt][3];
            }
            if (MODE == 1) {
                float b0 = bias[n], b1 = bias[n + 1];
                v0 += b0; v1 += b1; v2 += b0; v3 += b1;
            }
            if (MODE == 2 || MODE == 3) {
                h16 h0 = __float2half(v0);
                h16 h1 = __float2half(v1);
                h16 h2 = __float2half(v2);
                h16 h3 = __float2half(v3);
                __half2 hh0{h0, h1}, hh1{h2, h3};
                *(__half2*)&Ch[co + (size_t)m * ldc + n]       = hh0;
                *(__half2*)&Ch[co + (size_t)(m + 8) * ldc + n] = hh1;
                if (MODE == 2) {
                    h16 l0 = __float2half(v0 - __half2float(h0));
                    h16 l1 = __float2half(v1 - __half2float(h1));
                    h16 l2 = __float2half(v2 - __half2float(h2));
                    h16 l3 = __float2half(v3 - __half2float(h3));
                    __half2 ll0{l0, l1}, ll1{l2, l3};
                    *(__half2*)&Cl[co + (size_t)m * ldc + n]       = ll0;
                    *(__half2*)&Cl[co + (size_t)(m + 8) * ldc + n] = ll1;
                }
            } else {
                *(float2*)&C[co + (size_t)m * ldc + n]       = make_float2(v0, v1);
                *(float2*)&C[co + (size_t)(m + 8) * ldc + n] = make_float2(v2, v3);
            }
        }
    }
}

// ---------------------------------------------------------------------------
// Elementwise fp32 -> (hi, lo) fp16 split
// ---------------------------------------------------------------------------
__global__ __launch_bounds__(256) void split_kernel(
    const float* __restrict__ in, h16* __restrict__ oh, h16* __restrict__ ol,
    long long n)
{
    long long i = (long long)blockIdx.x * 256 + threadIdx.x;
    long long stride = (long long)gridDim.x * 256;
    for (; i < n; i += stride) {
        float v = in[i];
        h16 h = __float2half(v);
        oh[i] = h;
        ol[i] = __float2half(v - __half2float(h));
    }
}

// ---------------------------------------------------------------------------
// Elementwise fp32 -> fp16 round (hi only)
// ---------------------------------------------------------------------------
__global__ __launch_bounds__(256) void round_kernel(
    const float* __restrict__ in, h16* __restrict__ oh, long long n)
{
    long long i = (long long)blockIdx.x * 256 + threadIdx.x;
    long long stride = (long long)gridDim.x * 256;
    for (; i < n; i += stride)
        oh[i] = __float2half(in[i]);
}

// ---------------------------------------------------------------------------
// Row softmax: read fp32 scores, write fp16 probs (single-rounded).
// ---------------------------------------------------------------------------
__global__ __launch_bounds__(256) void softmax_kernel(
    const float* __restrict__ scores, h16* __restrict__ ph)
{
    const float* row = scores + (size_t)blockIdx.x * SEQ;
    h16* rh = ph + (size_t)blockIdx.x * SEQ;
    const int t = threadIdx.x;

    float v[8];
    float m = -INFINITY;
#pragma unroll
    for (int i = 0; i < 8; i++) {
        v[i] = row[t + i * 256];
        m = fmaxf(m, v[i]);
    }
#pragma unroll
    for (int o = 16; o > 0; o >>= 1)
        m = fmaxf(m, __shfl_xor_sync(0xffffffffu, m, o));

    __shared__ float redmax[8], redsum[8];
    if ((t & 31) == 0) redmax[t >> 5] = m;
    __syncthreads();
    float mm = redmax[0];
#pragma unroll
    for (int i = 1; i < 8; i++) mm = fmaxf(mm, redmax[i]);

    float s = 0.f;
#pragma unroll
    for (int i = 0; i < 8; i++) { v[i] = __expf(v[i] - mm); s += v[i]; }
#pragma unroll
    for (int o = 16; o > 0; o >>= 1)
        s += __shfl_xor_sync(0xffffffffu, s, o);
    if ((t & 31) == 0) redsum[t >> 5] = s;
    __syncthreads();
    float ss = 0.f;
#pragma unroll
    for (int i = 0; i < 8; i++) ss += redsum[i];
    float inv = 1.0f / ss;

#pragma unroll
    for (int i = 0; i < 8; i++)
        rh[t + i * 256] = __float2half(v[i] * inv);
}

// ---------------------------------------------------------------------------
// Per-batch transpose of a single fp16 array: out[c][r] = in[r][c]
// ---------------------------------------------------------------------------
__global__ __launch_bounds__(256) void transpose_one(
    const h16* __restrict__ in, h16* __restrict__ out,
    int ld_in, int ld_out, long long sIn, long long sOut)
{
    __shared__ h16 t[32][33];
    in  += (long long)blockIdx.z * sIn;
    out += (long long)blockIdx.z * sOut;
    const int x0 = blockIdx.x * 32;
    const int y0 = blockIdx.y * 32;

#pragma unroll
    for (int i = threadIdx.y; i < 32; i += 8)
        t[i][threadIdx.x] = in[(size_t)(y0 + i) * ld_in + x0 + threadIdx.x];
    __syncthreads();
#pragma unroll
    for (int i = threadIdx.y; i < 32; i += 8)
        out[(size_t)(x0 + i) * ld_out + y0 + threadIdx.x] = t[threadIdx.x][i];
}

// ---------------------------------------------------------------------------
extern "C" void kernel_launch(void* const* d_in, const int* in_sizes, int n_in,
                              void* d_out, int out_size)
{
    const float* x      = (const float*)d_in[0];   // [B,S,E]
    const float* w_qkv  = (const float*)d_in[1];   // [3H,E]
    const float* w_proj = (const float*)d_in[2];   // [E,H]
    const float* b_proj = (const float*)d_in[3];   // [E]
    float* y = (float*)d_out;                      // [B,S,E]

    h16 *xh, *xl, *wqh, *wql, *wph, *qkvh, *qkvl;
    h16 *ph, *vTh, *oh, *oTh;
    float* scores;
    cudaGetSymbolAddress((void**)&xh, g_xh);     cudaGetSymbolAddress((void**)&xl, g_xl);
    cudaGetSymbolAddress((void**)&wqh, g_wqh);   cudaGetSymbolAddress((void**)&wql, g_wql);
    cudaGetSymbolAddress((void**)&wph, g_wph);
    cudaGetSymbolAddress((void**)&qkvh, g_qkvh); cudaGetSymbolAddress((void**)&qkvl, g_qkvl);
    cudaGetSymbolAddress((void**)&scores, g_scores);
    cudaGetSymbolAddress((void**)&ph, g_ph);
    cudaGetSymbolAddress((void**)&vTh, g_vTh);
    cudaGetSymbolAddress((void**)&oh, g_oh);
    cudaGetSymbolAddress((void**)&oTh, g_oTh);

    const int shm2 = 4 * 49152;   // NL=2: 192KB
    const int shm1 = 4 * 32768;   // NL=1: 128KB
    const int shm0 = 4 * 24576;   // NL=0: 96KB
    cudaFuncSetAttribute(tc_gemm<2,2>, cudaFuncAttributeMaxDynamicSharedMemorySize, shm2);
    cudaFuncSetAttribute(tc_gemm<0,1>, cudaFuncAttributeMaxDynamicSharedMemorySize, shm1);
    cudaFuncSetAttribute(tc_gemm<3,0>, cudaFuncAttributeMaxDynamicSharedMemorySize, shm0);
    cudaFuncSetAttribute(tc_gemm<1,0>, cudaFuncAttributeMaxDynamicSharedMemorySize, shm0);

    const long long sQKV = (long long)SEQ * QKV3;
    const long long sSS  = (long long)SEQ * SEQ;
    const long long sSH  = (long long)SEQ * HSZ;
    const long long sHS  = (long long)HSZ * SEQ;

    // 0. split / round inputs to fp16
    split_kernel<<<1024, 256>>>(x,      xh,  xl,  (long long)BS * EMBED);
    split_kernel<<<512,  256>>>(w_qkv,  wqh, wql, (long long)QKV3 * EMBED);
    round_kernel<<<256,  256>>>(w_proj, wph,      (long long)EMBED * HSZ);

    // 1. qkv = x @ w_qkv^T   [8192 x 3072 x 1024], 3-MMA, split out. 3072 CTAs.
    tc_gemm<2,2><<<dim3(QKV3 / 128, BS / 64, 1), 256, shm2>>>(
        xh, xl, wqh, wql, nullptr, qkvh, qkvl, nullptr,
        EMBED, EMBED, EMBED, QKV3, 0, 0, 0, 1.0f);

    // 2. scores = 0.125 * q @ k^T   4x [2048 x 2048 x 1024], 2-MMA
    //    (q two-limb, k single-rounded hi). 2048 CTAs.
    tc_gemm<0,1><<<dim3(SEQ / 128, SEQ / 64, BATCH), 256, shm1>>>(
        qkvh, qkvl, qkvh + HSZ, nullptr, scores, nullptr, nullptr, nullptr,
        HSZ, QKV3, QKV3, SEQ, sQKV, sQKV, sSS, 0.125f);

    // 3. softmax -> fp16 probs (single-rounded)
    softmax_kernel<<<BATCH * SEQ, 256>>>(scores, ph);

    // 4. vT = v^T per batch (hi limb only)
    transpose_one<<<dim3(HSZ / 32, SEQ / 32, BATCH), dim3(32, 8)>>>(
        qkvh + 2 * HSZ, vTh, QKV3, SEQ, sQKV, sHS);

    // 5. out = probs @ vT^T   4x [2048 x 1024 x 2048], 1-MMA pure fp16. 1024 CTAs.
    tc_gemm<3,0><<<dim3(HSZ / 128, SEQ / 64, BATCH), 256, shm0>>>(
        ph, nullptr, vTh, nullptr, nullptr, oh, nullptr, nullptr,
        SEQ, SEQ, SEQ, HSZ, sSS, sHS, sSH, 1.0f);

    // 6. scrambling reshape == per-batch transpose (flat re-view)
    transpose_one<<<dim3(HSZ / 32, SEQ / 32, BATCH), dim3(32, 8)>>>(
        oh, oTh, HSZ, SEQ, sSH, sHS);

    // 7. y = out2 @ w_proj^T + b   [8192 x 1024 x 1024], 1-MMA, fp32+bias. 1024 CTAs.
    tc_gemm<1,0><<<dim3(EMBED / 128, BS / 64, 1), 256, shm0>>>(
        oTh, nullptr, wph, nullptr, y, nullptr, nullptr, b_proj,
        HSZ, HSZ, HSZ, EMBED, 0, 0, 0, 1.0f);
}

// round 14
// speedup vs baseline: 1.7239x; 1.1356x over previous
#include <cuda_runtime.h>
#include <cuda_fp16.h>
#include <math.h>
#include <stdint.h>

// Problem constants
#define BATCH 4
#define SEQ   2048
#define EMBED 1024
#define HSZ   1024
#define QKV3  3072
#define BS    (BATCH*SEQ)

typedef __half h16;

// Scratch (device globals -- no allocation allowed)
__device__ h16   g_xh[(size_t)BS * EMBED];
__device__ h16   g_xl[(size_t)BS * EMBED];
__device__ h16   g_wqh[(size_t)QKV3 * EMBED];
__device__ h16   g_wph[(size_t)EMBED * HSZ];
__device__ h16   g_qkvh[(size_t)BS * QKV3];
__device__ h16   g_qkvl[(size_t)BS * QKV3];
__device__ float g_scores[(size_t)BATCH * SEQ * SEQ];
__device__ h16   g_ph[(size_t)BATCH * SEQ * SEQ];
__device__ h16   g_vTh[(size_t)BATCH * HSZ * SEQ];
__device__ h16   g_oh[(size_t)BATCH * SEQ * HSZ];
__device__ h16   g_oTh[(size_t)BATCH * HSZ * SEQ];

// ---------------------------------------------------------------------------
__device__ __forceinline__ uint32_t smem_u32(const void* p) {
    uint32_t a;
    asm("{ .reg .u64 t; cvta.to.shared.u64 t, %1; cvt.u32.u64 %0, t; }"
        : "=r"(a) : "l"(p));
    return a;
}
__device__ __forceinline__ void cp16(uint32_t dst, const void* src) {
    asm volatile("cp.async.cg.shared.global [%0], [%1], 16;"
                 :: "r"(dst), "l"(src));
}
__device__ __forceinline__ void ldsm4(uint32_t* r, uint32_t addr) {
    asm volatile("ldmatrix.sync.aligned.m8n8.x4.shared.b16 {%0,%1,%2,%3}, [%4];"
                 : "=r"(r[0]), "=r"(r[1]), "=r"(r[2]), "=r"(r[3]) : "r"(addr));
}
// fp16 inputs, fp32 accumulators (main term)
__device__ __forceinline__ void mma_f32(float* c, const uint32_t* a,
                                        const uint32_t* b) {
    asm volatile(
        "mma.sync.aligned.m16n8k16.row.col.f32.f16.f16.f32 "
        "{%0,%1,%2,%3}, {%4,%5,%6,%7}, {%8,%9}, {%0,%1,%2,%3};"
        : "+f"(c[0]), "+f"(c[1]), "+f"(c[2]), "+f"(c[3])
        : "r"(a[0]), "r"(a[1]), "r"(a[2]), "r"(a[3]), "r"(b[0]), "r"(b[1]));
}
// fp16 inputs, fp16 accumulators (cross terms, ~2^-11 of result magnitude)
__device__ __forceinline__ void mma_f16(uint32_t* d, const uint32_t* a,
                                        const uint32_t* b) {
    asm volatile(
        "mma.sync.aligned.m16n8k16.row.col.f16.f16.f16.f16 "
        "{%0,%1}, {%2,%3,%4,%5}, {%6,%7}, {%0,%1};"
        : "+r"(d[0]), "+r"(d[1])
        : "r"(a[0]), "r"(a[1]), "r"(a[2]), "r"(a[3]), "r"(b[0]), "r"(b[1]));
}

// ---------------------------------------------------------------------------
// fp16 multi-limb NT GEMM.
// NL=2: C = alpha*(Ah+Al)*(Bh+Bl)^T, 3 MMAs (ah*bh f32; crosses f16-acc).
// NL=1: C = alpha*(Ah+Al)*Bh^T,      2 MMAs (ah*bh f32; al*bh f16-acc).
// NL=0: C = alpha*Ah*Bh^T,           1 MMA  (pure fp16 in, f32 acc).
// BM=64, BN=128, BK=64. 256 threads = 8 warps (2m x 4n); warp tile 32x32.
// 4-stage cp.async pipeline, ONE __syncthreads per K-iter, frag double-buffer.
// MODE 0: fp32 out; 1: fp32+bias; 2: split fp16 out (Ch,Cl); 3: fp16 out (Ch)
// ---------------------------------------------------------------------------
template <int MODE, int NL>
__global__ __launch_bounds__(256, 1) void tc_gemm(
    const h16* __restrict__ Ah, const h16* __restrict__ Al,
    const h16* __restrict__ Bh, const h16* __restrict__ Bl,
    float* __restrict__ C, h16* __restrict__ Ch, h16* __restrict__ Cl,
    const float* __restrict__ bias,
    int K, int lda, int ldb, int ldc,
    long long sA, long long sB, long long sC, float alpha)
{
    constexpr int ALN = (NL >= 1) ? 2 : 1;            // A limbs
    constexpr int BLN = (NL == 2) ? 2 : 1;            // B limbs
    constexpr uint32_t A_LIMB = 8192u;                // 64 rows x 128B
    constexpr uint32_t B_OFF  = (uint32_t)ALN * A_LIMB;
    constexpr uint32_t B_LIMB = 16384u;               // 128 rows x 128B
    constexpr uint32_t STAGE  = B_OFF + (uint32_t)BLN * B_LIMB;

    extern __shared__ char dsm[];
    const uint32_t base = smem_u32(dsm);

    const int tid = threadIdx.x;
    const int wid = tid >> 5, lane = tid & 31;
    const int wm = wid >> 2, wn = wid & 3;     // 2 x 4 warps
    const int gid = lane >> 2, tig = lane & 3;

    Ah += (long long)blockIdx.z * sA;
    if (ALN == 2) Al += (long long)blockIdx.z * sA;
    Bh += (long long)blockIdx.z * sB;
    if (BLN == 2) Bl += (long long)blockIdx.z * sB;
    const long long co = (long long)blockIdx.z * sC;
    const int m0 = blockIdx.y * 64;
    const int n0 = blockIdx.x * 128;

    // ldmatrix per-lane row/chunk decode
    const int rAl = lane & 15,                       cA16 = (lane >> 4) << 4;
    const int rBl = (lane & 7) | ((lane >> 4) << 3), cB16 = ((lane >> 3) & 1) << 4;

    uint32_t rbA[2], swA[2], rbB[2], swB[2];
#pragma unroll
    for (int mt = 0; mt < 2; mt++) {
        int row = wm * 32 + mt * 16 + rAl;
        rbA[mt] = (uint32_t)row << 7;
        swA[mt] = (uint32_t)(row & 7) << 4;
    }
#pragma unroll
    for (int np = 0; np < 2; np++) {
        int row = wn * 32 + np * 16 + rBl;
        rbB[np] = (uint32_t)row << 7;
        swB[np] = (uint32_t)(row & 7) << 4;
    }

    float c[2][4][4];
    uint32_t cf[2][4][2];                      // f16x2 cross accumulators
#pragma unroll
    for (int mt = 0; mt < 2; mt++)
#pragma unroll
        for (int nt = 0; nt < 4; nt++) {
#pragma unroll
            for (int i = 0; i < 4; i++) c[mt][nt][i] = 0.f;
            cf[mt][nt][0] = 0u; cf[mt][nt][1] = 0u;
        }

    const int NIT = K >> 6;   // BK = 64

    auto load_stage = [&](int it, int s) {
        const uint32_t st = base + (uint32_t)s * STAGE;
        const int c0 = it << 6;
#pragma unroll
        for (int i = 0; i < 2; i++) {              // A: 64 rows x 8 cp16
            int idx = tid + i * 256;
            int r = idx >> 3, ch = idx & 7;
            uint32_t off = ((uint32_t)r << 7) + (((uint32_t)ch << 4) ^ ((uint32_t)(r & 7) << 4));
            cp16(st + off, Ah + (size_t)(m0 + r) * lda + c0 + ch * 8);
            if (ALN == 2)
                cp16(st + A_LIMB + off, Al + (size_t)(m0 + r) * lda + c0 + ch * 8);
        }
#pragma unroll
        for (int i = 0; i < 4; i++) {              // B: 128 rows x 8 cp16
            int idx = tid + i * 256;
            int r = idx >> 3, ch = idx & 7;
            uint32_t off = ((uint32_t)r << 7) + (((uint32_t)ch << 4) ^ ((uint32_t)(r & 7) << 4));
            cp16(st + B_OFF + off, Bh + (size_t)(n0 + r) * ldb + c0 + ch * 8);
            if (BLN == 2)
                cp16(st + B_OFF + B_LIMB + off, Bl + (size_t)(n0 + r) * ldb + c0 + ch * 8);
        }
        asm volatile("cp.async.commit_group;" ::: "memory");
    };

    load_stage(0, 0);
    load_stage(1, 1);
    load_stage(2, 2);

    // Fragment double buffers
    uint32_t ah[2][2][4], al[2][2][4];   // [buf][mt][reg]
    uint32_t bh[2][2][4], bl[2][2][4];   // [buf][np][reg]

    auto ld_frags = [&](uint32_t st, int ks, int buf) {
        const uint32_t kb = (uint32_t)ks << 5;
#pragma unroll
        for (int mt = 0; mt < 2; mt++) {
            uint32_t a = st + rbA[mt] + ((kb + cA16) ^ swA[mt]);
            ldsm4(ah[buf][mt], a);
            if (ALN == 2) ldsm4(al[buf][mt], a + A_LIMB);
        }
#pragma unroll
        for (int np = 0; np < 2; np++) {
            uint32_t b = st + B_OFF + rbB[np] + ((kb + cB16) ^ swB[np]);
            ldsm4(bh[buf][np], b);
            if (BLN == 2) ldsm4(bl[buf][np], b + B_LIMB);
        }
    };

    auto do_mmas = [&](int buf) {
#pragma unroll
        for (int np = 0; np < 2; np++)
#pragma unroll
            for (int mt = 0; mt < 2; mt++)
#pragma unroll
                for (int h = 0; h < 2; h++) {
                    float*    cc = c[mt][np * 2 + h];
                    uint32_t* xf = cf[mt][np * 2 + h];
                    mma_f32(cc, ah[buf][mt], bh[buf][np] + 2 * h);
                    if (NL == 2) mma_f16(xf, ah[buf][mt], bl[buf][np] + 2 * h);
                    if (NL >= 1) mma_f16(xf, al[buf][mt], bh[buf][np] + 2 * h);
                }
    };

#pragma unroll 1
    for (int it = 0; it < NIT; it++) {
        asm volatile("cp.async.wait_group 2;" ::: "memory");
        __syncthreads();

        const uint32_t st = base + (uint32_t)(it & 3) * STAGE;
        ld_frags(st, 0, 0);
#pragma unroll
        for (int ks = 0; ks < 4; ks++) {
            if (ks < 3) {
                ld_frags(st, ks + 1, (ks + 1) & 1);   // prefetch next k-step
            } else {
                // overlap next-stage global loads with last k-step's MMAs;
                // slot (it+3)&3 == (it-1)&3 was fully consumed before this
                // iteration's __syncthreads -> safe to overwrite.
                if (it + 3 < NIT) load_stage(it + 3, (it + 3) & 3);
                else asm volatile("cp.async.commit_group;" ::: "memory");
            }
            do_mmas(ks & 1);
        }
    }

    // Epilogue: result = main(f32) + cross(f16x2 unpacked, if any)
#pragma unroll
    for (int mt = 0; mt < 2; mt++) {
#pragma unroll
        for (int nt = 0; nt < 4; nt++) {
            int m = m0 + wm * 32 + mt * 16 + gid;
            int n = n0 + wn * 32 + nt * 8 + tig * 2;
            float v0, v1, v2, v3;
            if (NL >= 1) {
                __half2 u0 = *reinterpret_cast<__half2*>(&cf[mt][nt][0]);
                __half2 u1 = *reinterpret_cast<__half2*>(&cf[mt][nt][1]);
                v0 = alpha * (c[mt][nt][0] + __low2float(u0));
                v1 = alpha * (c[mt][nt][1] + __high2float(u0));
                v2 = alpha * (c[mt][nt][2] + __low2float(u1));
                v3 = alpha * (c[mt][nt][3] + __high2float(u1));
            } else {
                v0 = alpha * c[mt][nt][0];
                v1 = alpha * c[mt][nt][1];
                v2 = alpha * c[mt][nt][2];
                v3 = alpha * c[mt][nt][3];
            }
            if (MODE == 1) {
                float b0 = bias[n], b1 = bias[n + 1];
                v0 += b0; v1 += b1; v2 += b0; v3 += b1;
            }
            if (MODE == 2 || MODE == 3) {
                h16 h0 = __float2half(v0);
                h16 h1 = __float2half(v1);
                h16 h2 = __float2half(v2);
                h16 h3 = __float2half(v3);
                __half2 hh0{h0, h1}, hh1{h2, h3};
                *(__half2*)&Ch[co + (size_t)m * ldc + n]       = hh0;
                *(__half2*)&Ch[co + (size_t)(m + 8) * ldc + n] = hh1;
                if (MODE == 2) {
                    h16 l0 = __float2half(v0 - __half2float(h0));
                    h16 l1 = __float2half(v1 - __half2float(h1));
                    h16 l2 = __float2half(v2 - __half2float(h2));
                    h16 l3 = __float2half(v3 - __half2float(h3));
                    __half2 ll0{l0, l1}, ll1{l2, l3};
                    *(__half2*)&Cl[co + (size_t)m * ldc + n]       = ll0;
                    *(__half2*)&Cl[co + (size_t)(m + 8) * ldc + n] = ll1;
                }
            } else {
                *(float2*)&C[co + (size_t)m * ldc + n]       = make_float2(v0, v1);
                *(float2*)&C[co + (size_t)(m + 8) * ldc + n] = make_float2(v2, v3);
            }
        }
    }
}

// ---------------------------------------------------------------------------
// Elementwise fp32 -> (hi, lo) fp16 split
// ---------------------------------------------------------------------------
__global__ __launch_bounds__(256) void split_kernel(
    const float* __restrict__ in, h16* __restrict__ oh, h16* __restrict__ ol,
    long long n)
{
    long long i = (long long)blockIdx.x * 256 + threadIdx.x;
    long long stride = (long long)gridDim.x * 256;
    for (; i < n; i += stride) {
        float v = in[i];
        h16 h = __float2half(v);
        oh[i] = h;
        ol[i] = __float2half(v - __half2float(h));
    }
}

// ---------------------------------------------------------------------------
// Elementwise fp32 -> fp16 round (hi only)
// ---------------------------------------------------------------------------
__global__ __launch_bounds__(256) void round_kernel(
    const float* __restrict__ in, h16* __restrict__ oh, long long n)
{
    long long i = (long long)blockIdx.x * 256 + threadIdx.x;
    long long stride = (long long)gridDim.x * 256;
    for (; i < n; i += stride)
        oh[i] = __float2half(in[i]);
}

// ---------------------------------------------------------------------------
// Row softmax: read fp32 scores, write fp16 probs (single-rounded).
// ---------------------------------------------------------------------------
__global__ __launch_bounds__(256) void softmax_kernel(
    const float* __restrict__ scores, h16* __restrict__ ph)
{
    const float* row = scores + (size_t)blockIdx.x * SEQ;
    h16* rh = ph + (size_t)blockIdx.x * SEQ;
    const int t = threadIdx.x;

    float v[8];
    float m = -INFINITY;
#pragma unroll
    for (int i = 0; i < 8; i++) {
        v[i] = row[t + i * 256];
        m = fmaxf(m, v[i]);
    }
#pragma unroll
    for (int o = 16; o > 0; o >>= 1)
        m = fmaxf(m, __shfl_xor_sync(0xffffffffu, m, o));

    __shared__ float redmax[8], redsum[8];
    if ((t & 31) == 0) redmax[t >> 5] = m;
    __syncthreads();
    float mm = redmax[0];
#pragma unroll
    for (int i = 1; i < 8; i++) mm = fmaxf(mm, redmax[i]);

    float s = 0.f;
#pragma unroll
    for (int i = 0; i < 8; i++) { v[i] = __expf(v[i] - mm); s += v[i]; }
#pragma unroll
    for (int o = 16; o > 0; o >>= 1)
        s += __shfl_xor_sync(0xffffffffu, s, o);
    if ((t & 31) == 0) redsum[t >> 5] = s;
    __syncthreads();
    float ss = 0.f;
#pragma unroll
    for (int i = 0; i < 8; i++) ss += redsum[i];
    float inv = 1.0f / ss;

#pragma unroll
    for (int i = 0; i < 8; i++)
        rh[t + i * 256] = __float2half(v[i] * inv);
}

// ---------------------------------------------------------------------------
// Per-batch transpose of a single fp16 array: out[c][r] = in[r][c]
// ---------------------------------------------------------------------------
__global__ __launch_bounds__(256) void transpose_one(
    const h16* __restrict__ in, h16* __restrict__ out,
    int ld_in, int ld_out, long long sIn, long long sOut)
{
    __shared__ h16 t[32][33];
    in  += (long long)blockIdx.z * sIn;
    out += (long long)blockIdx.z * sOut;
    const int x0 = blockIdx.x * 32;
    const int y0 = blockIdx.y * 32;

#pragma unroll
    for (int i = threadIdx.y; i < 32; i += 8)
        t[i][threadIdx.x] = in[(size_t)(y0 + i) * ld_in + x0 + threadIdx.x];
    __syncthreads();
#pragma unroll
    for (int i = threadIdx.y; i < 32; i += 8)
        out[(size_t)(x0 + i) * ld_out + y0 + threadIdx.x] = t[threadIdx.x][i];
}

// ---------------------------------------------------------------------------
extern "C" void kernel_launch(void* const* d_in, const int* in_sizes, int n_in,
                              void* d_out, int out_size)
{
    const float* x      = (const float*)d_in[0];   // [B,S,E]
    const float* w_qkv  = (const float*)d_in[1];   // [3H,E]
    const float* w_proj = (const float*)d_in[2];   // [E,H]
    const float* b_proj = (const float*)d_in[3];   // [E]
    float* y = (float*)d_out;                      // [B,S,E]

    h16 *xh, *xl, *wqh, *wph, *qkvh, *qkvl;
    h16 *ph, *vTh, *oh, *oTh;
    float* scores;
    cudaGetSymbolAddress((void**)&xh, g_xh);     cudaGetSymbolAddress((void**)&xl, g_xl);
    cudaGetSymbolAddress((void**)&wqh, g_wqh);
    cudaGetSymbolAddress((void**)&wph, g_wph);
    cudaGetSymbolAddress((void**)&qkvh, g_qkvh); cudaGetSymbolAddress((void**)&qkvl, g_qkvl);
    cudaGetSymbolAddress((void**)&scores, g_scores);
    cudaGetSymbolAddress((void**)&ph, g_ph);
    cudaGetSymbolAddress((void**)&vTh, g_vTh);
    cudaGetSymbolAddress((void**)&oh, g_oh);
    cudaGetSymbolAddress((void**)&oTh, g_oTh);

    const int shm1 = 4 * 32768;   // NL=1: 128KB
    const int shm0 = 4 * 24576;   // NL=0: 96KB
    cudaFuncSetAttribute(tc_gemm<2,1>, cudaFuncAttributeMaxDynamicSharedMemorySize, shm1);
    cudaFuncSetAttribute(tc_gemm<0,1>, cudaFuncAttributeMaxDynamicSharedMemorySize, shm1);
    cudaFuncSetAttribute(tc_gemm<3,0>, cudaFuncAttributeMaxDynamicSharedMemorySize, shm0);
    cudaFuncSetAttribute(tc_gemm<1,0>, cudaFuncAttributeMaxDynamicSharedMemorySize, shm0);

    const long long sQKV = (long long)SEQ * QKV3;
    const long long sSS  = (long long)SEQ * SEQ;
    const long long sSH  = (long long)SEQ * HSZ;
    const long long sHS  = (long long)HSZ * SEQ;

    // 0. split / round inputs to fp16
    split_kernel<<<1024, 256>>>(x,      xh,  xl, (long long)BS * EMBED);
    round_kernel<<<512,  256>>>(w_qkv,  wqh,     (long long)QKV3 * EMBED);
    round_kernel<<<256,  256>>>(w_proj, wph,     (long long)EMBED * HSZ);

    // 1. qkv = x @ w_qkv^T   [8192 x 3072 x 1024], 2-MMA
    //    (x two-limb, w_qkv single-rounded), split out. 3072 CTAs.
    tc_gemm<2,1><<<dim3(QKV3 / 128, BS / 64, 1), 256, shm1>>>(
        xh, xl, wqh, nullptr, nullptr, qkvh, qkvl, nullptr,
        EMBED, EMBED, EMBED, QKV3, 0, 0, 0, 1.0f);

    // 2. scores = 0.125 * q @ k^T   4x [2048 x 2048 x 1024], 2-MMA
    //    (q two-limb, k single-rounded hi). 2048 CTAs.
    tc_gemm<0,1><<<dim3(SEQ / 128, SEQ / 64, BATCH), 256, shm1>>>(
        qkvh, qkvl, qkvh + HSZ, nullptr, scores, nullptr, nullptr, nullptr,
        HSZ, QKV3, QKV3, SEQ, sQKV, sQKV, sSS, 0.125f);

    // 3. softmax -> fp16 probs (single-rounded)
    softmax_kernel<<<BATCH * SEQ, 256>>>(scores, ph);

    // 4. vT = v^T per batch (hi limb only)
    transpose_one<<<dim3(HSZ / 32, SEQ / 32, BATCH), dim3(32, 8)>>>(
        qkvh + 2 * HSZ, vTh, QKV3, SEQ, sQKV, sHS);

    // 5. out = probs @ vT^T   4x [2048 x 1024 x 2048], 1-MMA pure fp16. 1024 CTAs.
    tc_gemm<3,0><<<dim3(HSZ / 128, SEQ / 64, BATCH), 256, shm0>>>(
        ph, nullptr, vTh, nullptr, nullptr, oh, nullptr, nullptr,
        SEQ, SEQ, SEQ, HSZ, sSS, sHS, sSH, 1.0f);

    // 6. scrambling reshape == per-batch transpose (flat re-view)
    transpose_one<<<dim3(HSZ / 32, SEQ / 32, BATCH), dim3(32, 8)>>>(
        oh, oTh, HSZ, SEQ, sSH, sHS);

    // 7. y = out2 @ w_proj^T + b   [8192 x 1024 x 1024], 1-MMA, fp32+bias. 1024 CTAs.
    tc_gemm<1,0><<<dim3(EMBED / 128, BS / 64, 1), 256, shm0>>>(
        oTh, nullptr, wph, nullptr, y, nullptr, nullptr, b_proj,
        HSZ, HSZ, HSZ, EMBED, 0, 0, 0, 1.0f);
}

// round 15
// speedup vs baseline: 1.9732x; 1.1447x over previous
#include <cuda_runtime.h>
#include <cuda_fp16.h>
#include <math.h>
#include <stdint.h>

// Problem constants
#define BATCH 4
#define SEQ   2048
#define EMBED 1024
#define HSZ   1024
#define QKV3  3072
#define BS    (BATCH*SEQ)

typedef __half h16;

// Scratch (device globals -- no allocation allowed)
__device__ h16   g_xh[(size_t)BS * EMBED];
__device__ h16   g_xl[(size_t)BS * EMBED];
__device__ h16   g_wqh[(size_t)QKV3 * EMBED];
__device__ h16   g_wph[(size_t)EMBED * HSZ];
__device__ h16   g_qkvh[(size_t)BS * QKV3];
__device__ float g_scores[(size_t)BATCH * SEQ * SEQ];
__device__ h16   g_ph[(size_t)BATCH * SEQ * SEQ];
__device__ h16   g_vTh[(size_t)BATCH * HSZ * SEQ];
__device__ h16   g_oh[(size_t)BATCH * SEQ * HSZ];
__device__ h16   g_oTh[(size_t)BATCH * HSZ * SEQ];

// ---------------------------------------------------------------------------
__device__ __forceinline__ uint32_t smem_u32(const void* p) {
    uint32_t a;
    asm("{ .reg .u64 t; cvta.to.shared.u64 t, %1; cvt.u32.u64 %0, t; }"
        : "=r"(a) : "l"(p));
    return a;
}
__device__ __forceinline__ void cp16(uint32_t dst, const void* src) {
    asm volatile("cp.async.cg.shared.global [%0], [%1], 16;"
                 :: "r"(dst), "l"(src));
}
__device__ __forceinline__ void ldsm4(uint32_t* r, uint32_t addr) {
    asm volatile("ldmatrix.sync.aligned.m8n8.x4.shared.b16 {%0,%1,%2,%3}, [%4];"
                 : "=r"(r[0]), "=r"(r[1]), "=r"(r[2]), "=r"(r[3]) : "r"(addr));
}
// fp16 inputs, fp32 accumulators (main term)
__device__ __forceinline__ void mma_f32(float* c, const uint32_t* a,
                                        const uint32_t* b) {
    asm volatile(
        "mma.sync.aligned.m16n8k16.row.col.f32.f16.f16.f32 "
        "{%0,%1,%2,%3}, {%4,%5,%6,%7}, {%8,%9}, {%0,%1,%2,%3};"
        : "+f"(c[0]), "+f"(c[1]), "+f"(c[2]), "+f"(c[3])
        : "r"(a[0]), "r"(a[1]), "r"(a[2]), "r"(a[3]), "r"(b[0]), "r"(b[1]));
}
// fp16 inputs, fp16 accumulators (cross terms, ~2^-11 of result magnitude)
__device__ __forceinline__ void mma_f16(uint32_t* d, const uint32_t* a,
                                        const uint32_t* b) {
    asm volatile(
        "mma.sync.aligned.m16n8k16.row.col.f16.f16.f16.f16 "
        "{%0,%1}, {%2,%3,%4,%5}, {%6,%7}, {%0,%1};"
        : "+r"(d[0]), "+r"(d[1])
        : "r"(a[0]), "r"(a[1]), "r"(a[2]), "r"(a[3]), "r"(b[0]), "r"(b[1]));
}

// ---------------------------------------------------------------------------
// fp16 multi-limb NT GEMM.
// NL=2: C = alpha*(Ah+Al)*(Bh+Bl)^T, 3 MMAs (ah*bh f32; crosses f16-acc).
// NL=1: C = alpha*(Ah+Al)*Bh^T,      2 MMAs (ah*bh f32; al*bh f16-acc).
// NL=0: C = alpha*Ah*Bh^T,           1 MMA  (pure fp16 in, f32 acc).
// BM=64, BN=128, BK=64. 256 threads = 8 warps (2m x 4n); warp tile 32x32.
// 4-stage cp.async pipeline, ONE __syncthreads per K-iter, frag double-buffer.
// MODE 0: fp32 out; 1: fp32+bias; 2: split fp16 out (Ch,Cl); 3: fp16 out (Ch)
// ---------------------------------------------------------------------------
template <int MODE, int NL>
__global__ __launch_bounds__(256, 1) void tc_gemm(
    const h16* __restrict__ Ah, const h16* __restrict__ Al,
    const h16* __restrict__ Bh, const h16* __restrict__ Bl,
    float* __restrict__ C, h16* __restrict__ Ch, h16* __restrict__ Cl,
    const float* __restrict__ bias,
    int K, int lda, int ldb, int ldc,
    long long sA, long long sB, long long sC, float alpha)
{
    constexpr int ALN = (NL >= 1) ? 2 : 1;            // A limbs
    constexpr int BLN = (NL == 2) ? 2 : 1;            // B limbs
    constexpr uint32_t A_LIMB = 8192u;                // 64 rows x 128B
    constexpr uint32_t B_OFF  = (uint32_t)ALN * A_LIMB;
    constexpr uint32_t B_LIMB = 16384u;               // 128 rows x 128B
    constexpr uint32_t STAGE  = B_OFF + (uint32_t)BLN * B_LIMB;

    extern __shared__ char dsm[];
    const uint32_t base = smem_u32(dsm);

    const int tid = threadIdx.x;
    const int wid = tid >> 5, lane = tid & 31;
    const int wm = wid >> 2, wn = wid & 3;     // 2 x 4 warps
    const int gid = lane >> 2, tig = lane & 3;

    Ah += (long long)blockIdx.z * sA;
    if (ALN == 2) Al += (long long)blockIdx.z * sA;
    Bh += (long long)blockIdx.z * sB;
    if (BLN == 2) Bl += (long long)blockIdx.z * sB;
    const long long co = (long long)blockIdx.z * sC;
    const int m0 = blockIdx.y * 64;
    const int n0 = blockIdx.x * 128;

    // ldmatrix per-lane row/chunk decode
    const int rAl = lane & 15,                       cA16 = (lane >> 4) << 4;
    const int rBl = (lane & 7) | ((lane >> 4) << 3), cB16 = ((lane >> 3) & 1) << 4;

    uint32_t rbA[2], swA[2], rbB[2], swB[2];
#pragma unroll
    for (int mt = 0; mt < 2; mt++) {
        int row = wm * 32 + mt * 16 + rAl;
        rbA[mt] = (uint32_t)row << 7;
        swA[mt] = (uint32_t)(row & 7) << 4;
    }
#pragma unroll
    for (int np = 0; np < 2; np++) {
        int row = wn * 32 + np * 16 + rBl;
        rbB[np] = (uint32_t)row << 7;
        swB[np] = (uint32_t)(row & 7) << 4;
    }

    float c[2][4][4];
    uint32_t cf[2][4][2];                      // f16x2 cross accumulators
#pragma unroll
    for (int mt = 0; mt < 2; mt++)
#pragma unroll
        for (int nt = 0; nt < 4; nt++) {
#pragma unroll
            for (int i = 0; i < 4; i++) c[mt][nt][i] = 0.f;
            cf[mt][nt][0] = 0u; cf[mt][nt][1] = 0u;
        }

    const int NIT = K >> 6;   // BK = 64

    auto load_stage = [&](int it, int s) {
        const uint32_t st = base + (uint32_t)s * STAGE;
        const int c0 = it << 6;
#pragma unroll
        for (int i = 0; i < 2; i++) {              // A: 64 rows x 8 cp16
            int idx = tid + i * 256;
            int r = idx >> 3, ch = idx & 7;
            uint32_t off = ((uint32_t)r << 7) + (((uint32_t)ch << 4) ^ ((uint32_t)(r & 7) << 4));
            cp16(st + off, Ah + (size_t)(m0 + r) * lda + c0 + ch * 8);
            if (ALN == 2)
                cp16(st + A_LIMB + off, Al + (size_t)(m0 + r) * lda + c0 + ch * 8);
        }
#pragma unroll
        for (int i = 0; i < 4; i++) {              // B: 128 rows x 8 cp16
            int idx = tid + i * 256;
            int r = idx >> 3, ch = idx & 7;
            uint32_t off = ((uint32_t)r << 7) + (((uint32_t)ch << 4) ^ ((uint32_t)(r & 7) << 4));
            cp16(st + B_OFF + off, Bh + (size_t)(n0 + r) * ldb + c0 + ch * 8);
            if (BLN == 2)
                cp16(st + B_OFF + B_LIMB + off, Bl + (size_t)(n0 + r) * ldb + c0 + ch * 8);
        }
        asm volatile("cp.async.commit_group;" ::: "memory");
    };

    load_stage(0, 0);
    load_stage(1, 1);
    load_stage(2, 2);

    // Fragment double buffers
    uint32_t ah[2][2][4], al[2][2][4];   // [buf][mt][reg]
    uint32_t bh[2][2][4], bl[2][2][4];   // [buf][np][reg]

    auto ld_frags = [&](uint32_t st, int ks, int buf) {
        const uint32_t kb = (uint32_t)ks << 5;
#pragma unroll
        for (int mt = 0; mt < 2; mt++) {
            uint32_t a = st + rbA[mt] + ((kb + cA16) ^ swA[mt]);
            ldsm4(ah[buf][mt], a);
            if (ALN == 2) ldsm4(al[buf][mt], a + A_LIMB);
        }
#pragma unroll
        for (int np = 0; np < 2; np++) {
            uint32_t b = st + B_OFF + rbB[np] + ((kb + cB16) ^ swB[np]);
            ldsm4(bh[buf][np], b);
            if (BLN == 2) ldsm4(bl[buf][np], b + B_LIMB);
        }
    };

    auto do_mmas = [&](int buf) {
#pragma unroll
        for (int np = 0; np < 2; np++)
#pragma unroll
            for (int mt = 0; mt < 2; mt++)
#pragma unroll
                for (int h = 0; h < 2; h++) {
                    float*    cc = c[mt][np * 2 + h];
                    uint32_t* xf = cf[mt][np * 2 + h];
                    mma_f32(cc, ah[buf][mt], bh[buf][np] + 2 * h);
                    if (NL == 2) mma_f16(xf, ah[buf][mt], bl[buf][np] + 2 * h);
                    if (NL >= 1) mma_f16(xf, al[buf][mt], bh[buf][np] + 2 * h);
                }
    };

#pragma unroll 1
    for (int it = 0; it < NIT; it++) {
        asm volatile("cp.async.wait_group 2;" ::: "memory");
        __syncthreads();

        const uint32_t st = base + (uint32_t)(it & 3) * STAGE;
        ld_frags(st, 0, 0);
#pragma unroll
        for (int ks = 0; ks < 4; ks++) {
            if (ks < 3) {
                ld_frags(st, ks + 1, (ks + 1) & 1);   // prefetch next k-step
            } else {
                // overlap next-stage global loads with last k-step's MMAs;
                // slot (it+3)&3 == (it-1)&3 was fully consumed before this
                // iteration's __syncthreads -> safe to overwrite.
                if (it + 3 < NIT) load_stage(it + 3, (it + 3) & 3);
                else asm volatile("cp.async.commit_group;" ::: "memory");
            }
            do_mmas(ks & 1);
        }
    }

    // Epilogue: result = main(f32) + cross(f16x2 unpacked, if any)
#pragma unroll
    for (int mt = 0; mt < 2; mt++) {
#pragma unroll
        for (int nt = 0; nt < 4; nt++) {
            int m = m0 + wm * 32 + mt * 16 + gid;
            int n = n0 + wn * 32 + nt * 8 + tig * 2;
            float v0, v1, v2, v3;
            if (NL >= 1) {
                __half2 u0 = *reinterpret_cast<__half2*>(&cf[mt][nt][0]);
                __half2 u1 = *reinterpret_cast<__half2*>(&cf[mt][nt][1]);
                v0 = alpha * (c[mt][nt][0] + __low2float(u0));
                v1 = alpha * (c[mt][nt][1] + __high2float(u0));
                v2 = alpha * (c[mt][nt][2] + __low2float(u1));
                v3 = alpha * (c[mt][nt][3] + __high2float(u1));
            } else {
                v0 = alpha * c[mt][nt][0];
                v1 = alpha * c[mt][nt][1];
                v2 = alpha * c[mt][nt][2];
                v3 = alpha * c[mt][nt][3];
            }
            if (MODE == 1) {
                float b0 = bias[n], b1 = bias[n + 1];
                v0 += b0; v1 += b1; v2 += b0; v3 += b1;
            }
            if (MODE == 2 || MODE == 3) {
                h16 h0 = __float2half(v0);
                h16 h1 = __float2half(v1);
                h16 h2 = __float2half(v2);
                h16 h3 = __float2half(v3);
                __half2 hh0{h0, h1}, hh1{h2, h3};
                *(__half2*)&Ch[co + (size_t)m * ldc + n]       = hh0;
                *(__half2*)&Ch[co + (size_t)(m + 8) * ldc + n] = hh1;
                if (MODE == 2) {
                    h16 l0 = __float2half(v0 - __half2float(h0));
                    h16 l1 = __float2half(v1 - __half2float(h1));
                    h16 l2 = __float2half(v2 - __half2float(h2));
                    h16 l3 = __float2half(v3 - __half2float(h3));
                    __half2 ll0{l0, l1}, ll1{l2, l3};
                    *(__half2*)&Cl[co + (size_t)m * ldc + n]       = ll0;
                    *(__half2*)&Cl[co + (size_t)(m + 8) * ldc + n] = ll1;
                }
            } else {
                *(float2*)&C[co + (size_t)m * ldc + n]       = make_float2(v0, v1);
                *(float2*)&C[co + (size_t)(m + 8) * ldc + n] = make_float2(v2, v3);
            }
        }
    }
}

// ---------------------------------------------------------------------------
// Elementwise fp32 -> (hi, lo) fp16 split
// ---------------------------------------------------------------------------
__global__ __launch_bounds__(256) void split_kernel(
    const float* __restrict__ in, h16* __restrict__ oh, h16* __restrict__ ol,
    long long n)
{
    long long i = (long long)blockIdx.x * 256 + threadIdx.x;
    long long stride = (long long)gridDim.x * 256;
    for (; i < n; i += stride) {
        float v = in[i];
        h16 h = __float2half(v);
        oh[i] = h;
        ol[i] = __float2half(v - __half2float(h));
    }
}

// ---------------------------------------------------------------------------
// Elementwise fp32 -> fp16 round (hi only)
// ---------------------------------------------------------------------------
__global__ __launch_bounds__(256) void round_kernel(
    const float* __restrict__ in, h16* __restrict__ oh, long long n)
{
    long long i = (long long)blockIdx.x * 256 + threadIdx.x;
    long long stride = (long long)gridDim.x * 256;
    for (; i < n; i += stride)
        oh[i] = __float2half(in[i]);
}

// ---------------------------------------------------------------------------
// Row softmax: read fp32 scores, write fp16 probs (single-rounded).
// ---------------------------------------------------------------------------
__global__ __launch_bounds__(256) void softmax_kernel(
    const float* __restrict__ scores, h16* __restrict__ ph)
{
    const float* row = scores + (size_t)blockIdx.x * SEQ;
    h16* rh = ph + (size_t)blockIdx.x * SEQ;
    const int t = threadIdx.x;

    float v[8];
    float m = -INFINITY;
#pragma unroll
    for (int i = 0; i < 8; i++) {
        v[i] = row[t + i * 256];
        m = fmaxf(m, v[i]);
    }
#pragma unroll
    for (int o = 16; o > 0; o >>= 1)
        m = fmaxf(m, __shfl_xor_sync(0xffffffffu, m, o));

    __shared__ float redmax[8], redsum[8];
    if ((t & 31) == 0) redmax[t >> 5] = m;
    __syncthreads();
    float mm = redmax[0];
#pragma unroll
    for (int i = 1; i < 8; i++) mm = fmaxf(mm, redmax[i]);

    float s = 0.f;
#pragma unroll
    for (int i = 0; i < 8; i++) { v[i] = __expf(v[i] - mm); s += v[i]; }
#pragma unroll
    for (int o = 16; o > 0; o >>= 1)
        s += __shfl_xor_sync(0xffffffffu, s, o);
    if ((t & 31) == 0) redsum[t >> 5] = s;
    __syncthreads();
    float ss = 0.f;
#pragma unroll
    for (int i = 0; i < 8; i++) ss += redsum[i];
    float inv = 1.0f / ss;

#pragma unroll
    for (int i = 0; i < 8; i++)
        rh[t + i * 256] = __float2half(v[i] * inv);
}

// ---------------------------------------------------------------------------
// Per-batch transpose of a single fp16 array: out[c][r] = in[r][c]
// ---------------------------------------------------------------------------
__global__ __launch_bounds__(256) void transpose_one(
    const h16* __restrict__ in, h16* __restrict__ out,
    int ld_in, int ld_out, long long sIn, long long sOut)
{
    __shared__ h16 t[32][33];
    in  += (long long)blockIdx.z * sIn;
    out += (long long)blockIdx.z * sOut;
    const int x0 = blockIdx.x * 32;
    const int y0 = blockIdx.y * 32;

#pragma unroll
    for (int i = threadIdx.y; i < 32; i += 8)
        t[i][threadIdx.x] = in[(size_t)(y0 + i) * ld_in + x0 + threadIdx.x];
    __syncthreads();
#pragma unroll
    for (int i = threadIdx.y; i < 32; i += 8)
        out[(size_t)(x0 + i) * ld_out + y0 + threadIdx.x] = t[threadIdx.x][i];
}

// ---------------------------------------------------------------------------
extern "C" void kernel_launch(void* const* d_in, const int* in_sizes, int n_in,
                              void* d_out, int out_size)
{
    const float* x      = (const float*)d_in[0];   // [B,S,E]
    const float* w_qkv  = (const float*)d_in[1];   // [3H,E]
    const float* w_proj = (const float*)d_in[2];   // [E,H]
    const float* b_proj = (const float*)d_in[3];   // [E]
    float* y = (float*)d_out;                      // [B,S,E]

    h16 *xh, *xl, *wqh, *wph, *qkvh;
    h16 *ph, *vTh, *oh, *oTh;
    float* scores;
    cudaGetSymbolAddress((void**)&xh, g_xh);     cudaGetSymbolAddress((void**)&xl, g_xl);
    cudaGetSymbolAddress((void**)&wqh, g_wqh);
    cudaGetSymbolAddress((void**)&wph, g_wph);
    cudaGetSymbolAddress((void**)&qkvh, g_qkvh);
    cudaGetSymbolAddress((void**)&scores, g_scores);
    cudaGetSymbolAddress((void**)&ph, g_ph);
    cudaGetSymbolAddress((void**)&vTh, g_vTh);
    cudaGetSymbolAddress((void**)&oh, g_oh);
    cudaGetSymbolAddress((void**)&oTh, g_oTh);

    const int shm1 = 4 * 32768;   // NL=1: 128KB
    const int shm0 = 4 * 24576;   // NL=0: 96KB
    cudaFuncSetAttribute(tc_gemm<3,1>, cudaFuncAttributeMaxDynamicSharedMemorySize, shm1);
    cudaFuncSetAttribute(tc_gemm<0,0>, cudaFuncAttributeMaxDynamicSharedMemorySize, shm0);
    cudaFuncSetAttribute(tc_gemm<3,0>, cudaFuncAttributeMaxDynamicSharedMemorySize, shm0);
    cudaFuncSetAttribute(tc_gemm<1,0>, cudaFuncAttributeMaxDynamicSharedMemorySize, shm0);

    const long long sQKV = (long long)SEQ * QKV3;
    const long long sSS  = (long long)SEQ * SEQ;
    const long long sSH  = (long long)SEQ * HSZ;
    const long long sHS  = (long long)HSZ * SEQ;

    // 0. split / round inputs to fp16
    split_kernel<<<1024, 256>>>(x,      xh,  xl, (long long)BS * EMBED);
    round_kernel<<<512,  256>>>(w_qkv,  wqh,     (long long)QKV3 * EMBED);
    round_kernel<<<256,  256>>>(w_proj, wph,     (long long)EMBED * HSZ);

    // 1. qkv = x @ w_qkv^T   [8192 x 3072 x 1024], 2-MMA
    //    (x two-limb, w_qkv single-rounded), fp16 hi-only out. 3072 CTAs.
    tc_gemm<3,1><<<dim3(QKV3 / 128, BS / 64, 1), 256, shm1>>>(
        xh, xl, wqh, nullptr, nullptr, qkvh, nullptr, nullptr,
        EMBED, EMBED, EMBED, QKV3, 0, 0, 0, 1.0f);

    // 2. scores = 0.125 * q @ k^T   4x [2048 x 2048 x 1024], 1-MMA pure fp16
    //    (q and k both single-rounded). 2048 CTAs.
    tc_gemm<0,0><<<dim3(SEQ / 128, SEQ / 64, BATCH), 256, shm0>>>(
        qkvh, nullptr, qkvh + HSZ, nullptr, scores, nullptr, nullptr, nullptr,
        HSZ, QKV3, QKV3, SEQ, sQKV, sQKV, sSS, 0.125f);

    // 3. softmax -> fp16 probs (single-rounded)
    softmax_kernel<<<BATCH * SEQ, 256>>>(scores, ph);

    // 4. vT = v^T per batch (hi limb only)
    transpose_one<<<dim3(HSZ / 32, SEQ / 32, BATCH), dim3(32, 8)>>>(
        qkvh + 2 * HSZ, vTh, QKV3, SEQ, sQKV, sHS);

    // 5. out = probs @ vT^T   4x [2048 x 1024 x 2048], 1-MMA pure fp16. 1024 CTAs.
    tc_gemm<3,0><<<dim3(HSZ / 128, SEQ / 64, BATCH), 256, shm0>>>(
        ph, nullptr, vTh, nullptr, nullptr, oh, nullptr, nullptr,
        SEQ, SEQ, SEQ, HSZ, sSS, sHS, sSH, 1.0f);

    // 6. scrambling reshape == per-batch transpose (flat re-view)
    transpose_one<<<dim3(HSZ / 32, SEQ / 32, BATCH), dim3(32, 8)>>>(
        oh, oTh, HSZ, SEQ, sSH, sHS);

    // 7. y = out2 @ w_proj^T + b   [8192 x 1024 x 1024], 1-MMA, fp32+bias. 1024 CTAs.
    tc_gemm<1,0><<<dim3(EMBED / 128, BS / 64, 1), 256, shm0>>>(
        oTh, nullptr, wph, nullptr, y, nullptr, nullptr, b_proj,
        HSZ, HSZ, HSZ, EMBED, 0, 0, 0, 1.0f);
}

// round 16
// speedup vs baseline: 2.0977x; 1.0631x over previous
#include <cuda_runtime.h>
#include <cuda_fp16.h>
#include <math.h>
#include <stdint.h>

// Problem constants
#define BATCH 4
#define SEQ   2048
#define EMBED 1024
#define HSZ   1024
#define QKV3  3072
#define BS    (BATCH*SEQ)

typedef __half h16;

// Scratch (device globals -- no allocation allowed)
__device__ h16   g_xh[(size_t)BS * EMBED];
__device__ h16   g_xl[(size_t)BS * EMBED];
__device__ h16   g_wqh[(size_t)QKV3 * EMBED];
__device__ h16   g_wph[(size_t)EMBED * HSZ];
__device__ h16   g_qkvh[(size_t)BS * QKV3];
__device__ float g_scores[(size_t)BATCH * SEQ * SEQ];
__device__ h16   g_ph[(size_t)BATCH * SEQ * SEQ];
__device__ h16   g_vTh[(size_t)BATCH * HSZ * SEQ];
__device__ h16   g_oh[(size_t)BATCH * SEQ * HSZ];
__device__ h16   g_oTh[(size_t)BATCH * HSZ * SEQ];

// ---------------------------------------------------------------------------
__device__ __forceinline__ uint32_t smem_u32(const void* p) {
    uint32_t a;
    asm("{ .reg .u64 t; cvta.to.shared.u64 t, %1; cvt.u32.u64 %0, t; }"
        : "=r"(a) : "l"(p));
    return a;
}
__device__ __forceinline__ void cp16(uint32_t dst, const void* src) {
    asm volatile("cp.async.cg.shared.global [%0], [%1], 16;"
                 :: "r"(dst), "l"(src));
}
__device__ __forceinline__ void ldsm4(uint32_t* r, uint32_t addr) {
    asm volatile("ldmatrix.sync.aligned.m8n8.x4.shared.b16 {%0,%1,%2,%3}, [%4];"
                 : "=r"(r[0]), "=r"(r[1]), "=r"(r[2]), "=r"(r[3]) : "r"(addr));
}
// fp16 inputs, fp32 accumulators (main term)
__device__ __forceinline__ void mma_f32(float* c, const uint32_t* a,
                                        const uint32_t* b) {
    asm volatile(
        "mma.sync.aligned.m16n8k16.row.col.f32.f16.f16.f32 "
        "{%0,%1,%2,%3}, {%4,%5,%6,%7}, {%8,%9}, {%0,%1,%2,%3};"
        : "+f"(c[0]), "+f"(c[1]), "+f"(c[2]), "+f"(c[3])
        : "r"(a[0]), "r"(a[1]), "r"(a[2]), "r"(a[3]), "r"(b[0]), "r"(b[1]));
}
// fp16 inputs, fp16 accumulators (cross terms, ~2^-11 of result magnitude)
__device__ __forceinline__ void mma_f16(uint32_t* d, const uint32_t* a,
                                        const uint32_t* b) {
    asm volatile(
        "mma.sync.aligned.m16n8k16.row.col.f16.f16.f16.f16 "
        "{%0,%1}, {%2,%3,%4,%5}, {%6,%7}, {%0,%1};"
        : "+r"(d[0]), "+r"(d[1])
        : "r"(a[0]), "r"(a[1]), "r"(a[2]), "r"(a[3]), "r"(b[0]), "r"(b[1]));
}

// ---------------------------------------------------------------------------
// fp16 multi-limb NT GEMM.
// NL=1: C = alpha*(Ah+Al)*Bh^T,  2 MMAs (ah*bh f32; al*bh f16-acc).
// NL=0: C = alpha*Ah*Bh^T,       1 MMA  (pure fp16 in, f32 acc).
// BM=64, BN in {128,256}. 256 threads = 8 warps (2m x 4n);
// warp tile 32 x (BN/4); NP = BN/64 n-subtiles of 16.
// 4-stage cp.async pipeline, ONE __syncthreads per K-iter, frag double-buffer.
// MODE 0: fp32 out; 1: fp32+bias; 3: fp16 out (Ch)
// ---------------------------------------------------------------------------
template <int MODE, int NL, int BN>
__global__ __launch_bounds__(256, 1) void tc_gemm(
    const h16* __restrict__ Ah, const h16* __restrict__ Al,
    const h16* __restrict__ Bh,
    float* __restrict__ C, h16* __restrict__ Ch,
    const float* __restrict__ bias,
    int K, int lda, int ldb, int ldc,
    long long sA, long long sB, long long sC, float alpha)
{
    constexpr int ALN = (NL >= 1) ? 2 : 1;            // A limbs
    constexpr int NP  = BN / 64;                      // n-subtiles per warp
    constexpr uint32_t A_LIMB = 8192u;                // 64 rows x 128B
    constexpr uint32_t B_OFF  = (uint32_t)ALN * A_LIMB;
    constexpr uint32_t B_LIMB = (uint32_t)BN * 128u;  // BN rows x 128B
    constexpr uint32_t STAGE  = B_OFF + B_LIMB;

    extern __shared__ char dsm[];
    const uint32_t base = smem_u32(dsm);

    const int tid = threadIdx.x;
    const int wid = tid >> 5, lane = tid & 31;
    const int wm = wid >> 2, wn = wid & 3;     // 2 x 4 warps
    const int gid = lane >> 2, tig = lane & 3;

    Ah += (long long)blockIdx.z * sA;
    if (ALN == 2) Al += (long long)blockIdx.z * sA;
    Bh += (long long)blockIdx.z * sB;
    const long long co = (long long)blockIdx.z * sC;
    const int m0 = blockIdx.y * 64;
    const int n0 = blockIdx.x * BN;

    // ldmatrix per-lane row/chunk decode
    const int rAl = lane & 15,                       cA16 = (lane >> 4) << 4;
    const int rBl = (lane & 7) | ((lane >> 4) << 3), cB16 = ((lane >> 3) & 1) << 4;

    uint32_t rbA[2], swA[2], rbB[NP], swB[NP];
#pragma unroll
    for (int mt = 0; mt < 2; mt++) {
        int row = wm * 32 + mt * 16 + rAl;
        rbA[mt] = (uint32_t)row << 7;
        swA[mt] = (uint32_t)(row & 7) << 4;
    }
#pragma unroll
    for (int np = 0; np < NP; np++) {
        int row = wn * (BN / 4) + np * 16 + rBl;
        rbB[np] = (uint32_t)row << 7;
        swB[np] = (uint32_t)(row & 7) << 4;
    }

    float c[2][2 * NP][4];
    uint32_t cf[2][2 * NP][2];                 // f16x2 cross accumulators
#pragma unroll
    for (int mt = 0; mt < 2; mt++)
#pragma unroll
        for (int nt = 0; nt < 2 * NP; nt++) {
#pragma unroll
            for (int i = 0; i < 4; i++) c[mt][nt][i] = 0.f;
            cf[mt][nt][0] = 0u; cf[mt][nt][1] = 0u;
        }

    const int NIT = K >> 6;   // BK = 64

    auto load_stage = [&](int it, int s) {
        const uint32_t st = base + (uint32_t)s * STAGE;
        const int c0 = it << 6;
#pragma unroll
        for (int i = 0; i < 2; i++) {              // A: 64 rows x 8 cp16
            int idx = tid + i * 256;
            int r = idx >> 3, ch = idx & 7;
            uint32_t off = ((uint32_t)r << 7) + (((uint32_t)ch << 4) ^ ((uint32_t)(r & 7) << 4));
            cp16(st + off, Ah + (size_t)(m0 + r) * lda + c0 + ch * 8);
            if (ALN == 2)
                cp16(st + A_LIMB + off, Al + (size_t)(m0 + r) * lda + c0 + ch * 8);
        }
#pragma unroll
        for (int i = 0; i < BN / 32; i++) {        // B: BN rows x 8 cp16
            int idx = tid + i * 256;
            int r = idx >> 3, ch = idx & 7;
            uint32_t off = ((uint32_t)r << 7) + (((uint32_t)ch << 4) ^ ((uint32_t)(r & 7) << 4));
            cp16(st + B_OFF + off, Bh + (size_t)(n0 + r) * ldb + c0 + ch * 8);
        }
        asm volatile("cp.async.commit_group;" ::: "memory");
    };

    load_stage(0, 0);
    load_stage(1, 1);
    load_stage(2, 2);

    // Fragment double buffers
    uint32_t ah[2][2][4], al[2][2][4];    // [buf][mt][reg]
    uint32_t bh[2][NP][4];                // [buf][np][reg]

    auto ld_frags = [&](uint32_t st, int ks, int buf) {
        const uint32_t kb = (uint32_t)ks << 5;
#pragma unroll
        for (int mt = 0; mt < 2; mt++) {
            uint32_t a = st + rbA[mt] + ((kb + cA16) ^ swA[mt]);
            ldsm4(ah[buf][mt], a);
            if (ALN == 2) ldsm4(al[buf][mt], a + A_LIMB);
        }
#pragma unroll
        for (int np = 0; np < NP; np++) {
            uint32_t b = st + B_OFF + rbB[np] + ((kb + cB16) ^ swB[np]);
            ldsm4(bh[buf][np], b);
        }
    };

    auto do_mmas = [&](int buf) {
#pragma unroll
        for (int np = 0; np < NP; np++)
#pragma unroll
            for (int mt = 0; mt < 2; mt++)
#pragma unroll
                for (int h = 0; h < 2; h++) {
                    float*    cc = c[mt][np * 2 + h];
                    uint32_t* xf = cf[mt][np * 2 + h];
                    mma_f32(cc, ah[buf][mt], bh[buf][np] + 2 * h);
                    if (NL >= 1) mma_f16(xf, al[buf][mt], bh[buf][np] + 2 * h);
                }
    };

#pragma unroll 1
    for (int it = 0; it < NIT; it++) {
        asm volatile("cp.async.wait_group 2;" ::: "memory");
        __syncthreads();

        const uint32_t st = base + (uint32_t)(it & 3) * STAGE;
        ld_frags(st, 0, 0);
#pragma unroll
        for (int ks = 0; ks < 4; ks++) {
            if (ks < 3) {
                ld_frags(st, ks + 1, (ks + 1) & 1);   // prefetch next k-step
            } else {
                // overlap next-stage global loads with last k-step's MMAs;
                // slot (it+3)&3 == (it-1)&3 was fully consumed before this
                // iteration's __syncthreads -> safe to overwrite.
                if (it + 3 < NIT) load_stage(it + 3, (it + 3) & 3);
                else asm volatile("cp.async.commit_group;" ::: "memory");
            }
            do_mmas(ks & 1);
        }
    }

    // Epilogue: result = main(f32) + cross(f16x2 unpacked, if any)
#pragma unroll
    for (int mt = 0; mt < 2; mt++) {
#pragma unroll
        for (int nt = 0; nt < 2 * NP; nt++) {
            int m = m0 + wm * 32 + mt * 16 + gid;
            int n = n0 + wn * (BN / 4) + nt * 8 + tig * 2;
            float v0, v1, v2, v3;
            if (NL >= 1) {
                __half2 u0 = *reinterpret_cast<__half2*>(&cf[mt][nt][0]);
                __half2 u1 = *reinterpret_cast<__half2*>(&cf[mt][nt][1]);
                v0 = alpha * (c[mt][nt][0] + __low2float(u0));
                v1 = alpha * (c[mt][nt][1] + __high2float(u0));
                v2 = alpha * (c[mt][nt][2] + __low2float(u1));
                v3 = alpha * (c[mt][nt][3] + __high2float(u1));
            } else {
                v0 = alpha * c[mt][nt][0];
                v1 = alpha * c[mt][nt][1];
                v2 = alpha * c[mt][nt][2];
                v3 = alpha * c[mt][nt][3];
            }
            if (MODE == 1) {
                float b0 = bias[n], b1 = bias[n + 1];
                v0 += b0; v1 += b1; v2 += b0; v3 += b1;
            }
            if (MODE == 3) {
                __half2 hh0{__float2half(v0), __float2half(v1)};
                __half2 hh1{__float2half(v2), __float2half(v3)};
                *(__half2*)&Ch[co + (size_t)m * ldc + n]       = hh0;
                *(__half2*)&Ch[co + (size_t)(m + 8) * ldc + n] = hh1;
            } else {
                *(float2*)&C[co + (size_t)m * ldc + n]       = make_float2(v0, v1);
                *(float2*)&C[co + (size_t)(m + 8) * ldc + n] = make_float2(v2, v3);
            }
        }
    }
}

// ---------------------------------------------------------------------------
// Elementwise fp32 -> (hi, lo) fp16 split
// ---------------------------------------------------------------------------
__global__ __launch_bounds__(256) void split_kernel(
    const float* __restrict__ in, h16* __restrict__ oh, h16* __restrict__ ol,
    long long n)
{
    long long i = (long long)blockIdx.x * 256 + threadIdx.x;
    long long stride = (long long)gridDim.x * 256;
    for (; i < n; i += stride) {
        float v = in[i];
        h16 h = __float2half(v);
        oh[i] = h;
        ol[i] = __float2half(v - __half2float(h));
    }
}

// ---------------------------------------------------------------------------
// Elementwise fp32 -> fp16 round (hi only)
// ---------------------------------------------------------------------------
__global__ __launch_bounds__(256) void round_kernel(
    const float* __restrict__ in, h16* __restrict__ oh, long long n)
{
    long long i = (long long)blockIdx.x * 256 + threadIdx.x;
    long long stride = (long long)gridDim.x * 256;
    for (; i < n; i += stride)
        oh[i] = __float2half(in[i]);
}

// ---------------------------------------------------------------------------
// Row softmax: read fp32 scores, write fp16 probs (single-rounded).
// ---------------------------------------------------------------------------
__global__ __launch_bounds__(256) void softmax_kernel(
    const float* __restrict__ scores, h16* __restrict__ ph)
{
    const float* row = scores + (size_t)blockIdx.x * SEQ;
    h16* rh = ph + (size_t)blockIdx.x * SEQ;
    const int t = threadIdx.x;

    float v[8];
    float m = -INFINITY;
#pragma unroll
    for (int i = 0; i < 8; i++) {
        v[i] = row[t + i * 256];
        m = fmaxf(m, v[i]);
    }
#pragma unroll
    for (int o = 16; o > 0; o >>= 1)
        m = fmaxf(m, __shfl_xor_sync(0xffffffffu, m, o));

    __shared__ float redmax[8], redsum[8];
    if ((t & 31) == 0) redmax[t >> 5] = m;
    __syncthreads();
    float mm = redmax[0];
#pragma unroll
    for (int i = 1; i < 8; i++) mm = fmaxf(mm, redmax[i]);

    float s = 0.f;
#pragma unroll
    for (int i = 0; i < 8; i++) { v[i] = __expf(v[i] - mm); s += v[i]; }
#pragma unroll
    for (int o = 16; o > 0; o >>= 1)
        s += __shfl_xor_sync(0xffffffffu, s, o);
    if ((t & 31) == 0) redsum[t >> 5] = s;
    __syncthreads();
    float ss = 0.f;
#pragma unroll
    for (int i = 0; i < 8; i++) ss += redsum[i];
    float inv = 1.0f / ss;

#pragma unroll
    for (int i = 0; i < 8; i++)
        rh[t + i * 256] = __float2half(v[i] * inv);
}

// ---------------------------------------------------------------------------
// Per-batch transpose of a single fp16 array: out[c][r] = in[r][c]
// ---------------------------------------------------------------------------
__global__ __launch_bounds__(256) void transpose_one(
    const h16* __restrict__ in, h16* __restrict__ out,
    int ld_in, int ld_out, long long sIn, long long sOut)
{
    __shared__ h16 t[32][33];
    in  += (long long)blockIdx.z * sIn;
    out += (long long)blockIdx.z * sOut;
    const int x0 = blockIdx.x * 32;
    const int y0 = blockIdx.y * 32;

#pragma unroll
    for (int i = threadIdx.y; i < 32; i += 8)
        t[i][threadIdx.x] = in[(size_t)(y0 + i) * ld_in + x0 + threadIdx.x];
    __syncthreads();
#pragma unroll
    for (int i = threadIdx.y; i < 32; i += 8)
        out[(size_t)(x0 + i) * ld_out + y0 + threadIdx.x] = t[threadIdx.x][i];
}

// ---------------------------------------------------------------------------
extern "C" void kernel_launch(void* const* d_in, const int* in_sizes, int n_in,
                              void* d_out, int out_size)
{
    const float* x      = (const float*)d_in[0];   // [B,S,E]
    const float* w_qkv  = (const float*)d_in[1];   // [3H,E]
    const float* w_proj = (const float*)d_in[2];   // [E,H]
    const float* b_proj = (const float*)d_in[3];   // [E]
    float* y = (float*)d_out;                      // [B,S,E]

    h16 *xh, *xl, *wqh, *wph, *qkvh;
    h16 *ph, *vTh, *oh, *oTh;
    float* scores;
    cudaGetSymbolAddress((void**)&xh, g_xh);     cudaGetSymbolAddress((void**)&xl, g_xl);
    cudaGetSymbolAddress((void**)&wqh, g_wqh);
    cudaGetSymbolAddress((void**)&wph, g_wph);
    cudaGetSymbolAddress((void**)&qkvh, g_qkvh);
    cudaGetSymbolAddress((void**)&scores, g_scores);
    cudaGetSymbolAddress((void**)&ph, g_ph);
    cudaGetSymbolAddress((void**)&vTh, g_vTh);
    cudaGetSymbolAddress((void**)&oh, g_oh);
    cudaGetSymbolAddress((void**)&oTh, g_oTh);

    const int shm1_256 = 4 * 49152;   // NL=1, BN=256: 192KB
    const int shm0_256 = 4 * 40960;   // NL=0, BN=256: 160KB
    const int shm0_128 = 4 * 24576;   // NL=0, BN=128: 96KB
    cudaFuncSetAttribute(tc_gemm<3,1,256>, cudaFuncAttributeMaxDynamicSharedMemorySize, shm1_256);
    cudaFuncSetAttribute(tc_gemm<0,0,256>, cudaFuncAttributeMaxDynamicSharedMemorySize, shm0_256);
    cudaFuncSetAttribute(tc_gemm<3,0,128>, cudaFuncAttributeMaxDynamicSharedMemorySize, shm0_128);
    cudaFuncSetAttribute(tc_gemm<1,0,128>, cudaFuncAttributeMaxDynamicSharedMemorySize, shm0_128);

    const long long sQKV = (long long)SEQ * QKV3;
    const long long sSS  = (long long)SEQ * SEQ;
    const long long sSH  = (long long)SEQ * HSZ;
    const long long sHS  = (long long)HSZ * SEQ;

    // 0. split / round inputs to fp16
    split_kernel<<<1024, 256>>>(x,      xh,  xl, (long long)BS * EMBED);
    round_kernel<<<512,  256>>>(w_qkv,  wqh,     (long long)QKV3 * EMBED);
    round_kernel<<<256,  256>>>(w_proj, wph,     (long long)EMBED * HSZ);

    // 1. qkv = x @ w_qkv^T   [8192 x 3072 x 1024], 2-MMA, BN=256. 1536 CTAs.
    tc_gemm<3,1,256><<<dim3(QKV3 / 256, BS / 64, 1), 256, shm1_256>>>(
        xh, xl, wqh, nullptr, qkvh, nullptr,
        EMBED, EMBED, EMBED, QKV3, 0, 0, 0, 1.0f);

    // 2. scores = 0.125 * q @ k^T   4x [2048 x 2048 x 1024], 1-MMA, BN=256. 1024 CTAs.
    tc_gemm<0,0,256><<<dim3(SEQ / 256, SEQ / 64, BATCH), 256, shm0_256>>>(
        qkvh, nullptr, qkvh + HSZ, scores, nullptr, nullptr,
        HSZ, QKV3, QKV3, SEQ, sQKV, sQKV, sSS, 0.125f);

    // 3. softmax -> fp16 probs (single-rounded)
    softmax_kernel<<<BATCH * SEQ, 256>>>(scores, ph);

    // 4. vT = v^T per batch (hi limb only)
    transpose_one<<<dim3(HSZ / 32, SEQ / 32, BATCH), dim3(32, 8)>>>(
        qkvh + 2 * HSZ, vTh, QKV3, SEQ, sQKV, sHS);

    // 5. out = probs @ vT^T   4x [2048 x 1024 x 2048], 1-MMA, BN=128. 1024 CTAs.
    tc_gemm<3,0,128><<<dim3(HSZ / 128, SEQ / 64, BATCH), 256, shm0_128>>>(
        ph, nullptr, vTh, nullptr, oh, nullptr,
        SEQ, SEQ, SEQ, HSZ, sSS, sHS, sSH, 1.0f);

    // 6. scrambling reshape == per-batch transpose (flat re-view)
    transpose_one<<<dim3(HSZ / 32, SEQ / 32, BATCH), dim3(32, 8)>>>(
        oh, oTh, HSZ, SEQ, sSH, sHS);

    // 7. y = out2 @ w_proj^T + b   [8192 x 1024 x 1024], 1-MMA, BN=128. 1024 CTAs.
    tc_gemm<1,0,128><<<dim3(EMBED / 128, BS / 64, 1), 256, shm0_128>>>(
        oTh, nullptr, wph, y, nullptr, b_proj,
        HSZ, HSZ, HSZ, EMBED, 0, 0, 0, 1.0f);
}

// round 17
// speedup vs baseline: 2.1359x; 1.0182x over previous
#include <cuda_runtime.h>
#include <cuda_fp16.h>
#include <math.h>
#include <stdint.h>

// Problem constants
#define BATCH 4
#define SEQ   2048
#define EMBED 1024
#define HSZ   1024
#define QKV3  3072
#define BS    (BATCH*SEQ)

typedef __half h16;

// Scratch (device globals -- no allocation allowed)
__device__ h16   g_xh[(size_t)BS * EMBED];
__device__ h16   g_xl[(size_t)BS * EMBED];
__device__ h16   g_wqh[(size_t)QKV3 * EMBED];
__device__ h16   g_wph[(size_t)EMBED * HSZ];
__device__ h16   g_qkvh[(size_t)BS * QKV3];
__device__ float g_scores[(size_t)BATCH * SEQ * SEQ];
__device__ h16   g_ph[(size_t)BATCH * SEQ * SEQ];
__device__ h16   g_vTh[(size_t)BATCH * HSZ * SEQ];
__device__ h16   g_oTh[(size_t)BATCH * HSZ * SEQ];

// ---------------------------------------------------------------------------
__device__ __forceinline__ uint32_t smem_u32(const void* p) {
    uint32_t a;
    asm("{ .reg .u64 t; cvta.to.shared.u64 t, %1; cvt.u32.u64 %0, t; }"
        : "=r"(a) : "l"(p));
    return a;
}
__device__ __forceinline__ void cp16(uint32_t dst, const void* src) {
    asm volatile("cp.async.cg.shared.global [%0], [%1], 16;"
                 :: "r"(dst), "l"(src));
}
__device__ __forceinline__ void ldsm4(uint32_t* r, uint32_t addr) {
    asm volatile("ldmatrix.sync.aligned.m8n8.x4.shared.b16 {%0,%1,%2,%3}, [%4];"
                 : "=r"(r[0]), "=r"(r[1]), "=r"(r[2]), "=r"(r[3]) : "r"(addr));
}
// fp16 inputs, fp32 accumulators (main term)
__device__ __forceinline__ void mma_f32(float* c, const uint32_t* a,
                                        const uint32_t* b) {
    asm volatile(
        "mma.sync.aligned.m16n8k16.row.col.f32.f16.f16.f32 "
        "{%0,%1,%2,%3}, {%4,%5,%6,%7}, {%8,%9}, {%0,%1,%2,%3};"
        : "+f"(c[0]), "+f"(c[1]), "+f"(c[2]), "+f"(c[3])
        : "r"(a[0]), "r"(a[1]), "r"(a[2]), "r"(a[3]), "r"(b[0]), "r"(b[1]));
}
// fp16 inputs, fp16 accumulators (cross terms, ~2^-11 of result magnitude)
__device__ __forceinline__ void mma_f16(uint32_t* d, const uint32_t* a,
                                        const uint32_t* b) {
    asm volatile(
        "mma.sync.aligned.m16n8k16.row.col.f16.f16.f16.f16 "
        "{%0,%1}, {%2,%3,%4,%5}, {%6,%7}, {%0,%1};"
        : "+r"(d[0]), "+r"(d[1])
        : "r"(a[0]), "r"(a[1]), "r"(a[2]), "r"(a[3]), "r"(b[0]), "r"(b[1]));
}

// ---------------------------------------------------------------------------
// fp16 multi-limb NT GEMM.
// NL=1: C = alpha*(Ah+Al)*Bh^T,  2 MMAs (ah*bh f32; al*bh f16-acc).
// NL=0: C = alpha*Ah*Bh^T,       1 MMA  (pure fp16 in, f32 acc).
// BM=64, BN in {128,256}. 256 threads = 8 warps (2m x 4n);
// warp tile 32 x (BN/4); NP = BN/64 n-subtiles of 16.
// 4-stage cp.async pipeline, ONE __syncthreads per K-iter, frag double-buffer.
// MODE 0: fp32 out; 1: fp32+bias; 3: fp16 out (Ch)
// ---------------------------------------------------------------------------
template <int MODE, int NL, int BN>
__global__ __launch_bounds__(256, 1) void tc_gemm(
    const h16* __restrict__ Ah, const h16* __restrict__ Al,
    const h16* __restrict__ Bh,
    float* __restrict__ C, h16* __restrict__ Ch,
    const float* __restrict__ bias,
    int K, int lda, int ldb, int ldc,
    long long sA, long long sB, long long sC, float alpha)
{
    constexpr int ALN = (NL >= 1) ? 2 : 1;            // A limbs
    constexpr int NP  = BN / 64;                      // n-subtiles per warp
    constexpr uint32_t A_LIMB = 8192u;                // 64 rows x 128B
    constexpr uint32_t B_OFF  = (uint32_t)ALN * A_LIMB;
    constexpr uint32_t B_LIMB = (uint32_t)BN * 128u;  // BN rows x 128B
    constexpr uint32_t STAGE  = B_OFF + B_LIMB;

    extern __shared__ char dsm[];
    const uint32_t base = smem_u32(dsm);

    const int tid = threadIdx.x;
    const int wid = tid >> 5, lane = tid & 31;
    const int wm = wid >> 2, wn = wid & 3;     // 2 x 4 warps
    const int gid = lane >> 2, tig = lane & 3;

    Ah += (long long)blockIdx.z * sA;
    if (ALN == 2) Al += (long long)blockIdx.z * sA;
    Bh += (long long)blockIdx.z * sB;
    const long long co = (long long)blockIdx.z * sC;
    const int m0 = blockIdx.y * 64;
    const int n0 = blockIdx.x * BN;

    // ldmatrix per-lane row/chunk decode
    const int rAl = lane & 15,                       cA16 = (lane >> 4) << 4;
    const int rBl = (lane & 7) | ((lane >> 4) << 3), cB16 = ((lane >> 3) & 1) << 4;

    uint32_t rbA[2], swA[2], rbB[NP], swB[NP];
#pragma unroll
    for (int mt = 0; mt < 2; mt++) {
        int row = wm * 32 + mt * 16 + rAl;
        rbA[mt] = (uint32_t)row << 7;
        swA[mt] = (uint32_t)(row & 7) << 4;
    }
#pragma unroll
    for (int np = 0; np < NP; np++) {
        int row = wn * (BN / 4) + np * 16 + rBl;
        rbB[np] = (uint32_t)row << 7;
        swB[np] = (uint32_t)(row & 7) << 4;
    }

    float c[2][2 * NP][4];
    uint32_t cf[2][2 * NP][2];                 // f16x2 cross accumulators
#pragma unroll
    for (int mt = 0; mt < 2; mt++)
#pragma unroll
        for (int nt = 0; nt < 2 * NP; nt++) {
#pragma unroll
            for (int i = 0; i < 4; i++) c[mt][nt][i] = 0.f;
            cf[mt][nt][0] = 0u; cf[mt][nt][1] = 0u;
        }

    const int NIT = K >> 6;   // BK = 64

    auto load_stage = [&](int it, int s) {
        const uint32_t st = base + (uint32_t)s * STAGE;
        const int c0 = it << 6;
#pragma unroll
        for (int i = 0; i < 2; i++) {              // A: 64 rows x 8 cp16
            int idx = tid + i * 256;
            int r = idx >> 3, ch = idx & 7;
            uint32_t off = ((uint32_t)r << 7) + (((uint32_t)ch << 4) ^ ((uint32_t)(r & 7) << 4));
            cp16(st + off, Ah + (size_t)(m0 + r) * lda + c0 + ch * 8);
            if (ALN == 2)
                cp16(st + A_LIMB + off, Al + (size_t)(m0 + r) * lda + c0 + ch * 8);
        }
#pragma unroll
        for (int i = 0; i < BN / 32; i++) {        // B: BN rows x 8 cp16
            int idx = tid + i * 256;
            int r = idx >> 3, ch = idx & 7;
            uint32_t off = ((uint32_t)r << 7) + (((uint32_t)ch << 4) ^ ((uint32_t)(r & 7) << 4));
            cp16(st + B_OFF + off, Bh + (size_t)(n0 + r) * ldb + c0 + ch * 8);
        }
        asm volatile("cp.async.commit_group;" ::: "memory");
    };

    load_stage(0, 0);
    load_stage(1, 1);
    load_stage(2, 2);

    // Fragment double buffers
    uint32_t ah[2][2][4], al[2][2][4];    // [buf][mt][reg]
    uint32_t bh[2][NP][4];                // [buf][np][reg]

    auto ld_frags = [&](uint32_t st, int ks, int buf) {
        const uint32_t kb = (uint32_t)ks << 5;
#pragma unroll
        for (int mt = 0; mt < 2; mt++) {
            uint32_t a = st + rbA[mt] + ((kb + cA16) ^ swA[mt]);
            ldsm4(ah[buf][mt], a);
            if (ALN == 2) ldsm4(al[buf][mt], a + A_LIMB);
        }
#pragma unroll
        for (int np = 0; np < NP; np++) {
            uint32_t b = st + B_OFF + rbB[np] + ((kb + cB16) ^ swB[np]);
            ldsm4(bh[buf][np], b);
        }
    };

    auto do_mmas = [&](int buf) {
#pragma unroll
        for (int np = 0; np < NP; np++)
#pragma unroll
            for (int mt = 0; mt < 2; mt++)
#pragma unroll
                for (int h = 0; h < 2; h++) {
                    float*    cc = c[mt][np * 2 + h];
                    uint32_t* xf = cf[mt][np * 2 + h];
                    mma_f32(cc, ah[buf][mt], bh[buf][np] + 2 * h);
                    if (NL >= 1) mma_f16(xf, al[buf][mt], bh[buf][np] + 2 * h);
                }
    };

#pragma unroll 1
    for (int it = 0; it < NIT; it++) {
        asm volatile("cp.async.wait_group 2;" ::: "memory");
        __syncthreads();

        const uint32_t st = base + (uint32_t)(it & 3) * STAGE;
        ld_frags(st, 0, 0);
#pragma unroll
        for (int ks = 0; ks < 4; ks++) {
            if (ks < 3) {
                ld_frags(st, ks + 1, (ks + 1) & 1);   // prefetch next k-step
            } else {
                // overlap next-stage global loads with last k-step's MMAs;
                // slot (it+3)&3 == (it-1)&3 was fully consumed before this
                // iteration's __syncthreads -> safe to overwrite.
                if (it + 3 < NIT) load_stage(it + 3, (it + 3) & 3);
                else asm volatile("cp.async.commit_group;" ::: "memory");
            }
            do_mmas(ks & 1);
        }
    }

    // Epilogue: result = main(f32) + cross(f16x2 unpacked, if any)
#pragma unroll
    for (int mt = 0; mt < 2; mt++) {
#pragma unroll
        for (int nt = 0; nt < 2 * NP; nt++) {
            int m = m0 + wm * 32 + mt * 16 + gid;
            int n = n0 + wn * (BN / 4) + nt * 8 + tig * 2;
            float v0, v1, v2, v3;
            if (NL >= 1) {
                __half2 u0 = *reinterpret_cast<__half2*>(&cf[mt][nt][0]);
                __half2 u1 = *reinterpret_cast<__half2*>(&cf[mt][nt][1]);
                v0 = alpha * (c[mt][nt][0] + __low2float(u0));
                v1 = alpha * (c[mt][nt][1] + __high2float(u0));
                v2 = alpha * (c[mt][nt][2] + __low2float(u1));
                v3 = alpha * (c[mt][nt][3] + __high2float(u1));
            } else {
                v0 = alpha * c[mt][nt][0];
                v1 = alpha * c[mt][nt][1];
                v2 = alpha * c[mt][nt][2];
                v3 = alpha * c[mt][nt][3];
            }
            if (MODE == 1) {
                float b0 = bias[n], b1 = bias[n + 1];
                v0 += b0; v1 += b1; v2 += b0; v3 += b1;
            }
            if (MODE == 3) {
                __half2 hh0{__float2half(v0), __float2half(v1)};
                __half2 hh1{__float2half(v2), __float2half(v3)};
                *(__half2*)&Ch[co + (size_t)m * ldc + n]       = hh0;
                *(__half2*)&Ch[co + (size_t)(m + 8) * ldc + n] = hh1;
            } else {
                *(float2*)&C[co + (size_t)m * ldc + n]       = make_float2(v0, v1);
                *(float2*)&C[co + (size_t)(m + 8) * ldc + n] = make_float2(v2, v3);
            }
        }
    }
}

// ---------------------------------------------------------------------------
// Elementwise fp32 -> (hi, lo) fp16 split
// ---------------------------------------------------------------------------
__global__ __launch_bounds__(256) void split_kernel(
    const float* __restrict__ in, h16* __restrict__ oh, h16* __restrict__ ol,
    long long n)
{
    long long i = (long long)blockIdx.x * 256 + threadIdx.x;
    long long stride = (long long)gridDim.x * 256;
    for (; i < n; i += stride) {
        float v = in[i];
        h16 h = __float2half(v);
        oh[i] = h;
        ol[i] = __float2half(v - __half2float(h));
    }
}

// ---------------------------------------------------------------------------
// Elementwise fp32 -> fp16 round (hi only)
// ---------------------------------------------------------------------------
__global__ __launch_bounds__(256) void round_kernel(
    const float* __restrict__ in, h16* __restrict__ oh, long long n)
{
    long long i = (long long)blockIdx.x * 256 + threadIdx.x;
    long long stride = (long long)gridDim.x * 256;
    for (; i < n; i += stride)
        oh[i] = __float2half(in[i]);
}

// ---------------------------------------------------------------------------
// Row softmax: read fp32 scores, write fp16 probs (single-rounded).
// ---------------------------------------------------------------------------
__global__ __launch_bounds__(256) void softmax_kernel(
    const float* __restrict__ scores, h16* __restrict__ ph)
{
    const float* row = scores + (size_t)blockIdx.x * SEQ;
    h16* rh = ph + (size_t)blockIdx.x * SEQ;
    const int t = threadIdx.x;

    float v[8];
    float m = -INFINITY;
#pragma unroll
    for (int i = 0; i < 8; i++) {
        v[i] = row[t + i * 256];
        m = fmaxf(m, v[i]);
    }
#pragma unroll
    for (int o = 16; o > 0; o >>= 1)
        m = fmaxf(m, __shfl_xor_sync(0xffffffffu, m, o));

    __shared__ float redmax[8], redsum[8];
    if ((t & 31) == 0) redmax[t >> 5] = m;
    __syncthreads();
    float mm = redmax[0];
#pragma unroll
    for (int i = 1; i < 8; i++) mm = fmaxf(mm, redmax[i]);

    float s = 0.f;
#pragma unroll
    for (int i = 0; i < 8; i++) { v[i] = __expf(v[i] - mm); s += v[i]; }
#pragma unroll
    for (int o = 16; o > 0; o >>= 1)
        s += __shfl_xor_sync(0xffffffffu, s, o);
    if ((t & 31) == 0) redsum[t >> 5] = s;
    __syncthreads();
    float ss = 0.f;
#pragma unroll
    for (int i = 0; i < 8; i++) ss += redsum[i];
    float inv = 1.0f / ss;

#pragma unroll
    for (int i = 0; i < 8; i++)
        rh[t + i * 256] = __float2half(v[i] * inv);
}

// ---------------------------------------------------------------------------
// Per-batch transpose of a single fp16 array: out[c][r] = in[r][c]
// ---------------------------------------------------------------------------
__global__ __launch_bounds__(256) void transpose_one(
    const h16* __restrict__ in, h16* __restrict__ out,
    int ld_in, int ld_out, long long sIn, long long sOut)
{
    __shared__ h16 t[32][33];
    in  += (long long)blockIdx.z * sIn;
    out += (long long)blockIdx.z * sOut;
    const int x0 = blockIdx.x * 32;
    const int y0 = blockIdx.y * 32;

#pragma unroll
    for (int i = threadIdx.y; i < 32; i += 8)
        t[i][threadIdx.x] = in[(size_t)(y0 + i) * ld_in + x0 + threadIdx.x];
    __syncthreads();
#pragma unroll
    for (int i = threadIdx.y; i < 32; i += 8)
        out[(size_t)(x0 + i) * ld_out + y0 + threadIdx.x] = t[threadIdx.x][i];
}

// ---------------------------------------------------------------------------
extern "C" void kernel_launch(void* const* d_in, const int* in_sizes, int n_in,
                              void* d_out, int out_size)
{
    const float* x      = (const float*)d_in[0];   // [B,S,E]
    const float* w_qkv  = (const float*)d_in[1];   // [3H,E]
    const float* w_proj = (const float*)d_in[2];   // [E,H]
    const float* b_proj = (const float*)d_in[3];   // [E]
    float* y = (float*)d_out;                      // [B,S,E]

    h16 *xh, *xl, *wqh, *wph, *qkvh;
    h16 *ph, *vTh, *oTh;
    float* scores;
    cudaGetSymbolAddress((void**)&xh, g_xh);     cudaGetSymbolAddress((void**)&xl, g_xl);
    cudaGetSymbolAddress((void**)&wqh, g_wqh);
    cudaGetSymbolAddress((void**)&wph, g_wph);
    cudaGetSymbolAddress((void**)&qkvh, g_qkvh);
    cudaGetSymbolAddress((void**)&scores, g_scores);
    cudaGetSymbolAddress((void**)&ph, g_ph);
    cudaGetSymbolAddress((void**)&vTh, g_vTh);
    cudaGetSymbolAddress((void**)&oTh, g_oTh);

    const int shm1_256 = 4 * 49152;   // NL=1, BN=256: 192KB
    const int shm0_256 = 4 * 40960;   // NL=0, BN=256: 160KB
    const int shm0_128 = 4 * 24576;   // NL=0, BN=128: 96KB
    cudaFuncSetAttribute(tc_gemm<3,1,256>, cudaFuncAttributeMaxDynamicSharedMemorySize, shm1_256);
    cudaFuncSetAttribute(tc_gemm<0,0,256>, cudaFuncAttributeMaxDynamicSharedMemorySize, shm0_256);
    cudaFuncSetAttribute(tc_gemm<3,0,128>, cudaFuncAttributeMaxDynamicSharedMemorySize, shm0_128);
    cudaFuncSetAttribute(tc_gemm<1,0,128>, cudaFuncAttributeMaxDynamicSharedMemorySize, shm0_128);

    const long long sQKV = (long long)SEQ * QKV3;
    const long long sSS  = (long long)SEQ * SEQ;
    const long long sHS  = (long long)HSZ * SEQ;

    // 0. split / round inputs to fp16
    split_kernel<<<1024, 256>>>(x,      xh,  xl, (long long)BS * EMBED);
    round_kernel<<<512,  256>>>(w_qkv,  wqh,     (long long)QKV3 * EMBED);
    round_kernel<<<256,  256>>>(w_proj, wph,     (long long)EMBED * HSZ);

    // 1. qkv = x @ w_qkv^T   [8192 x 3072 x 1024], 2-MMA, BN=256. 1536 CTAs.
    tc_gemm<3,1,256><<<dim3(QKV3 / 256, BS / 64, 1), 256, shm1_256>>>(
        xh, xl, wqh, nullptr, qkvh, nullptr,
        EMBED, EMBED, EMBED, QKV3, 0, 0, 0, 1.0f);

    // 2. scores = 0.125 * q @ k^T   4x [2048 x 2048 x 1024], 1-MMA, BN=256. 1024 CTAs.
    tc_gemm<0,0,256><<<dim3(SEQ / 256, SEQ / 64, BATCH), 256, shm0_256>>>(
        qkvh, nullptr, qkvh + HSZ, scores, nullptr, nullptr,
        HSZ, QKV3, QKV3, SEQ, sQKV, sQKV, sSS, 0.125f);

    // 3. softmax -> fp16 probs (single-rounded)
    softmax_kernel<<<BATCH * SEQ, 256>>>(scores, ph);

    // 4. vT = v^T per batch (hi limb only)
    transpose_one<<<dim3(HSZ / 32, SEQ / 32, BATCH), dim3(32, 8)>>>(
        qkvh + 2 * HSZ, vTh, QKV3, SEQ, sQKV, sHS);

    // 5. oT = out^T = vT @ probs^T   4x [1024 x 2048 x 2048] NT, 1-MMA, BN=128.
    //    oT flat-viewed per batch IS out2 (the scrambling reshape) -- the
    //    standalone reshape transpose is eliminated. 1024 CTAs.
    tc_gemm<3,0,128><<<dim3(SEQ / 128, HSZ / 64, BATCH), 256, shm0_128>>>(
        vTh, nullptr, ph, nullptr, oTh, nullptr,
        SEQ, SEQ, SEQ, SEQ, sHS, sSS, sHS, 1.0f);

    // 6. y = out2 @ w_proj^T + b   [8192 x 1024 x 1024], 1-MMA, BN=128. 1024 CTAs.
    tc_gemm<1,0,128><<<dim3(EMBED / 128, BS / 64, 1), 256, shm0_128>>>(
        oTh, nullptr, wph, y, nullptr, b_proj,
        HSZ, HSZ, HSZ, EMBED, 0, 0, 0, 1.0f);
}